// round 4
// baseline (speedup 1.0000x reference)
#include <cuda_runtime.h>
#include <math.h>
#include <stdint.h>

#define BATCH 8
#define DIM 256
#define HEADS 8
#define HEAD_DIM 32
#define HW 4096
#define RHW 256
#define SCALE 0.17677669529663687f

// -------- scratch (static device globals; no cudaMalloc allowed) --------
__device__ float g_q [BATCH * DIM * HW];    // 32 MB
__device__ float g_xr[BATCH * 4096 * RHW];  // 32 MB  (im2col-repacked x)
__device__ float g_k [BATCH * DIM * RHW];   // 2 MB
__device__ float g_v [BATCH * DIM * RHW];   // 2 MB
__device__ float g_ao[BATCH * DIM * HW];    // 32 MB

// ======================= tf32 MMA helpers =======================
__device__ __forceinline__ void split_tf32(float v, uint32_t& hi, uint32_t& lo) {
    asm("cvt.rna.tf32.f32 %0, %1;" : "=r"(hi) : "f"(v));
    float r = v - __uint_as_float(hi);
    asm("cvt.rna.tf32.f32 %0, %1;" : "=r"(lo) : "f"(r));
}

__device__ __forceinline__ float2 split1(float v) {
    uint32_t hi, lo; split_tf32(v, hi, lo);
    return make_float2(__uint_as_float(hi), __uint_as_float(lo));
}

__device__ __forceinline__ void mma_tf32(float c[4], const uint32_t a[4], const uint32_t b[2]) {
    asm volatile(
        "mma.sync.aligned.m16n8k8.row.col.f32.tf32.tf32.f32 "
        "{%0,%1,%2,%3},{%4,%5,%6,%7},{%8,%9},{%0,%1,%2,%3};"
        : "+f"(c[0]), "+f"(c[1]), "+f"(c[2]), "+f"(c[3])
        : "r"(a[0]), "r"(a[1]), "r"(a[2]), "r"(a[3]), "r"(b[0]), "r"(b[1]));
}

__device__ __forceinline__ void mma3(float c[4], const uint32_t ah[4], const uint32_t al[4],
                                     const uint32_t bh[2], const uint32_t bl[2]) {
    mma_tf32(c, ah, bh);
    mma_tf32(c, al, bh);
    mma_tf32(c, ah, bl);
}

// ======================= generic 3xTF32 GEMM body (pre-split smem) =======================
// C[m][n] = sum_k A[m][k] * B[k][n].  A row-major [*][K], B [K][N], C [M][N].
// 256 threads, warps 2(m) x 4(n).
template<int BM, int BN>
__device__ __forceinline__ void gemm3x_body(
    const float* __restrict__ A, const float* __restrict__ B, float* __restrict__ C,
    int N, int K, int m0, int n0, float* smem)
{
    constexpr int BK = 32;
    constexpr int LDA = BK + 4;    // 36
    constexpr int LDB = BN + 4;
    constexpr int WM = BM / 2, WN = BN / 4;
    constexpr int MT = WM / 16, NT = WN / 8;

    float* Ash = smem;
    float* Asl = Ash + BM * LDA;
    float* Bsh = Asl + BM * LDA;
    float* Bsl = Bsh + BK * LDB;

    const int tid = threadIdx.x, warp = tid >> 5, lane = tid & 31;
    const int wm = warp >> 2, wn = warp & 3;
    const int lr = lane >> 2, lc = lane & 3;

    float acc[MT][NT][4];
    #pragma unroll
    for (int i = 0; i < MT; i++)
        #pragma unroll
        for (int j = 0; j < NT; j++)
            #pragma unroll
            for (int q = 0; q < 4; q++) acc[i][j][q] = 0.f;

    for (int k0 = 0; k0 < K; k0 += BK) {
        #pragma unroll
        for (int i = tid; i < BM * (BK / 4); i += 256) {
            int r = i / (BK / 4), c = (i % (BK / 4)) * 4;
            float4 a = *(const float4*)&A[(size_t)(m0 + r) * K + k0 + c];
            float2 s0 = split1(a.x), s1 = split1(a.y), s2 = split1(a.z), s3 = split1(a.w);
            *(float4*)&Ash[r * LDA + c] = make_float4(s0.x, s1.x, s2.x, s3.x);
            *(float4*)&Asl[r * LDA + c] = make_float4(s0.y, s1.y, s2.y, s3.y);
        }
        #pragma unroll
        for (int i = tid; i < BK * (BN / 4); i += 256) {
            int r = i / (BN / 4), c = (i % (BN / 4)) * 4;
            float4 b = *(const float4*)&B[(size_t)(k0 + r) * N + n0 + c];
            float2 s0 = split1(b.x), s1 = split1(b.y), s2 = split1(b.z), s3 = split1(b.w);
            *(float4*)&Bsh[r * LDB + c] = make_float4(s0.x, s1.x, s2.x, s3.x);
            *(float4*)&Bsl[r * LDB + c] = make_float4(s0.y, s1.y, s2.y, s3.y);
        }
        __syncthreads();

        #pragma unroll
        for (int kk = 0; kk < BK; kk += 8) {
            uint32_t ah[MT][4], al[MT][4];
            #pragma unroll
            for (int mt = 0; mt < MT; mt++) {
                int r = wm * WM + mt * 16 + lr, c = kk + lc;
                ah[mt][0] = __float_as_uint(Ash[r * LDA + c]);
                ah[mt][1] = __float_as_uint(Ash[(r + 8) * LDA + c]);
                ah[mt][2] = __float_as_uint(Ash[r * LDA + c + 4]);
                ah[mt][3] = __float_as_uint(Ash[(r + 8) * LDA + c + 4]);
                al[mt][0] = __float_as_uint(Asl[r * LDA + c]);
                al[mt][1] = __float_as_uint(Asl[(r + 8) * LDA + c]);
                al[mt][2] = __float_as_uint(Asl[r * LDA + c + 4]);
                al[mt][3] = __float_as_uint(Asl[(r + 8) * LDA + c + 4]);
            }
            uint32_t bh[NT][2], bl[NT][2];
            #pragma unroll
            for (int nt = 0; nt < NT; nt++) {
                int cc = wn * WN + nt * 8 + lr, rr = kk + lc;
                bh[nt][0] = __float_as_uint(Bsh[rr * LDB + cc]);
                bh[nt][1] = __float_as_uint(Bsh[(rr + 4) * LDB + cc]);
                bl[nt][0] = __float_as_uint(Bsl[rr * LDB + cc]);
                bl[nt][1] = __float_as_uint(Bsl[(rr + 4) * LDB + cc]);
            }
            #pragma unroll
            for (int mt = 0; mt < MT; mt++)
                #pragma unroll
                for (int nt = 0; nt < NT; nt++)
                    mma3(acc[mt][nt], ah[mt], al[mt], bh[nt], bl[nt]);
        }
        __syncthreads();
    }

    #pragma unroll
    for (int mt = 0; mt < MT; mt++) {
        int r = m0 + wm * WM + mt * 16 + lr;
        #pragma unroll
        for (int nt = 0; nt < NT; nt++) {
            int c = n0 + wn * WN + nt * 8 + lc * 2;
            *(float2*)&C[(size_t)r * N + c]       = make_float2(acc[mt][nt][0], acc[mt][nt][1]);
            *(float2*)&C[(size_t)(r + 8) * N + c] = make_float2(acc[mt][nt][2], acc[mt][nt][3]);
        }
    }
}

// K1/K4: 1x1 conv GEMM.  M=256, N=4096, K=256 per batch.
__global__ __launch_bounds__(256)
void gemm1x1_kernel(const float* __restrict__ A, const float* __restrict__ Bg,
                    float* __restrict__ Cg) {
    extern __shared__ float smem[];
    const float* B = Bg + (size_t)blockIdx.z * DIM * HW;
    float*       C = Cg + (size_t)blockIdx.z * DIM * HW;
    gemm3x_body<128, 128>(A, B, C, HW, DIM, blockIdx.y * 128, blockIdx.x * 128, smem);
}

// K2b: fused k&v GEMM. Stacked M=512 (blocks 0-3: k, 4-7: v). N=256, K=4096.
__global__ __launch_bounds__(256)
void kv_gemm_kernel(const float* __restrict__ Wk, const float* __restrict__ Wv,
                    const float* __restrict__ XR,
                    float* __restrict__ Kout, float* __restrict__ Vout) {
    extern __shared__ float smem[];
    const int mblk = blockIdx.y;
    const float* A = (mblk < 4) ? Wk : Wv;
    float* Cg      = (mblk < 4) ? Kout : Vout;
    const int m0 = (mblk & 3) * 64;
    const float* B = XR + (size_t)blockIdx.z * 4096 * RHW;
    float*       C = Cg + (size_t)blockIdx.z * DIM * RHW;
    gemm3x_body<64, 64>(A, B, C, RHW, 4096, m0, blockIdx.x * 64, smem);
}

// ======================= im2col repack =======================
__global__ __launch_bounds__(256)
void repack_kernel(const float* __restrict__ X, float* __restrict__ XR) {
    __shared__ float pl[4096];
    const int ci = blockIdx.x, b = blockIdx.y, tid = threadIdx.x;
    const float* src = X + ((size_t)b * DIM + ci) * HW;
    #pragma unroll
    for (int i = tid; i < 1024; i += 256)
        ((float4*)pl)[i] = ((const float4*)src)[i];
    __syncthreads();
    const int oh = tid >> 4, ow = tid & 15;
    float* dst = XR + ((size_t)b * 4096 + ci * 16) * RHW;
    #pragma unroll
    for (int kh = 0; kh < 4; kh++)
        #pragma unroll
        for (int kw = 0; kw < 4; kw++)
            dst[(kh * 4 + kw) * RHW + tid] = pl[(oh * 4 + kh) * 64 + ow * 4 + kw];
}

// ======================= fused attention (tf32 MMA, pre-split K/V) =======================
__global__ __launch_bounds__(256)
void attn_kernel(const float* __restrict__ Q, const float* __restrict__ Kg,
                 const float* __restrict__ Vg, float* __restrict__ O) {
    extern __shared__ float sm[];
    float* qs  = sm;                  // [64][36]
    float* ksh = qs  + 64 * 36;       // [32][260]
    float* ksl = ksh + 32 * 260;      // [32][260]
    float* vsh = ksl + 32 * 260;      // [256][36]
    float* vsl = vsh + 256 * 36;      // [256][36]
    float* ps  = vsl + 256 * 36;      // [64][260]
    float* li  = ps  + 64 * 260;      // [64]
    float* po  = li  + 64;            // [64][36]  (warps 0-3 partial)
    float* po2 = ksh;                 // [64][36]  aliases dead K tile (warps 4-7 partial)

    const int tid = threadIdx.x, warp = tid >> 5, lane = tid & 31;
    const int lr = lane >> 2, lc = lane & 3;
    const int b = blockIdx.z, h = blockIdx.y, i0 = blockIdx.x * 64;

    const float* Qb = Q  + ((size_t)b * DIM + h * HEAD_DIM) * HW + i0;
    const float* Kb = Kg + ((size_t)b * DIM + h * HEAD_DIM) * RHW;
    const float* Vb = Vg + ((size_t)b * DIM + h * HEAD_DIM) * RHW;

    // loads
    for (int idx = tid; idx < 64 * 32; idx += 256) {       // q[d][i] -> qs[i][d]*SCALE
        int d = idx >> 6, i = idx & 63;
        qs[i * 36 + d] = Qb[(size_t)d * HW + i] * SCALE;
    }
    for (int idx = tid; idx < (32 * 256) / 4; idx += 256) { // k[d][j] pre-split
        int d = idx >> 6, j4 = (idx & 63) * 4;
        float4 k4 = *(const float4*)&Kb[(size_t)d * RHW + j4];
        float2 s0 = split1(k4.x), s1 = split1(k4.y), s2 = split1(k4.z), s3 = split1(k4.w);
        *(float4*)&ksh[d * 260 + j4] = make_float4(s0.x, s1.x, s2.x, s3.x);
        *(float4*)&ksl[d * 260 + j4] = make_float4(s0.y, s1.y, s2.y, s3.y);
    }
    for (int idx = tid; idx < 32 * 256; idx += 256) {       // v[d][j] -> transposed, pre-split
        int d = idx >> 8, j = idx & 255;
        float2 s = split1(Vb[(size_t)d * RHW + j]);
        vsh[j * 36 + d] = s.x;
        vsl[j * 36 + d] = s.y;
    }
    __syncthreads();

    // ---- S = qs * ksᵀ : M=64, N=256, K=32.  warps 2(i) x 4(j) ----
    {
        const int wm = warp >> 2, wn = warp & 3;
        float sacc[2][8][4];
        #pragma unroll
        for (int mt = 0; mt < 2; mt++)
            #pragma unroll
            for (int nt = 0; nt < 8; nt++)
                #pragma unroll
                for (int q = 0; q < 4; q++) sacc[mt][nt][q] = 0.f;

        #pragma unroll
        for (int kk = 0; kk < 32; kk += 8) {
            uint32_t ah[2][4], al[2][4];
            #pragma unroll
            for (int mt = 0; mt < 2; mt++) {
                int r = wm * 32 + mt * 16 + lr, c = kk + lc;
                split_tf32(qs[r * 36 + c],           ah[mt][0], al[mt][0]);
                split_tf32(qs[(r + 8) * 36 + c],     ah[mt][1], al[mt][1]);
                split_tf32(qs[r * 36 + c + 4],       ah[mt][2], al[mt][2]);
                split_tf32(qs[(r + 8) * 36 + c + 4], ah[mt][3], al[mt][3]);
            }
            uint32_t bh[8][2], bl[8][2];
            #pragma unroll
            for (int nt = 0; nt < 8; nt++) {
                int jj = wn * 64 + nt * 8 + lr, rr = kk + lc;
                bh[nt][0] = __float_as_uint(ksh[rr * 260 + jj]);
                bh[nt][1] = __float_as_uint(ksh[(rr + 4) * 260 + jj]);
                bl[nt][0] = __float_as_uint(ksl[rr * 260 + jj]);
                bl[nt][1] = __float_as_uint(ksl[(rr + 4) * 260 + jj]);
            }
            #pragma unroll
            for (int mt = 0; mt < 2; mt++)
                #pragma unroll
                for (int nt = 0; nt < 8; nt++)
                    mma3(sacc[mt][nt], ah[mt], al[mt], bh[nt], bl[nt]);
        }
        // exp -> ps
        #pragma unroll
        for (int mt = 0; mt < 2; mt++) {
            int r = wm * 32 + mt * 16 + lr;
            #pragma unroll
            for (int nt = 0; nt < 8; nt++) {
                int c = wn * 64 + nt * 8 + lc * 2;
                ps[r * 260 + c]           = __expf(sacc[mt][nt][0]);
                ps[r * 260 + c + 1]       = __expf(sacc[mt][nt][1]);
                ps[(r + 8) * 260 + c]     = __expf(sacc[mt][nt][2]);
                ps[(r + 8) * 260 + c + 1] = __expf(sacc[mt][nt][3]);
            }
        }
    }
    __syncthreads();   // ps complete; S reads of ks done -> po2 alias safe after next sync

    // ---- row sums ----
    {
        int i = tid >> 2, seg = tid & 3;
        float s = 0.f;
        #pragma unroll 8
        for (int j = seg * 64; j < seg * 64 + 64; j++) s += ps[i * 260 + j];
        s += __shfl_xor_sync(0xFFFFFFFFu, s, 1);
        s += __shfl_xor_sync(0xFFFFFFFFu, s, 2);
        if (seg == 0) li[i] = 1.f / s;
    }
    __syncthreads();

    // ---- O = P * Vᵀ : M=64(i), N=32(d), K=256(j). All 8 warps: split-K over j. ----
    {
        const int iw = (warp & 3) * 16;          // i-strip
        const int kbase = (warp >> 2) * 128;     // j half
        float* pobuf = (warp < 4) ? po : po2;

        float oacc[4][4];
        #pragma unroll
        for (int nt = 0; nt < 4; nt++)
            #pragma unroll
            for (int q = 0; q < 4; q++) oacc[nt][q] = 0.f;

        for (int kk = kbase; kk < kbase + 128; kk += 8) {
            uint32_t ah[4], al[4];
            int r = iw + lr, c = kk + lc;
            split_tf32(ps[r * 260 + c],           ah[0], al[0]);
            split_tf32(ps[(r + 8) * 260 + c],     ah[1], al[1]);
            split_tf32(ps[r * 260 + c + 4],       ah[2], al[2]);
            split_tf32(ps[(r + 8) * 260 + c + 4], ah[3], al[3]);
            #pragma unroll
            for (int nt = 0; nt < 4; nt++) {
                uint32_t bh[2], bl[2];
                int d = nt * 8 + lr, rr = kk + lc;
                bh[0] = __float_as_uint(vsh[rr * 36 + d]);
                bh[1] = __float_as_uint(vsh[(rr + 4) * 36 + d]);
                bl[0] = __float_as_uint(vsl[rr * 36 + d]);
                bl[1] = __float_as_uint(vsl[(rr + 4) * 36 + d]);
                mma3(oacc[nt], ah, al, bh, bl);
            }
        }
        #pragma unroll
        for (int nt = 0; nt < 4; nt++) {
            int r = iw + lr, c = nt * 8 + lc * 2;
            pobuf[r * 36 + c]           = oacc[nt][0];
            pobuf[r * 36 + c + 1]       = oacc[nt][1];
            pobuf[(r + 8) * 36 + c]     = oacc[nt][2];
            pobuf[(r + 8) * 36 + c + 1] = oacc[nt][3];
        }
    }
    __syncthreads();

    // coalesced store with partial-sum reduce + normalize
    float* Ob = O + ((size_t)b * DIM + h * HEAD_DIM) * HW + i0;
    for (int idx = tid; idx < 64 * 32; idx += 256) {
        int d = idx >> 6, i = idx & 63;
        Ob[(size_t)d * HW + i] = (po[i * 36 + d] + po2[i * 36 + d]) * li[i];
    }
}

// ============================================================================
extern "C" void kernel_launch(void* const* d_in, const int* in_sizes, int n_in,
                              void* d_out, int out_size) {
    const float* x    = (const float*)d_in[0];
    const float* wq   = (const float*)d_in[1];
    const float* wk   = (const float*)d_in[2];
    const float* wv   = (const float*)d_in[3];
    const float* wout = (const float*)d_in[4];
    float* out = (float*)d_out;

    float *qp, *xrp, *kp, *vp, *aop;
    cudaGetSymbolAddress((void**)&qp,  g_q);
    cudaGetSymbolAddress((void**)&xrp, g_xr);
    cudaGetSymbolAddress((void**)&kp,  g_k);
    cudaGetSymbolAddress((void**)&vp,  g_v);
    cudaGetSymbolAddress((void**)&aop, g_ao);

    const int g1_smem   = (128 * 36 * 2 + 32 * 132 * 2) * (int)sizeof(float);  // ~70.7 KB
    const int kv_smem   = (64 * 36 * 2 + 32 * 68 * 2) * (int)sizeof(float);    // ~35.8 KB
    const int attn_smem = (64*36 + 2*32*260 + 2*256*36 + 64*260 + 64 + 64*36) * (int)sizeof(float); // ~220 KB

    cudaFuncSetAttribute(gemm1x1_kernel, cudaFuncAttributeMaxDynamicSharedMemorySize, g1_smem);
    cudaFuncSetAttribute(kv_gemm_kernel, cudaFuncAttributeMaxDynamicSharedMemorySize, kv_smem);
    cudaFuncSetAttribute(attn_kernel,    cudaFuncAttributeMaxDynamicSharedMemorySize, attn_smem);

    // K1: q = wq @ x
    gemm1x1_kernel<<<dim3(HW / 128, DIM / 128, BATCH), 256, g1_smem>>>(wq, x, qp);
    // K2a: im2col repack
    repack_kernel<<<dim3(DIM, BATCH), 256>>>(x, xrp);
    // K2b: fused k & v GEMM (stacked M)
    kv_gemm_kernel<<<dim3(RHW / 64, 8, BATCH), 256, kv_smem>>>(wk, wv, xrp, kp, vp);
    // K3: fused attention
    attn_kernel<<<dim3(HW / 64, HEADS, BATCH), 256, attn_smem>>>(qp, kp, vp, aop);
    // K4: out = wout @ attn_out
    gemm1x1_kernel<<<dim3(HW / 128, DIM / 128, BATCH), 256, g1_smem>>>(wout, aop, out);
}

// round 6
// speedup vs baseline: 1.1978x; 1.1978x over previous
#include <cuda_runtime.h>
#include <math.h>
#include <stdint.h>

#define BATCH 8
#define DIM 256
#define HEADS 8
#define HEAD_DIM 32
#define HW 4096
#define RHW 256
#define SCALE 0.17677669529663687f

// -------- scratch (static device globals; no cudaMalloc allowed) --------
__device__ float g_q  [BATCH * DIM * HW];      // 32 MB
__device__ float g_xr [BATCH * 4096 * RHW];    // 32 MB  (im2col-repacked x)
__device__ float g_kvp[4 * BATCH * 512 * RHW]; // 16 MB  (kv split-K partials)
__device__ float g_k  [BATCH * DIM * RHW];     // 2 MB
__device__ float g_v  [BATCH * DIM * RHW];     // 2 MB
__device__ float g_ao [BATCH * DIM * HW];      // 32 MB

// ======================= tf32 MMA helpers =======================
__device__ __forceinline__ void split_tf32(float v, uint32_t& hi, uint32_t& lo) {
    asm("cvt.rna.tf32.f32 %0, %1;" : "=r"(hi) : "f"(v));
    float r = v - __uint_as_float(hi);
    asm("cvt.rna.tf32.f32 %0, %1;" : "=r"(lo) : "f"(r));
}
__device__ __forceinline__ float2 split1(float v) {
    uint32_t hi, lo; split_tf32(v, hi, lo);
    return make_float2(__uint_as_float(hi), __uint_as_float(lo));
}
__device__ __forceinline__ void mma_tf32(float c[4], const uint32_t a[4], const uint32_t b[2]) {
    asm volatile(
        "mma.sync.aligned.m16n8k8.row.col.f32.tf32.tf32.f32 "
        "{%0,%1,%2,%3},{%4,%5,%6,%7},{%8,%9},{%0,%1,%2,%3};"
        : "+f"(c[0]), "+f"(c[1]), "+f"(c[2]), "+f"(c[3])
        : "r"(a[0]), "r"(a[1]), "r"(a[2]), "r"(a[3]), "r"(b[0]), "r"(b[1]));
}
__device__ __forceinline__ void mma3(float c[4], const uint32_t ah[4], const uint32_t al[4],
                                     const uint32_t bh[2], const uint32_t bl[2]) {
    mma_tf32(c, ah, bh);
    mma_tf32(c, al, bh);
    mma_tf32(c, ah, bl);
}

// ======================= generic 3xTF32 GEMM body (pre-split smem) =======================
// C[(m0+r)*ldc + n0+c] = sum_{k<ksteps} A[(m0+r)*lda + k] * B[k*ldb + n0+c]
// 256 threads, warps 2(m) x 4(n).
template<int BM, int BN>
__device__ __forceinline__ void gemm3x_body(
    const float* __restrict__ A, int lda, const float* __restrict__ B, int ldb,
    float* __restrict__ C, int ldc, int ksteps, int m0, int n0, float* smem)
{
    constexpr int BK = 32;
    constexpr int LDA = BK + 4;
    constexpr int LDB = BN + 4;
    constexpr int WM = BM / 2, WN = BN / 4;
    constexpr int MT = WM / 16, NT = WN / 8;

    float* Ash = smem;
    float* Asl = Ash + BM * LDA;
    float* Bsh = Asl + BM * LDA;
    float* Bsl = Bsh + BK * LDB;

    const int tid = threadIdx.x, warp = tid >> 5, lane = tid & 31;
    const int wm = warp >> 2, wn = warp & 3;
    const int lr = lane >> 2, lc = lane & 3;

    float acc[MT][NT][4];
    #pragma unroll
    for (int i = 0; i < MT; i++)
        #pragma unroll
        for (int j = 0; j < NT; j++)
            #pragma unroll
            for (int q = 0; q < 4; q++) acc[i][j][q] = 0.f;

    for (int k0 = 0; k0 < ksteps; k0 += BK) {
        #pragma unroll
        for (int i = tid; i < BM * (BK / 4); i += 256) {
            int r = i / (BK / 4), c = (i % (BK / 4)) * 4;
            float4 a = *(const float4*)&A[(size_t)(m0 + r) * lda + k0 + c];
            float2 s0 = split1(a.x), s1 = split1(a.y), s2 = split1(a.z), s3 = split1(a.w);
            *(float4*)&Ash[r * LDA + c] = make_float4(s0.x, s1.x, s2.x, s3.x);
            *(float4*)&Asl[r * LDA + c] = make_float4(s0.y, s1.y, s2.y, s3.y);
        }
        #pragma unroll
        for (int i = tid; i < BK * (BN / 4); i += 256) {
            int r = i / (BN / 4), c = (i % (BN / 4)) * 4;
            float4 b = *(const float4*)&B[(size_t)(k0 + r) * ldb + n0 + c];
            float2 s0 = split1(b.x), s1 = split1(b.y), s2 = split1(b.z), s3 = split1(b.w);
            *(float4*)&Bsh[r * LDB + c] = make_float4(s0.x, s1.x, s2.x, s3.x);
            *(float4*)&Bsl[r * LDB + c] = make_float4(s0.y, s1.y, s2.y, s3.y);
        }
        __syncthreads();

        #pragma unroll
        for (int kk = 0; kk < BK; kk += 8) {
            uint32_t ah[MT][4], al[MT][4];
            #pragma unroll
            for (int mt = 0; mt < MT; mt++) {
                int r = wm * WM + mt * 16 + lr, c = kk + lc;
                ah[mt][0] = __float_as_uint(Ash[r * LDA + c]);
                ah[mt][1] = __float_as_uint(Ash[(r + 8) * LDA + c]);
                ah[mt][2] = __float_as_uint(Ash[r * LDA + c + 4]);
                ah[mt][3] = __float_as_uint(Ash[(r + 8) * LDA + c + 4]);
                al[mt][0] = __float_as_uint(Asl[r * LDA + c]);
                al[mt][1] = __float_as_uint(Asl[(r + 8) * LDA + c]);
                al[mt][2] = __float_as_uint(Asl[r * LDA + c + 4]);
                al[mt][3] = __float_as_uint(Asl[(r + 8) * LDA + c + 4]);
            }
            uint32_t bh[NT][2], bl[NT][2];
            #pragma unroll
            for (int nt = 0; nt < NT; nt++) {
                int cc = wn * WN + nt * 8 + lr, rr = kk + lc;
                bh[nt][0] = __float_as_uint(Bsh[rr * LDB + cc]);
                bh[nt][1] = __float_as_uint(Bsh[(rr + 4) * LDB + cc]);
                bl[nt][0] = __float_as_uint(Bsl[rr * LDB + cc]);
                bl[nt][1] = __float_as_uint(Bsl[(rr + 4) * LDB + cc]);
            }
            #pragma unroll
            for (int mt = 0; mt < MT; mt++)
                #pragma unroll
                for (int nt = 0; nt < NT; nt++)
                    mma3(acc[mt][nt], ah[mt], al[mt], bh[nt], bl[nt]);
        }
        __syncthreads();
    }

    #pragma unroll
    for (int mt = 0; mt < MT; mt++) {
        int r = m0 + wm * WM + mt * 16 + lr;
        #pragma unroll
        for (int nt = 0; nt < NT; nt++) {
            int c = n0 + wn * WN + nt * 8 + lc * 2;
            *(float2*)&C[(size_t)r * ldc + c]       = make_float2(acc[mt][nt][0], acc[mt][nt][1]);
            *(float2*)&C[(size_t)(r + 8) * ldc + c] = make_float2(acc[mt][nt][2], acc[mt][nt][3]);
        }
    }
}

// K1/K4: 1x1 conv GEMM.  M=256, N=4096, K=256 per batch.
__global__ __launch_bounds__(256)
void gemm1x1_kernel(const float* __restrict__ A, const float* __restrict__ Bg,
                    float* __restrict__ Cg) {
    extern __shared__ float smem[];
    const float* B = Bg + (size_t)blockIdx.z * DIM * HW;
    float*       C = Cg + (size_t)blockIdx.z * DIM * HW;
    gemm3x_body<128, 128>(A, DIM, B, HW, C, HW, DIM, blockIdx.y * 128, blockIdx.x * 128, smem);
}

// K2b: fused k&v GEMM, split-K=4. Stacked M=512 (mblk 0-3: k, 4-7: v). N=256.
// grid: (RHW/64, 8, BATCH*4).  Writes partials to g_kvp[ks][b][m512][n].
// NOTE: m0 = mblk*64 is the row in the STACKED output (0..511). For the V half
// the weight pointer is biased back by 256 rows so A[(m0+r)*lda] stays inside Wv.
__global__ __launch_bounds__(256)
void kv_gemm_kernel(const float* __restrict__ Wk, const float* __restrict__ Wv,
                    const float* __restrict__ XR, float* __restrict__ Part) {
    extern __shared__ float smem[];
    const int mblk = blockIdx.y;
    const int b  = blockIdx.z & 7;
    const int ks = blockIdx.z >> 3;
    const int koff = ks * 1024;
    const float* A = (mblk < 4) ? (Wk + koff)
                                : (Wv + koff - (size_t)256 * 4096);   // un-bias stacked rows
    const float* B = XR + (size_t)b * 4096 * RHW + (size_t)koff * RHW;
    float*       C = Part + ((size_t)(ks * BATCH + b) * 512) * RHW;
    const int m0 = mblk * 64;                                          // stacked row 0..511
    gemm3x_body<64, 64>(A, 4096, B, RHW, C, RHW, 1024, m0, blockIdx.x * 64, smem);
}

// reduce the 4 split-K partials into g_k / g_v.
__global__ __launch_bounds__(256)
void kv_reduce_kernel(const float* __restrict__ P, float* __restrict__ Kout,
                      float* __restrict__ Vout) {
    const int idx = blockIdx.x * 256 + threadIdx.x;     // float4 index
    const float4* p = (const float4*)P;
    const int CH = 8 * 512 * RHW / 4;                    // float4 per split chunk
    float4 a = p[idx], b4 = p[idx + CH], c4 = p[idx + 2 * CH], d4 = p[idx + 3 * CH];
    float4 s = make_float4(a.x + b4.x + c4.x + d4.x, a.y + b4.y + c4.y + d4.y,
                           a.z + b4.z + c4.z + d4.z, a.w + b4.w + c4.w + d4.w);
    const int f = idx * 4;
    const int n = f & 255, m = (f >> 8) & 511, b = f >> 17;
    float* dst = (m < 256) ? (Kout + ((size_t)b * DIM + m) * RHW + n)
                           : (Vout + ((size_t)b * DIM + (m - 256)) * RHW + n);
    *(float4*)dst = s;
}

// ======================= im2col repack =======================
__global__ __launch_bounds__(256)
void repack_kernel(const float* __restrict__ X, float* __restrict__ XR) {
    __shared__ float pl[4096];
    const int ci = blockIdx.x, b = blockIdx.y, tid = threadIdx.x;
    const float* src = X + ((size_t)b * DIM + ci) * HW;
    #pragma unroll
    for (int i = tid; i < 1024; i += 256)
        ((float4*)pl)[i] = ((const float4*)src)[i];
    __syncthreads();
    const int oh = tid >> 4, ow = tid & 15;
    float* dst = XR + ((size_t)b * 4096 + ci * 16) * RHW;
    #pragma unroll
    for (int kh = 0; kh < 4; kh++)
        #pragma unroll
        for (int kw = 0; kw < 4; kw++)
            dst[(kh * 4 + kw) * RHW + tid] = pl[(oh * 4 + kh) * 64 + ow * 4 + kw];
}

// ======================= fused attention: j-tiled, O in registers =======================
// i-tile 64, j-tile 64 (4 tiles). smem ~88 KB -> 2 CTAs/SM.
__global__ __launch_bounds__(256, 2)
void attn_kernel(const float* __restrict__ Q, const float* __restrict__ Kg,
                 const float* __restrict__ Vg, float* __restrict__ O) {
    extern __shared__ float sm[];
    float* qsh = sm;                // [64][36]
    float* qsl = qsh + 2304;
    float* kth = qsl + 2304;        // [32][68]
    float* ktl = kth + 2176;
    float* vth = ktl + 2176;        // [64][36]
    float* vtl = vth + 2304;
    float* psh = vtl + 2304;        // [64][68]
    float* psl = psh + 4352;
    float* lacc = psl + 4352;       // [4][64] per-wn row-sum partials
    float* li  = lacc + 256;        // [64]
    float* po  = kth;               // [64][36] final staging (aliases dead K tile)

    const int tid = threadIdx.x, warp = tid >> 5, lane = tid & 31;
    const int lr = lane >> 2, lc = lane & 3;
    const int wm = warp >> 2, wn = warp & 3;      // S-phase mapping
    const int iw = (warp & 3) * 16;                // PV-phase i-strip
    const int db = (warp >> 2) * 16;               // PV-phase d-strip
    const int b = blockIdx.z, h = blockIdx.y, i0 = blockIdx.x * 64;

    const float* Qb = Q  + ((size_t)b * DIM + h * HEAD_DIM) * HW + i0;
    const float* Kb = Kg + ((size_t)b * DIM + h * HEAD_DIM) * RHW;
    const float* Vb = Vg + ((size_t)b * DIM + h * HEAD_DIM) * RHW;

    // load q (transpose to [i][d], scale, split)
    for (int idx = tid; idx < 64 * 32; idx += 256) {
        int d = idx >> 6, i = idx & 63;
        float2 s = split1(Qb[(size_t)d * HW + i] * SCALE);
        qsh[i * 36 + d] = s.x;
        qsl[i * 36 + d] = s.y;
    }
    lacc[tid] = 0.f;   // 4*64 == blockDim

    float oacc[2][4];
    #pragma unroll
    for (int nt = 0; nt < 2; nt++)
        #pragma unroll
        for (int q = 0; q < 4; q++) oacc[nt][q] = 0.f;

    for (int jt = 0; jt < 4; jt++) {
        const int j0 = jt * 64;
        __syncthreads();   // prev tile's PV reads done
        // K tile [32][64] split (coalesced along j)
        for (int idx = tid; idx < 2048; idx += 256) {
            int d = idx >> 6, j = idx & 63;
            float2 s = split1(Kb[(size_t)d * RHW + j0 + j]);
            kth[d * 68 + j] = s.x;
            ktl[d * 68 + j] = s.y;
        }
        // V tile transposed to [j][d], split
        for (int idx = tid; idx < 2048; idx += 256) {
            int d = idx >> 6, j = idx & 63;
            float2 s = split1(Vb[(size_t)d * RHW + j0 + j]);
            vth[j * 36 + d] = s.x;
            vtl[j * 36 + d] = s.y;
        }
        __syncthreads();

        // ---- S tile = qs * ktᵀ : M=64, N=64, K=32. warp tile 32x16 ----
        float sacc[2][2][4];
        #pragma unroll
        for (int mt = 0; mt < 2; mt++)
            #pragma unroll
            for (int nt = 0; nt < 2; nt++)
                #pragma unroll
                for (int q = 0; q < 4; q++) sacc[mt][nt][q] = 0.f;

        #pragma unroll
        for (int kk = 0; kk < 32; kk += 8) {
            uint32_t ah[2][4], al[2][4];
            #pragma unroll
            for (int mt = 0; mt < 2; mt++) {
                int r = wm * 32 + mt * 16 + lr, c = kk + lc;
                ah[mt][0] = __float_as_uint(qsh[r * 36 + c]);
                ah[mt][1] = __float_as_uint(qsh[(r + 8) * 36 + c]);
                ah[mt][2] = __float_as_uint(qsh[r * 36 + c + 4]);
                ah[mt][3] = __float_as_uint(qsh[(r + 8) * 36 + c + 4]);
                al[mt][0] = __float_as_uint(qsl[r * 36 + c]);
                al[mt][1] = __float_as_uint(qsl[(r + 8) * 36 + c]);
                al[mt][2] = __float_as_uint(qsl[r * 36 + c + 4]);
                al[mt][3] = __float_as_uint(qsl[(r + 8) * 36 + c + 4]);
            }
            uint32_t bh[2][2], bl[2][2];
            #pragma unroll
            for (int nt = 0; nt < 2; nt++) {
                int jj = wn * 16 + nt * 8 + lr, rr = kk + lc;
                bh[nt][0] = __float_as_uint(kth[rr * 68 + jj]);
                bh[nt][1] = __float_as_uint(kth[(rr + 4) * 68 + jj]);
                bl[nt][0] = __float_as_uint(ktl[rr * 68 + jj]);
                bl[nt][1] = __float_as_uint(ktl[(rr + 4) * 68 + jj]);
            }
            #pragma unroll
            for (int mt = 0; mt < 2; mt++)
                #pragma unroll
                for (int nt = 0; nt < 2; nt++)
                    mma3(sacc[mt][nt], ah[mt], al[mt], bh[nt], bl[nt]);
        }

        // ---- exp -> ps (pre-split), accumulate row sums ----
        #pragma unroll
        for (int mt = 0; mt < 2; mt++) {
            int r = wm * 32 + mt * 16 + lr;
            float rs0 = 0.f, rs1 = 0.f;
            #pragma unroll
            for (int nt = 0; nt < 2; nt++) {
                int c = wn * 16 + nt * 8 + lc * 2;
                float e0 = __expf(sacc[mt][nt][0]);
                float e1 = __expf(sacc[mt][nt][1]);
                float e2 = __expf(sacc[mt][nt][2]);
                float e3 = __expf(sacc[mt][nt][3]);
                float2 s0 = split1(e0), s1 = split1(e1), s2 = split1(e2), s3 = split1(e3);
                psh[r * 68 + c]           = s0.x;  psl[r * 68 + c]           = s0.y;
                psh[r * 68 + c + 1]       = s1.x;  psl[r * 68 + c + 1]       = s1.y;
                psh[(r + 8) * 68 + c]     = s2.x;  psl[(r + 8) * 68 + c]     = s2.y;
                psh[(r + 8) * 68 + c + 1] = s3.x;  psl[(r + 8) * 68 + c + 1] = s3.y;
                rs0 += e0 + e1;
                rs1 += e2 + e3;
            }
            rs0 += __shfl_xor_sync(0xFFFFFFFFu, rs0, 1);
            rs0 += __shfl_xor_sync(0xFFFFFFFFu, rs0, 2);
            rs1 += __shfl_xor_sync(0xFFFFFFFFu, rs1, 1);
            rs1 += __shfl_xor_sync(0xFFFFFFFFu, rs1, 2);
            if (lc == 0) {
                lacc[wn * 64 + r]     += rs0;
                lacc[wn * 64 + r + 8] += rs1;
            }
        }
        __syncthreads();

        // ---- PV accumulate: O[iw..+16][db..+16] += P_tile * V_tile ----
        #pragma unroll
        for (int kk = 0; kk < 64; kk += 8) {
            uint32_t ah[4], al[4];
            int r = iw + lr, c = kk + lc;
            ah[0] = __float_as_uint(psh[r * 68 + c]);
            ah[1] = __float_as_uint(psh[(r + 8) * 68 + c]);
            ah[2] = __float_as_uint(psh[r * 68 + c + 4]);
            ah[3] = __float_as_uint(psh[(r + 8) * 68 + c + 4]);
            al[0] = __float_as_uint(psl[r * 68 + c]);
            al[1] = __float_as_uint(psl[(r + 8) * 68 + c]);
            al[2] = __float_as_uint(psl[r * 68 + c + 4]);
            al[3] = __float_as_uint(psl[(r + 8) * 68 + c + 4]);
            #pragma unroll
            for (int nt = 0; nt < 2; nt++) {
                uint32_t bh[2], bl[2];
                int d = db + nt * 8 + lr, rr = kk + lc;
                bh[0] = __float_as_uint(vth[rr * 36 + d]);
                bh[1] = __float_as_uint(vth[(rr + 4) * 36 + d]);
                bl[0] = __float_as_uint(vtl[rr * 36 + d]);
                bl[1] = __float_as_uint(vtl[(rr + 4) * 36 + d]);
                mma3(oacc[nt], ah, al, bh, bl);
            }
        }
    }

    __syncthreads();
    if (tid < 64)
        li[tid] = 1.f / (lacc[tid] + lacc[64 + tid] + lacc[128 + tid] + lacc[192 + tid]);
    __syncthreads();

    // normalize + stage to po (aliases dead K tile)
    #pragma unroll
    for (int nt = 0; nt < 2; nt++) {
        int r = iw + lr, c = db + nt * 8 + lc * 2;
        float inv0 = li[r], inv1 = li[r + 8];
        po[r * 36 + c]           = oacc[nt][0] * inv0;
        po[r * 36 + c + 1]       = oacc[nt][1] * inv0;
        po[(r + 8) * 36 + c]     = oacc[nt][2] * inv1;
        po[(r + 8) * 36 + c + 1] = oacc[nt][3] * inv1;
    }
    __syncthreads();

    // coalesced transposed store: O[d][i]
    float* Ob = O + ((size_t)b * DIM + h * HEAD_DIM) * HW + i0;
    for (int idx = tid; idx < 64 * 32; idx += 256) {
        int d = idx >> 6, i = idx & 63;
        Ob[(size_t)d * HW + i] = po[i * 36 + d];
    }
}

// ============================================================================
extern "C" void kernel_launch(void* const* d_in, const int* in_sizes, int n_in,
                              void* d_out, int out_size) {
    const float* x    = (const float*)d_in[0];
    const float* wq   = (const float*)d_in[1];
    const float* wk   = (const float*)d_in[2];
    const float* wv   = (const float*)d_in[3];
    const float* wout = (const float*)d_in[4];
    float* out = (float*)d_out;

    float *qp, *xrp, *kvpp, *kp, *vp, *aop;
    cudaGetSymbolAddress((void**)&qp,   g_q);
    cudaGetSymbolAddress((void**)&xrp,  g_xr);
    cudaGetSymbolAddress((void**)&kvpp, g_kvp);
    cudaGetSymbolAddress((void**)&kp,   g_k);
    cudaGetSymbolAddress((void**)&vp,   g_v);
    cudaGetSymbolAddress((void**)&aop,  g_ao);

    const int g1_smem   = (128 * 36 * 2 + 32 * 132 * 2) * (int)sizeof(float);  // ~70.7 KB
    const int kv_smem   = (64 * 36 * 2 + 32 * 68 * 2) * (int)sizeof(float);    // ~35.8 KB
    const int attn_smem = (2*2304 + 2*2176 + 2*2304 + 2*4352 + 256 + 64) * (int)sizeof(float); // ~88.2 KB

    cudaFuncSetAttribute(gemm1x1_kernel, cudaFuncAttributeMaxDynamicSharedMemorySize, g1_smem);
    cudaFuncSetAttribute(kv_gemm_kernel, cudaFuncAttributeMaxDynamicSharedMemorySize, kv_smem);
    cudaFuncSetAttribute(attn_kernel,    cudaFuncAttributeMaxDynamicSharedMemorySize, attn_smem);

    // K1: q = wq @ x
    gemm1x1_kernel<<<dim3(HW / 128, DIM / 128, BATCH), 256, g1_smem>>>(wq, x, qp);
    // K2a: im2col repack
    repack_kernel<<<dim3(DIM, BATCH), 256>>>(x, xrp);
    // K2b: fused k & v GEMM, split-K=4 -> partials, then deterministic reduce
    kv_gemm_kernel<<<dim3(RHW / 64, 8, BATCH * 4), 256, kv_smem>>>(wk, wv, xrp, kvpp);
    kv_reduce_kernel<<<(8 * 512 * RHW / 4) / 256, 256>>>(kvpp, kp, vp);
    // K3: fused attention (j-tiled)
    attn_kernel<<<dim3(HW / 64, HEADS, BATCH), 256, attn_smem>>>(qp, kp, vp, aop);
    // K4: out = wout @ attn_out
    gemm1x1_kernel<<<dim3(HW / 128, DIM / 128, BATCH), 256, g1_smem>>>(wout, aop, out);
}

// round 7
// speedup vs baseline: 1.4006x; 1.1694x over previous
#include <cuda_runtime.h>
#include <math.h>
#include <stdint.h>

#define BATCH 8
#define DIM 256
#define HEADS 8
#define HEAD_DIM 32
#define HW 4096
#define RHW 256
#define SCALE 0.17677669529663687f

// -------- scratch (static device globals; no cudaMalloc allowed) --------
__device__ float g_q  [BATCH * DIM * HW];      // 32 MB
__device__ float g_xr [BATCH * 4096 * RHW];    // 32 MB  (im2col-repacked x)
__device__ float g_kvp[4 * BATCH * 512 * RHW]; // 16 MB  (kv split-K partials)
__device__ float g_k  [BATCH * DIM * RHW];     // 2 MB
__device__ float g_v  [BATCH * DIM * RHW];     // 2 MB
__device__ float g_ao [BATCH * DIM * HW];      // 32 MB

// ======================= tf32 MMA helpers =======================
__device__ __forceinline__ void split_tf32(float v, uint32_t& hi, uint32_t& lo) {
    asm("cvt.rna.tf32.f32 %0, %1;" : "=r"(hi) : "f"(v));
    float r = v - __uint_as_float(hi);
    asm("cvt.rna.tf32.f32 %0, %1;" : "=r"(lo) : "f"(r));
}
__device__ __forceinline__ float2 split1(float v) {
    uint32_t hi, lo; split_tf32(v, hi, lo);
    return make_float2(__uint_as_float(hi), __uint_as_float(lo));
}
__device__ __forceinline__ void mma_tf32(float c[4], const uint32_t a[4], const uint32_t b[2]) {
    asm volatile(
        "mma.sync.aligned.m16n8k8.row.col.f32.tf32.tf32.f32 "
        "{%0,%1,%2,%3},{%4,%5,%6,%7},{%8,%9},{%0,%1,%2,%3};"
        : "+f"(c[0]), "+f"(c[1]), "+f"(c[2]), "+f"(c[3])
        : "r"(a[0]), "r"(a[1]), "r"(a[2]), "r"(a[3]), "r"(b[0]), "r"(b[1]));
}
__device__ __forceinline__ void mma3(float c[4], const uint32_t ah[4], const uint32_t al[4],
                                     const uint32_t bh[2], const uint32_t bl[2]) {
    mma_tf32(c, ah, bh);
    mma_tf32(c, al, bh);
    mma_tf32(c, ah, bl);
}

// ======================= cp.async helpers =======================
__device__ __forceinline__ void cp16(float* smem_dst, const float* gsrc) {
    uint32_t s;
    asm("{ .reg .u64 t; cvta.to.shared.u64 t, %1; cvt.u32.u64 %0, t; }"
        : "=r"(s) : "l"(smem_dst));
    asm volatile("cp.async.ca.shared.global [%0], [%1], 16;" :: "r"(s), "l"(gsrc));
}
__device__ __forceinline__ void cp_commit() { asm volatile("cp.async.commit_group;"); }
__device__ __forceinline__ void cp_wait0()  { asm volatile("cp.async.wait_group 0;"); }

// ======================= pipelined 3xTF32 GEMM body =======================
// C[(m0+r)*ldc + n0+c] = sum_{k<ksteps} A[(m0+r)*lda + k] * B[k*ldb + n0+c]
// 256 threads, warps 2(m) x 4(n). cp.async stages raw tiles for k+1 during
// the MMAs of k; hi/lo split reads each thread's own staged data.
template<int BM, int BN>
__device__ __forceinline__ void gemm3x_body(
    const float* __restrict__ A, int lda, const float* __restrict__ B, int ldb,
    float* __restrict__ C, int ldc, int ksteps, int m0, int n0, float* smem)
{
    constexpr int BK = 32;
    constexpr int LDA = BK + 4;
    constexpr int LDB = BN + 4;
    constexpr int WM = BM / 2, WN = BN / 4;
    constexpr int MT = WM / 16, NT = WN / 8;

    float* Ash  = smem;
    float* Asl  = Ash  + BM * LDA;
    float* Bsh  = Asl  + BM * LDA;
    float* Bsl  = Bsh  + BK * LDB;
    float* Araw = Bsl  + BK * LDB;    // [BM][BK] raw
    float* Braw = Araw + BM * BK;     // [BK][BN] raw

    const int tid = threadIdx.x, warp = tid >> 5, lane = tid & 31;
    const int wm = warp >> 2, wn = warp & 3;
    const int lr = lane >> 2, lc = lane & 3;

    float acc[MT][NT][4];
    #pragma unroll
    for (int i = 0; i < MT; i++)
        #pragma unroll
        for (int j = 0; j < NT; j++)
            #pragma unroll
            for (int q = 0; q < 4; q++) acc[i][j][q] = 0.f;

    auto stage = [&](int k0) {
        #pragma unroll
        for (int i = tid; i < BM * (BK / 4); i += 256) {
            int r = i / (BK / 4), c = (i % (BK / 4)) * 4;
            cp16(&Araw[r * BK + c], &A[(size_t)(m0 + r) * lda + k0 + c]);
        }
        #pragma unroll
        for (int i = tid; i < BK * (BN / 4); i += 256) {
            int r = i / (BN / 4), c = (i % (BN / 4)) * 4;
            cp16(&Braw[r * BN + c], &B[(size_t)(k0 + r) * ldb + n0 + c]);
        }
        cp_commit();
    };

    stage(0);

    for (int k0 = 0; k0 < ksteps; k0 += BK) {
        cp_wait0();
        __syncthreads();   // all MMA reads of split tiles done; raw tiles landed

        // split raw -> hi/lo smem (same indexing as the cp16s this thread issued)
        #pragma unroll
        for (int i = tid; i < BM * (BK / 4); i += 256) {
            int r = i / (BK / 4), c = (i % (BK / 4)) * 4;
            float4 a = *(float4*)&Araw[r * BK + c];
            float2 s0 = split1(a.x), s1 = split1(a.y), s2 = split1(a.z), s3 = split1(a.w);
            *(float4*)&Ash[r * LDA + c] = make_float4(s0.x, s1.x, s2.x, s3.x);
            *(float4*)&Asl[r * LDA + c] = make_float4(s0.y, s1.y, s2.y, s3.y);
        }
        #pragma unroll
        for (int i = tid; i < BK * (BN / 4); i += 256) {
            int r = i / (BN / 4), c = (i % (BN / 4)) * 4;
            float4 b = *(float4*)&Braw[r * BN + c];
            float2 s0 = split1(b.x), s1 = split1(b.y), s2 = split1(b.z), s3 = split1(b.w);
            *(float4*)&Bsh[r * LDB + c] = make_float4(s0.x, s1.x, s2.x, s3.x);
            *(float4*)&Bsl[r * LDB + c] = make_float4(s0.y, s1.y, s2.y, s3.y);
        }
        __syncthreads();   // split tiles ready; raw reads done -> safe to re-stage

        if (k0 + BK < ksteps) stage(k0 + BK);   // overlaps with MMAs below

        #pragma unroll
        for (int kk = 0; kk < BK; kk += 8) {
            uint32_t ah[MT][4], al[MT][4];
            #pragma unroll
            for (int mt = 0; mt < MT; mt++) {
                int r = wm * WM + mt * 16 + lr, c = kk + lc;
                ah[mt][0] = __float_as_uint(Ash[r * LDA + c]);
                ah[mt][1] = __float_as_uint(Ash[(r + 8) * LDA + c]);
                ah[mt][2] = __float_as_uint(Ash[r * LDA + c + 4]);
                ah[mt][3] = __float_as_uint(Ash[(r + 8) * LDA + c + 4]);
                al[mt][0] = __float_as_uint(Asl[r * LDA + c]);
                al[mt][1] = __float_as_uint(Asl[(r + 8) * LDA + c]);
                al[mt][2] = __float_as_uint(Asl[r * LDA + c + 4]);
                al[mt][3] = __float_as_uint(Asl[(r + 8) * LDA + c + 4]);
            }
            uint32_t bh[NT][2], bl[NT][2];
            #pragma unroll
            for (int nt = 0; nt < NT; nt++) {
                int cc = wn * WN + nt * 8 + lr, rr = kk + lc;
                bh[nt][0] = __float_as_uint(Bsh[rr * LDB + cc]);
                bh[nt][1] = __float_as_uint(Bsh[(rr + 4) * LDB + cc]);
                bl[nt][0] = __float_as_uint(Bsl[rr * LDB + cc]);
                bl[nt][1] = __float_as_uint(Bsl[(rr + 4) * LDB + cc]);
            }
            #pragma unroll
            for (int mt = 0; mt < MT; mt++)
                #pragma unroll
                for (int nt = 0; nt < NT; nt++)
                    mma3(acc[mt][nt], ah[mt], al[mt], bh[nt], bl[nt]);
        }
    }

    #pragma unroll
    for (int mt = 0; mt < MT; mt++) {
        int r = m0 + wm * WM + mt * 16 + lr;
        #pragma unroll
        for (int nt = 0; nt < NT; nt++) {
            int c = n0 + wn * WN + nt * 8 + lc * 2;
            *(float2*)&C[(size_t)r * ldc + c]       = make_float2(acc[mt][nt][0], acc[mt][nt][1]);
            *(float2*)&C[(size_t)(r + 8) * ldc + c] = make_float2(acc[mt][nt][2], acc[mt][nt][3]);
        }
    }
}

// K1/K4: 1x1 conv GEMM.  M=256, N=4096, K=256 per batch.
__global__ __launch_bounds__(256, 2)
void gemm1x1_kernel(const float* __restrict__ A, const float* __restrict__ Bg,
                    float* __restrict__ Cg) {
    extern __shared__ float smem[];
    const float* B = Bg + (size_t)blockIdx.z * DIM * HW;
    float*       C = Cg + (size_t)blockIdx.z * DIM * HW;
    gemm3x_body<128, 128>(A, DIM, B, HW, C, HW, DIM, blockIdx.y * 128, blockIdx.x * 128, smem);
}

// K2b: fused k&v GEMM, split-K=4. Stacked M=512 (mblk 0-3: k, 4-7: v). N=256.
__global__ __launch_bounds__(256, 2)
void kv_gemm_kernel(const float* __restrict__ Wk, const float* __restrict__ Wv,
                    const float* __restrict__ XR, float* __restrict__ Part) {
    extern __shared__ float smem[];
    const int mblk = blockIdx.y;
    const int b  = blockIdx.z & 7;
    const int ks = blockIdx.z >> 3;
    const int koff = ks * 1024;
    const float* A = (mblk < 4) ? (Wk + koff)
                                : (Wv + koff - (size_t)256 * 4096);   // un-bias stacked rows
    const float* B = XR + (size_t)b * 4096 * RHW + (size_t)koff * RHW;
    float*       C = Part + ((size_t)(ks * BATCH + b) * 512) * RHW;
    const int m0 = mblk * 64;                                          // stacked row 0..511
    gemm3x_body<64, 64>(A, 4096, B, RHW, C, RHW, 1024, m0, blockIdx.x * 64, smem);
}

// reduce the 4 split-K partials into g_k / g_v.
__global__ __launch_bounds__(256)
void kv_reduce_kernel(const float* __restrict__ P, float* __restrict__ Kout,
                      float* __restrict__ Vout) {
    const int idx = blockIdx.x * 256 + threadIdx.x;     // float4 index
    const float4* p = (const float4*)P;
    const int CH = 8 * 512 * RHW / 4;                    // float4 per split chunk
    float4 a = p[idx], b4 = p[idx + CH], c4 = p[idx + 2 * CH], d4 = p[idx + 3 * CH];
    float4 s = make_float4(a.x + b4.x + c4.x + d4.x, a.y + b4.y + c4.y + d4.y,
                           a.z + b4.z + c4.z + d4.z, a.w + b4.w + c4.w + d4.w);
    const int f = idx * 4;
    const int n = f & 255, m = (f >> 8) & 511, b = f >> 17;
    float* dst = (m < 256) ? (Kout + ((size_t)b * DIM + m) * RHW + n)
                           : (Vout + ((size_t)b * DIM + (m - 256)) * RHW + n);
    *(float4*)dst = s;
}

// ======================= im2col repack =======================
__global__ __launch_bounds__(256)
void repack_kernel(const float* __restrict__ X, float* __restrict__ XR) {
    __shared__ float pl[4096];
    const int ci = blockIdx.x, b = blockIdx.y, tid = threadIdx.x;
    const float* src = X + ((size_t)b * DIM + ci) * HW;
    #pragma unroll
    for (int i = tid; i < 1024; i += 256)
        ((float4*)pl)[i] = ((const float4*)src)[i];
    __syncthreads();
    const int oh = tid >> 4, ow = tid & 15;
    float* dst = XR + ((size_t)b * 4096 + ci * 16) * RHW;
    #pragma unroll
    for (int kh = 0; kh < 4; kh++)
        #pragma unroll
        for (int kw = 0; kw < 4; kw++)
            dst[(kh * 4 + kw) * RHW + tid] = pl[(oh * 4 + kh) * 64 + ow * 4 + kw];
}

// ======================= fused attention: j-tiled, O in registers =======================
// i-tile 64, j-tile 64 (4 tiles). smem ~88 KB -> 2 CTAs/SM.
__global__ __launch_bounds__(256, 2)
void attn_kernel(const float* __restrict__ Q, const float* __restrict__ Kg,
                 const float* __restrict__ Vg, float* __restrict__ O) {
    extern __shared__ float sm[];
    float* qsh = sm;                // [64][36]
    float* qsl = qsh + 2304;
    float* kth = qsl + 2304;        // [32][68]
    float* ktl = kth + 2176;
    float* vth = ktl + 2176;        // [64][36]
    float* vtl = vth + 2304;
    float* psh = vtl + 2304;        // [64][68]
    float* psl = psh + 4352;
    float* lacc = psl + 4352;       // [4][64] per-wn row-sum partials
    float* li  = lacc + 256;        // [64]
    float* po  = kth;               // [64][36] final staging (aliases dead K tile)

    const int tid = threadIdx.x, warp = tid >> 5, lane = tid & 31;
    const int lr = lane >> 2, lc = lane & 3;
    const int wm = warp >> 2, wn = warp & 3;      // S-phase mapping
    const int iw = (warp & 3) * 16;                // PV-phase i-strip
    const int db = (warp >> 2) * 16;               // PV-phase d-strip
    const int b = blockIdx.z, h = blockIdx.y, i0 = blockIdx.x * 64;

    const float* Qb = Q  + ((size_t)b * DIM + h * HEAD_DIM) * HW + i0;
    const float* Kb = Kg + ((size_t)b * DIM + h * HEAD_DIM) * RHW;
    const float* Vb = Vg + ((size_t)b * DIM + h * HEAD_DIM) * RHW;

    // load q (transpose to [i][d], scale, split)
    for (int idx = tid; idx < 64 * 32; idx += 256) {
        int d = idx >> 6, i = idx & 63;
        float2 s = split1(Qb[(size_t)d * HW + i] * SCALE);
        qsh[i * 36 + d] = s.x;
        qsl[i * 36 + d] = s.y;
    }
    lacc[tid] = 0.f;   // 4*64 == blockDim

    float oacc[2][4];
    #pragma unroll
    for (int nt = 0; nt < 2; nt++)
        #pragma unroll
        for (int q = 0; q < 4; q++) oacc[nt][q] = 0.f;

    for (int jt = 0; jt < 4; jt++) {
        const int j0 = jt * 64;
        __syncthreads();   // prev tile's PV reads done
        // K tile [32][64] split (coalesced along j)
        for (int idx = tid; idx < 2048; idx += 256) {
            int d = idx >> 6, j = idx & 63;
            float2 s = split1(Kb[(size_t)d * RHW + j0 + j]);
            kth[d * 68 + j] = s.x;
            ktl[d * 68 + j] = s.y;
        }
        // V tile transposed to [j][d], split
        for (int idx = tid; idx < 2048; idx += 256) {
            int d = idx >> 6, j = idx & 63;
            float2 s = split1(Vb[(size_t)d * RHW + j0 + j]);
            vth[j * 36 + d] = s.x;
            vtl[j * 36 + d] = s.y;
        }
        __syncthreads();

        // ---- S tile = qs * ktᵀ : M=64, N=64, K=32. warp tile 32x16 ----
        float sacc[2][2][4];
        #pragma unroll
        for (int mt = 0; mt < 2; mt++)
            #pragma unroll
            for (int nt = 0; nt < 2; nt++)
                #pragma unroll
                for (int q = 0; q < 4; q++) sacc[mt][nt][q] = 0.f;

        #pragma unroll
        for (int kk = 0; kk < 32; kk += 8) {
            uint32_t ah[2][4], al[2][4];
            #pragma unroll
            for (int mt = 0; mt < 2; mt++) {
                int r = wm * 32 + mt * 16 + lr, c = kk + lc;
                ah[mt][0] = __float_as_uint(qsh[r * 36 + c]);
                ah[mt][1] = __float_as_uint(qsh[(r + 8) * 36 + c]);
                ah[mt][2] = __float_as_uint(qsh[r * 36 + c + 4]);
                ah[mt][3] = __float_as_uint(qsh[(r + 8) * 36 + c + 4]);
                al[mt][0] = __float_as_uint(qsl[r * 36 + c]);
                al[mt][1] = __float_as_uint(qsl[(r + 8) * 36 + c]);
                al[mt][2] = __float_as_uint(qsl[r * 36 + c + 4]);
                al[mt][3] = __float_as_uint(qsl[(r + 8) * 36 + c + 4]);
            }
            uint32_t bh[2][2], bl[2][2];
            #pragma unroll
            for (int nt = 0; nt < 2; nt++) {
                int jj = wn * 16 + nt * 8 + lr, rr = kk + lc;
                bh[nt][0] = __float_as_uint(kth[rr * 68 + jj]);
                bh[nt][1] = __float_as_uint(kth[(rr + 4) * 68 + jj]);
                bl[nt][0] = __float_as_uint(ktl[rr * 68 + jj]);
                bl[nt][1] = __float_as_uint(ktl[(rr + 4) * 68 + jj]);
            }
            #pragma unroll
            for (int mt = 0; mt < 2; mt++)
                #pragma unroll
                for (int nt = 0; nt < 2; nt++)
                    mma3(sacc[mt][nt], ah[mt], al[mt], bh[nt], bl[nt]);
        }

        // ---- exp -> ps (pre-split), accumulate row sums ----
        #pragma unroll
        for (int mt = 0; mt < 2; mt++) {
            int r = wm * 32 + mt * 16 + lr;
            float rs0 = 0.f, rs1 = 0.f;
            #pragma unroll
            for (int nt = 0; nt < 2; nt++) {
                int c = wn * 16 + nt * 8 + lc * 2;
                float e0 = __expf(sacc[mt][nt][0]);
                float e1 = __expf(sacc[mt][nt][1]);
                float e2 = __expf(sacc[mt][nt][2]);
                float e3 = __expf(sacc[mt][nt][3]);
                float2 s0 = split1(e0), s1 = split1(e1), s2 = split1(e2), s3 = split1(e3);
                psh[r * 68 + c]           = s0.x;  psl[r * 68 + c]           = s0.y;
                psh[r * 68 + c + 1]       = s1.x;  psl[r * 68 + c + 1]       = s1.y;
                psh[(r + 8) * 68 + c]     = s2.x;  psl[(r + 8) * 68 + c]     = s2.y;
                psh[(r + 8) * 68 + c + 1] = s3.x;  psl[(r + 8) * 68 + c + 1] = s3.y;
                rs0 += e0 + e1;
                rs1 += e2 + e3;
            }
            rs0 += __shfl_xor_sync(0xFFFFFFFFu, rs0, 1);
            rs0 += __shfl_xor_sync(0xFFFFFFFFu, rs0, 2);
            rs1 += __shfl_xor_sync(0xFFFFFFFFu, rs1, 1);
            rs1 += __shfl_xor_sync(0xFFFFFFFFu, rs1, 2);
            if (lc == 0) {
                lacc[wn * 64 + r]     += rs0;
                lacc[wn * 64 + r + 8] += rs1;
            }
        }
        __syncthreads();

        // ---- PV accumulate: O[iw..+16][db..+16] += P_tile * V_tile ----
        #pragma unroll
        for (int kk = 0; kk < 64; kk += 8) {
            uint32_t ah[4], al[4];
            int r = iw + lr, c = kk + lc;
            ah[0] = __float_as_uint(psh[r * 68 + c]);
            ah[1] = __float_as_uint(psh[(r + 8) * 68 + c]);
            ah[2] = __float_as_uint(psh[r * 68 + c + 4]);
            ah[3] = __float_as_uint(psh[(r + 8) * 68 + c + 4]);
            al[0] = __float_as_uint(psl[r * 68 + c]);
            al[1] = __float_as_uint(psl[(r + 8) * 68 + c]);
            al[2] = __float_as_uint(psl[r * 68 + c + 4]);
            al[3] = __float_as_uint(psl[(r + 8) * 68 + c + 4]);
            #pragma unroll
            for (int nt = 0; nt < 2; nt++) {
                uint32_t bh[2], bl[2];
                int d = db + nt * 8 + lr, rr = kk + lc;
                bh[0] = __float_as_uint(vth[rr * 36 + d]);
                bh[1] = __float_as_uint(vth[(rr + 4) * 36 + d]);
                bl[0] = __float_as_uint(vtl[rr * 36 + d]);
                bl[1] = __float_as_uint(vtl[(rr + 4) * 36 + d]);
                mma3(oacc[nt], ah, al, bh, bl);
            }
        }
    }

    __syncthreads();
    if (tid < 64)
        li[tid] = 1.f / (lacc[tid] + lacc[64 + tid] + lacc[128 + tid] + lacc[192 + tid]);
    __syncthreads();

    // normalize + stage to po (aliases dead K tile)
    #pragma unroll
    for (int nt = 0; nt < 2; nt++) {
        int r = iw + lr, c = db + nt * 8 + lc * 2;
        float inv0 = li[r], inv1 = li[r + 8];
        po[r * 36 + c]           = oacc[nt][0] * inv0;
        po[r * 36 + c + 1]       = oacc[nt][1] * inv0;
        po[(r + 8) * 36 + c]     = oacc[nt][2] * inv1;
        po[(r + 8) * 36 + c + 1] = oacc[nt][3] * inv1;
    }
    __syncthreads();

    // coalesced transposed store: O[d][i]
    float* Ob = O + ((size_t)b * DIM + h * HEAD_DIM) * HW + i0;
    for (int idx = tid; idx < 64 * 32; idx += 256) {
        int d = idx >> 6, i = idx & 63;
        Ob[(size_t)d * HW + i] = po[i * 36 + d];
    }
}

// ============================================================================
extern "C" void kernel_launch(void* const* d_in, const int* in_sizes, int n_in,
                              void* d_out, int out_size) {
    const float* x    = (const float*)d_in[0];
    const float* wq   = (const float*)d_in[1];
    const float* wk   = (const float*)d_in[2];
    const float* wv   = (const float*)d_in[3];
    const float* wout = (const float*)d_in[4];
    float* out = (float*)d_out;

    float *qp, *xrp, *kvpp, *kp, *vp, *aop;
    cudaGetSymbolAddress((void**)&qp,   g_q);
    cudaGetSymbolAddress((void**)&xrp,  g_xr);
    cudaGetSymbolAddress((void**)&kvpp, g_kvp);
    cudaGetSymbolAddress((void**)&kp,   g_k);
    cudaGetSymbolAddress((void**)&vp,   g_v);
    cudaGetSymbolAddress((void**)&aop,  g_ao);

    // split smem + raw staging buffers
    const int g1_smem   = ((128*36*2 + 32*132*2) + (128*32 + 32*128)) * (int)sizeof(float); // ~101 KB
    const int kv_smem   = ((64*36*2 + 32*68*2)   + (64*32 + 32*64))   * (int)sizeof(float); // ~51 KB
    const int attn_smem = (2*2304 + 2*2176 + 2*2304 + 2*4352 + 256 + 64) * (int)sizeof(float); // ~88.2 KB

    cudaFuncSetAttribute(gemm1x1_kernel, cudaFuncAttributeMaxDynamicSharedMemorySize, g1_smem);
    cudaFuncSetAttribute(kv_gemm_kernel, cudaFuncAttributeMaxDynamicSharedMemorySize, kv_smem);
    cudaFuncSetAttribute(attn_kernel,    cudaFuncAttributeMaxDynamicSharedMemorySize, attn_smem);

    // K1: q = wq @ x
    gemm1x1_kernel<<<dim3(HW / 128, DIM / 128, BATCH), 256, g1_smem>>>(wq, x, qp);
    // K2a: im2col repack
    repack_kernel<<<dim3(DIM, BATCH), 256>>>(x, xrp);
    // K2b: fused k & v GEMM, split-K=4 -> partials, then deterministic reduce
    kv_gemm_kernel<<<dim3(RHW / 64, 8, BATCH * 4), 256, kv_smem>>>(wk, wv, xrp, kvpp);
    kv_reduce_kernel<<<(8 * 512 * RHW / 4) / 256, 256>>>(kvpp, kp, vp);
    // K3: fused attention (j-tiled)
    attn_kernel<<<dim3(HW / 64, HEADS, BATCH), 256, attn_smem>>>(qp, kp, vp, aop);
    // K4: out = wout @ attn_out
    gemm1x1_kernel<<<dim3(HW / 128, DIM / 128, BATCH), 256, g1_smem>>>(wout, aop, out);
}

// round 8
// speedup vs baseline: 1.4425x; 1.0299x over previous
#include <cuda_runtime.h>
#include <math.h>
#include <stdint.h>

#define BATCH 8
#define DIM 256
#define HEADS 8
#define HEAD_DIM 32
#define HW 4096
#define RHW 256
#define SCALE 0.17677669529663687f

// -------- scratch (static device globals; no cudaMalloc allowed) --------
__device__ float g_q  [BATCH * DIM * HW];      // 32 MB
__device__ float g_xr [BATCH * 4096 * RHW];    // 32 MB  (im2col-repacked x)
__device__ float g_kvp[4 * BATCH * 512 * RHW]; // 16 MB  (kv split-K partials)
__device__ float g_k  [BATCH * DIM * RHW];     // 2 MB
__device__ float g_v  [BATCH * DIM * RHW];     // 2 MB
__device__ float g_ao [BATCH * DIM * HW];      // 32 MB

// ======================= tf32 MMA helpers =======================
__device__ __forceinline__ void split_tf32(float v, uint32_t& hi, uint32_t& lo) {
    asm("cvt.rna.tf32.f32 %0, %1;" : "=r"(hi) : "f"(v));
    float r = v - __uint_as_float(hi);
    asm("cvt.rna.tf32.f32 %0, %1;" : "=r"(lo) : "f"(r));
}
__device__ __forceinline__ float2 split1(float v) {
    uint32_t hi, lo; split_tf32(v, hi, lo);
    return make_float2(__uint_as_float(hi), __uint_as_float(lo));
}
__device__ __forceinline__ void mma_tf32(float c[4], const uint32_t a[4], const uint32_t b[2]) {
    asm volatile(
        "mma.sync.aligned.m16n8k8.row.col.f32.tf32.tf32.f32 "
        "{%0,%1,%2,%3},{%4,%5,%6,%7},{%8,%9},{%0,%1,%2,%3};"
        : "+f"(c[0]), "+f"(c[1]), "+f"(c[2]), "+f"(c[3])
        : "r"(a[0]), "r"(a[1]), "r"(a[2]), "r"(a[3]), "r"(b[0]), "r"(b[1]));
}
__device__ __forceinline__ void mma3(float c[4], const uint32_t ah[4], const uint32_t al[4],
                                     const uint32_t bh[2], const uint32_t bl[2]) {
    mma_tf32(c, ah, bh);
    mma_tf32(c, al, bh);
    mma_tf32(c, ah, bl);
}

// ======================= cp.async helpers =======================
__device__ __forceinline__ void cp16(float* smem_dst, const float* gsrc) {
    uint32_t s;
    asm("{ .reg .u64 t; cvta.to.shared.u64 t, %1; cvt.u32.u64 %0, t; }"
        : "=r"(s) : "l"(smem_dst));
    asm volatile("cp.async.ca.shared.global [%0], [%1], 16;" :: "r"(s), "l"(gsrc));
}
__device__ __forceinline__ void cp_commit() { asm volatile("cp.async.commit_group;"); }
__device__ __forceinline__ void cp_wait0()  { asm volatile("cp.async.wait_group 0;"); }

// ======================= pipelined 3xTF32 GEMM body =======================
// C[(m0+r)*ldc + n0+c] = sum_{k<ksteps} A[(m0+r)*lda + k] * B[k*ldb + n0+c]
// 256 threads, warps 2(m) x 4(n). cp.async stages raw tiles for k+1 during
// the MMAs of k; hi/lo split reads each thread's own staged data.
template<int BM, int BN>
__device__ __forceinline__ void gemm3x_body(
    const float* __restrict__ A, int lda, const float* __restrict__ B, int ldb,
    float* __restrict__ C, int ldc, int ksteps, int m0, int n0, float* smem)
{
    constexpr int BK = 32;
    constexpr int LDA = BK + 4;
    constexpr int LDB = BN + 4;
    constexpr int WM = BM / 2, WN = BN / 4;
    constexpr int MT = WM / 16, NT = WN / 8;

    float* Ash  = smem;
    float* Asl  = Ash  + BM * LDA;
    float* Bsh  = Asl  + BM * LDA;
    float* Bsl  = Bsh  + BK * LDB;
    float* Araw = Bsl  + BK * LDB;    // [BM][BK] raw
    float* Braw = Araw + BM * BK;     // [BK][BN] raw

    const int tid = threadIdx.x, warp = tid >> 5, lane = tid & 31;
    const int wm = warp >> 2, wn = warp & 3;
    const int lr = lane >> 2, lc = lane & 3;

    float acc[MT][NT][4];
    #pragma unroll
    for (int i = 0; i < MT; i++)
        #pragma unroll
        for (int j = 0; j < NT; j++)
            #pragma unroll
            for (int q = 0; q < 4; q++) acc[i][j][q] = 0.f;

    auto stage = [&](int k0) {
        #pragma unroll
        for (int i = tid; i < BM * (BK / 4); i += 256) {
            int r = i / (BK / 4), c = (i % (BK / 4)) * 4;
            cp16(&Araw[r * BK + c], &A[(size_t)(m0 + r) * lda + k0 + c]);
        }
        #pragma unroll
        for (int i = tid; i < BK * (BN / 4); i += 256) {
            int r = i / (BN / 4), c = (i % (BN / 4)) * 4;
            cp16(&Braw[r * BN + c], &B[(size_t)(k0 + r) * ldb + n0 + c]);
        }
        cp_commit();
    };

    stage(0);

    for (int k0 = 0; k0 < ksteps; k0 += BK) {
        cp_wait0();
        __syncthreads();   // all MMA reads of split tiles done; raw tiles landed

        // split raw -> hi/lo smem
        #pragma unroll
        for (int i = tid; i < BM * (BK / 4); i += 256) {
            int r = i / (BK / 4), c = (i % (BK / 4)) * 4;
            float4 a = *(float4*)&Araw[r * BK + c];
            float2 s0 = split1(a.x), s1 = split1(a.y), s2 = split1(a.z), s3 = split1(a.w);
            *(float4*)&Ash[r * LDA + c] = make_float4(s0.x, s1.x, s2.x, s3.x);
            *(float4*)&Asl[r * LDA + c] = make_float4(s0.y, s1.y, s2.y, s3.y);
        }
        #pragma unroll
        for (int i = tid; i < BK * (BN / 4); i += 256) {
            int r = i / (BN / 4), c = (i % (BN / 4)) * 4;
            float4 b = *(float4*)&Braw[r * BN + c];
            float2 s0 = split1(b.x), s1 = split1(b.y), s2 = split1(b.z), s3 = split1(b.w);
            *(float4*)&Bsh[r * LDB + c] = make_float4(s0.x, s1.x, s2.x, s3.x);
            *(float4*)&Bsl[r * LDB + c] = make_float4(s0.y, s1.y, s2.y, s3.y);
        }
        __syncthreads();   // split tiles ready; raw reads done -> safe to re-stage

        if (k0 + BK < ksteps) stage(k0 + BK);   // overlaps with MMAs below

        #pragma unroll
        for (int kk = 0; kk < BK; kk += 8) {
            uint32_t ah[MT][4], al[MT][4];
            #pragma unroll
            for (int mt = 0; mt < MT; mt++) {
                int r = wm * WM + mt * 16 + lr, c = kk + lc;
                ah[mt][0] = __float_as_uint(Ash[r * LDA + c]);
                ah[mt][1] = __float_as_uint(Ash[(r + 8) * LDA + c]);
                ah[mt][2] = __float_as_uint(Ash[r * LDA + c + 4]);
                ah[mt][3] = __float_as_uint(Ash[(r + 8) * LDA + c + 4]);
                al[mt][0] = __float_as_uint(Asl[r * LDA + c]);
                al[mt][1] = __float_as_uint(Asl[(r + 8) * LDA + c]);
                al[mt][2] = __float_as_uint(Asl[r * LDA + c + 4]);
                al[mt][3] = __float_as_uint(Asl[(r + 8) * LDA + c + 4]);
            }
            uint32_t bh[NT][2], bl[NT][2];
            #pragma unroll
            for (int nt = 0; nt < NT; nt++) {
                int cc = wn * WN + nt * 8 + lr, rr = kk + lc;
                bh[nt][0] = __float_as_uint(Bsh[rr * LDB + cc]);
                bh[nt][1] = __float_as_uint(Bsh[(rr + 4) * LDB + cc]);
                bl[nt][0] = __float_as_uint(Bsl[rr * LDB + cc]);
                bl[nt][1] = __float_as_uint(Bsl[(rr + 4) * LDB + cc]);
            }
            #pragma unroll
            for (int mt = 0; mt < MT; mt++)
                #pragma unroll
                for (int nt = 0; nt < NT; nt++)
                    mma3(acc[mt][nt], ah[mt], al[mt], bh[nt], bl[nt]);
        }
    }

    #pragma unroll
    for (int mt = 0; mt < MT; mt++) {
        int r = m0 + wm * WM + mt * 16 + lr;
        #pragma unroll
        for (int nt = 0; nt < NT; nt++) {
            int c = n0 + wn * WN + nt * 8 + lc * 2;
            *(float2*)&C[(size_t)r * ldc + c]       = make_float2(acc[mt][nt][0], acc[mt][nt][1]);
            *(float2*)&C[(size_t)(r + 8) * ldc + c] = make_float2(acc[mt][nt][2], acc[mt][nt][3]);
        }
    }
}

// K1/K4: 1x1 conv GEMM.  M=256, N=4096, K=256 per batch.
__global__ __launch_bounds__(256, 2)
void gemm1x1_kernel(const float* __restrict__ A, const float* __restrict__ Bg,
                    float* __restrict__ Cg) {
    extern __shared__ float smem[];
    const float* B = Bg + (size_t)blockIdx.z * DIM * HW;
    float*       C = Cg + (size_t)blockIdx.z * DIM * HW;
    gemm3x_body<128, 128>(A, DIM, B, HW, C, HW, DIM, blockIdx.y * 128, blockIdx.x * 128, smem);
}

// K2b: fused k&v GEMM, split-K=4. Stacked M=512 (mblk 0-3: k, 4-7: v). N=256.
__global__ __launch_bounds__(256, 2)
void kv_gemm_kernel(const float* __restrict__ Wk, const float* __restrict__ Wv,
                    const float* __restrict__ XR, float* __restrict__ Part) {
    extern __shared__ float smem[];
    const int mblk = blockIdx.y;
    const int b  = blockIdx.z & 7;
    const int ks = blockIdx.z >> 3;
    const int koff = ks * 1024;
    const float* A = (mblk < 4) ? (Wk + koff)
                                : (Wv + koff - (size_t)256 * 4096);   // un-bias stacked rows
    const float* B = XR + (size_t)b * 4096 * RHW + (size_t)koff * RHW;
    float*       C = Part + ((size_t)(ks * BATCH + b) * 512) * RHW;
    const int m0 = mblk * 64;                                          // stacked row 0..511
    gemm3x_body<64, 64>(A, 4096, B, RHW, C, RHW, 1024, m0, blockIdx.x * 64, smem);
}

// reduce the 4 split-K partials into g_k / g_v.
__global__ __launch_bounds__(256)
void kv_reduce_kernel(const float* __restrict__ P, float* __restrict__ Kout,
                      float* __restrict__ Vout) {
    const int idx = blockIdx.x * 256 + threadIdx.x;     // float4 index
    const float4* p = (const float4*)P;
    const int CH = 8 * 512 * RHW / 4;                    // float4 per split chunk
    float4 a = p[idx], b4 = p[idx + CH], c4 = p[idx + 2 * CH], d4 = p[idx + 3 * CH];
    float4 s = make_float4(a.x + b4.x + c4.x + d4.x, a.y + b4.y + c4.y + d4.y,
                           a.z + b4.z + c4.z + d4.z, a.w + b4.w + c4.w + d4.w);
    const int f = idx * 4;
    const int n = f & 255, m = (f >> 8) & 511, b = f >> 17;
    float* dst = (m < 256) ? (Kout + ((size_t)b * DIM + m) * RHW + n)
                           : (Vout + ((size_t)b * DIM + (m - 256)) * RHW + n);
    *(float4*)dst = s;
}

// ======================= im2col repack =======================
__global__ __launch_bounds__(256)
void repack_kernel(const float* __restrict__ X, float* __restrict__ XR) {
    __shared__ float pl[4096];
    const int ci = blockIdx.x, b = blockIdx.y, tid = threadIdx.x;
    const float* src = X + ((size_t)b * DIM + ci) * HW;
    #pragma unroll
    for (int i = tid; i < 1024; i += 256)
        ((float4*)pl)[i] = ((const float4*)src)[i];
    __syncthreads();
    const int oh = tid >> 4, ow = tid & 15;
    float* dst = XR + ((size_t)b * 4096 + ci * 16) * RHW;
    #pragma unroll
    for (int kh = 0; kh < 4; kh++)
        #pragma unroll
        for (int kw = 0; kw < 4; kw++)
            dst[(kh * 4 + kw) * RHW + tid] = pl[(oh * 4 + kh) * 64 + ow * 4 + kw];
}

// ======================= fused attention: j-tiled, cp.async staged K/V =======================
// i-tile 64, j-tile 64 (4 tiles). smem ~104 KB -> 2 CTAs/SM.
__global__ __launch_bounds__(256, 2)
void attn_kernel(const float* __restrict__ Q, const float* __restrict__ Kg,
                 const float* __restrict__ Vg, float* __restrict__ O) {
    extern __shared__ float sm[];
    float* qsh = sm;                // [64][36]
    float* qsl = qsh + 2304;
    float* kth = qsl + 2304;        // [32][68]
    float* ktl = kth + 2176;
    float* vth = ktl + 2176;        // [64][36]
    float* vtl = vth + 2304;
    float* psh = vtl + 2304;        // [64][68]
    float* psl = psh + 4352;
    float* lacc = psl + 4352;       // [4][64] per-wn row-sum partials
    float* li  = lacc + 256;        // [64]
    float* kraw = li + 64;          // [32][64] raw K tile (cp.async target)
    float* vraw = kraw + 2048;      // [32][64] raw V tile
    float* po  = kth;               // [64][36] final staging (aliases dead K tile)

    const int tid = threadIdx.x, warp = tid >> 5, lane = tid & 31;
    const int lr = lane >> 2, lc = lane & 3;
    const int wm = warp >> 2, wn = warp & 3;      // S-phase mapping
    const int iw = (warp & 3) * 16;                // PV-phase i-strip
    const int db = (warp >> 2) * 16;               // PV-phase d-strip
    const int b = blockIdx.z, h = blockIdx.y, i0 = blockIdx.x * 64;

    const float* Qb = Q  + ((size_t)b * DIM + h * HEAD_DIM) * HW + i0;
    const float* Kb = Kg + ((size_t)b * DIM + h * HEAD_DIM) * RHW;
    const float* Vb = Vg + ((size_t)b * DIM + h * HEAD_DIM) * RHW;

    auto stageKV = [&](int j0) {
        #pragma unroll
        for (int idx = tid; idx < 512; idx += 256) {     // 2048 floats / 4
            int d = idx >> 4, j4 = (idx & 15) * 4;
            cp16(&kraw[d * 64 + j4], &Kb[(size_t)d * RHW + j0 + j4]);
            cp16(&vraw[d * 64 + j4], &Vb[(size_t)d * RHW + j0 + j4]);
        }
        cp_commit();
    };

    stageKV(0);   // get tile 0 in flight before anything else

    // load q (transpose to [i][d], scale, split) — overlaps with staged cp group
    for (int idx = tid; idx < 64 * 32; idx += 256) {
        int d = idx >> 6, i = idx & 63;
        float2 s = split1(Qb[(size_t)d * HW + i] * SCALE);
        qsh[i * 36 + d] = s.x;
        qsl[i * 36 + d] = s.y;
    }
    lacc[tid] = 0.f;   // 4*64 == blockDim

    float oacc[2][4];
    #pragma unroll
    for (int nt = 0; nt < 2; nt++)
        #pragma unroll
        for (int q = 0; q < 4; q++) oacc[nt][q] = 0.f;

    for (int jt = 0; jt < 4; jt++) {
        cp_wait0();
        __syncthreads();   // raw tiles landed; prev tile's PV reads of vth done

        // split raw K -> kth/ktl, transpose-split raw V -> vth/vtl
        for (int idx = tid; idx < 2048; idx += 256) {
            int d = idx >> 6, j = idx & 63;
            float2 sk = split1(kraw[d * 64 + j]);
            kth[d * 68 + j] = sk.x;
            ktl[d * 68 + j] = sk.y;
            float2 sv = split1(vraw[d * 64 + j]);
            vth[j * 36 + d] = sv.x;
            vtl[j * 36 + d] = sv.y;
        }
        __syncthreads();   // split tiles ready; raw consumed -> safe to re-stage

        if (jt < 3) stageKV((jt + 1) * 64);   // overlaps with S/exp/PV below

        // ---- S tile = qs * ktᵀ : M=64, N=64, K=32. warp tile 32x16 ----
        float sacc[2][2][4];
        #pragma unroll
        for (int mt = 0; mt < 2; mt++)
            #pragma unroll
            for (int nt = 0; nt < 2; nt++)
                #pragma unroll
                for (int q = 0; q < 4; q++) sacc[mt][nt][q] = 0.f;

        #pragma unroll
        for (int kk = 0; kk < 32; kk += 8) {
            uint32_t ah[2][4], al[2][4];
            #pragma unroll
            for (int mt = 0; mt < 2; mt++) {
                int r = wm * 32 + mt * 16 + lr, c = kk + lc;
                ah[mt][0] = __float_as_uint(qsh[r * 36 + c]);
                ah[mt][1] = __float_as_uint(qsh[(r + 8) * 36 + c]);
                ah[mt][2] = __float_as_uint(qsh[r * 36 + c + 4]);
                ah[mt][3] = __float_as_uint(qsh[(r + 8) * 36 + c + 4]);
                al[mt][0] = __float_as_uint(qsl[r * 36 + c]);
                al[mt][1] = __float_as_uint(qsl[(r + 8) * 36 + c]);
                al[mt][2] = __float_as_uint(qsl[r * 36 + c + 4]);
                al[mt][3] = __float_as_uint(qsl[(r + 8) * 36 + c + 4]);
            }
            uint32_t bh[2][2], bl[2][2];
            #pragma unroll
            for (int nt = 0; nt < 2; nt++) {
                int jj = wn * 16 + nt * 8 + lr, rr = kk + lc;
                bh[nt][0] = __float_as_uint(kth[rr * 68 + jj]);
                bh[nt][1] = __float_as_uint(kth[(rr + 4) * 68 + jj]);
                bl[nt][0] = __float_as_uint(ktl[rr * 68 + jj]);
                bl[nt][1] = __float_as_uint(ktl[(rr + 4) * 68 + jj]);
            }
            #pragma unroll
            for (int mt = 0; mt < 2; mt++)
                #pragma unroll
                for (int nt = 0; nt < 2; nt++)
                    mma3(sacc[mt][nt], ah[mt], al[mt], bh[nt], bl[nt]);
        }

        // ---- exp -> ps (pre-split), accumulate row sums ----
        #pragma unroll
        for (int mt = 0; mt < 2; mt++) {
            int r = wm * 32 + mt * 16 + lr;
            float rs0 = 0.f, rs1 = 0.f;
            #pragma unroll
            for (int nt = 0; nt < 2; nt++) {
                int c = wn * 16 + nt * 8 + lc * 2;
                float e0 = __expf(sacc[mt][nt][0]);
                float e1 = __expf(sacc[mt][nt][1]);
                float e2 = __expf(sacc[mt][nt][2]);
                float e3 = __expf(sacc[mt][nt][3]);
                float2 s0 = split1(e0), s1 = split1(e1), s2 = split1(e2), s3 = split1(e3);
                psh[r * 68 + c]           = s0.x;  psl[r * 68 + c]           = s0.y;
                psh[r * 68 + c + 1]       = s1.x;  psl[r * 68 + c + 1]       = s1.y;
                psh[(r + 8) * 68 + c]     = s2.x;  psl[(r + 8) * 68 + c]     = s2.y;
                psh[(r + 8) * 68 + c + 1] = s3.x;  psl[(r + 8) * 68 + c + 1] = s3.y;
                rs0 += e0 + e1;
                rs1 += e2 + e3;
            }
            rs0 += __shfl_xor_sync(0xFFFFFFFFu, rs0, 1);
            rs0 += __shfl_xor_sync(0xFFFFFFFFu, rs0, 2);
            rs1 += __shfl_xor_sync(0xFFFFFFFFu, rs1, 1);
            rs1 += __shfl_xor_sync(0xFFFFFFFFu, rs1, 2);
            if (lc == 0) {
                lacc[wn * 64 + r]     += rs0;
                lacc[wn * 64 + r + 8] += rs1;
            }
        }
        __syncthreads();

        // ---- PV accumulate: O[iw..+16][db..+16] += P_tile * V_tile ----
        #pragma unroll
        for (int kk = 0; kk < 64; kk += 8) {
            uint32_t ah[4], al[4];
            int r = iw + lr, c = kk + lc;
            ah[0] = __float_as_uint(psh[r * 68 + c]);
            ah[1] = __float_as_uint(psh[(r + 8) * 68 + c]);
            ah[2] = __float_as_uint(psh[r * 68 + c + 4]);
            ah[3] = __float_as_uint(psh[(r + 8) * 68 + c + 4]);
            al[0] = __float_as_uint(psl[r * 68 + c]);
            al[1] = __float_as_uint(psl[(r + 8) * 68 + c]);
            al[2] = __float_as_uint(psl[r * 68 + c + 4]);
            al[3] = __float_as_uint(psl[(r + 8) * 68 + c + 4]);
            #pragma unroll
            for (int nt = 0; nt < 2; nt++) {
                uint32_t bh[2], bl[2];
                int d = db + nt * 8 + lr, rr = kk + lc;
                bh[0] = __float_as_uint(vth[rr * 36 + d]);
                bh[1] = __float_as_uint(vth[(rr + 4) * 36 + d]);
                bl[0] = __float_as_uint(vtl[rr * 36 + d]);
                bl[1] = __float_as_uint(vtl[(rr + 4) * 36 + d]);
                mma3(oacc[nt], ah, al, bh, bl);
            }
        }
    }

    __syncthreads();
    if (tid < 64)
        li[tid] = 1.f / (lacc[tid] + lacc[64 + tid] + lacc[128 + tid] + lacc[192 + tid]);
    __syncthreads();

    // normalize + stage to po (aliases dead K tile)
    #pragma unroll
    for (int nt = 0; nt < 2; nt++) {
        int r = iw + lr, c = db + nt * 8 + lc * 2;
        float inv0 = li[r], inv1 = li[r + 8];
        po[r * 36 + c]           = oacc[nt][0] * inv0;
        po[r * 36 + c + 1]       = oacc[nt][1] * inv0;
        po[(r + 8) * 36 + c]     = oacc[nt][2] * inv1;
        po[(r + 8) * 36 + c + 1] = oacc[nt][3] * inv1;
    }
    __syncthreads();

    // coalesced transposed store: O[d][i]
    float* Ob = O + ((size_t)b * DIM + h * HEAD_DIM) * HW + i0;
    for (int idx = tid; idx < 64 * 32; idx += 256) {
        int d = idx >> 6, i = idx & 63;
        Ob[(size_t)d * HW + i] = po[i * 36 + d];
    }
}

// ============================================================================
extern "C" void kernel_launch(void* const* d_in, const int* in_sizes, int n_in,
                              void* d_out, int out_size) {
    const float* x    = (const float*)d_in[0];
    const float* wq   = (const float*)d_in[1];
    const float* wk   = (const float*)d_in[2];
    const float* wv   = (const float*)d_in[3];
    const float* wout = (const float*)d_in[4];
    float* out = (float*)d_out;

    float *qp, *xrp, *kvpp, *kp, *vp, *aop;
    cudaGetSymbolAddress((void**)&qp,   g_q);
    cudaGetSymbolAddress((void**)&xrp,  g_xr);
    cudaGetSymbolAddress((void**)&kvpp, g_kvp);
    cudaGetSymbolAddress((void**)&kp,   g_k);
    cudaGetSymbolAddress((void**)&vp,   g_v);
    cudaGetSymbolAddress((void**)&aop,  g_ao);

    // split smem + raw staging buffers
    const int g1_smem   = ((128*36*2 + 32*132*2) + (128*32 + 32*128)) * (int)sizeof(float); // ~101 KB
    const int kv_smem   = ((64*36*2 + 32*68*2)   + (64*32 + 32*64))   * (int)sizeof(float); // ~51 KB
    const int attn_smem = (2*2304 + 2*2176 + 2*2304 + 2*4352 + 256 + 64 + 2*2048) * (int)sizeof(float); // ~104.3 KB

    cudaFuncSetAttribute(gemm1x1_kernel, cudaFuncAttributeMaxDynamicSharedMemorySize, g1_smem);
    cudaFuncSetAttribute(kv_gemm_kernel, cudaFuncAttributeMaxDynamicSharedMemorySize, kv_smem);
    cudaFuncSetAttribute(attn_kernel,    cudaFuncAttributeMaxDynamicSharedMemorySize, attn_smem);

    // K1: q = wq @ x
    gemm1x1_kernel<<<dim3(HW / 128, DIM / 128, BATCH), 256, g1_smem>>>(wq, x, qp);
    // K2a: im2col repack
    repack_kernel<<<dim3(DIM, BATCH), 256>>>(x, xrp);
    // K2b: fused k & v GEMM, split-K=4 -> partials, then deterministic reduce
    kv_gemm_kernel<<<dim3(RHW / 64, 8, BATCH * 4), 256, kv_smem>>>(wk, wv, xrp, kvpp);
    kv_reduce_kernel<<<(8 * 512 * RHW / 4) / 256, 256>>>(kvpp, kp, vp);
    // K3: fused attention (j-tiled, cp.async staged)
    attn_kernel<<<dim3(HW / 64, HEADS, BATCH), 256, attn_smem>>>(qp, kp, vp, aop);
    // K4: out = wout @ attn_out
    gemm1x1_kernel<<<dim3(HW / 128, DIM / 128, BATCH), 256, g1_smem>>>(wout, aop, out);
}

// round 9
// speedup vs baseline: 2.6053x; 1.8062x over previous
#include <cuda_runtime.h>
#include <math.h>
#include <stdint.h>

#define BATCH 8
#define DIM 256
#define HEADS 8
#define HEAD_DIM 32
#define HW 4096
#define RHW 256
#define SCALE 0.17677669529663687f

// -------- scratch (static device globals; no cudaMalloc allowed) --------
__device__ float g_q  [BATCH * DIM * HW];      // 32 MB
__device__ float g_xr [BATCH * 4096 * RHW];    // 32 MB  (im2col-repacked x)
__device__ float g_kvp[4 * BATCH * 512 * RHW]; // 16 MB  (kv split-K partials)
__device__ float g_k  [BATCH * DIM * RHW];     // 2 MB
__device__ float g_v  [BATCH * DIM * RHW];     // 2 MB
__device__ float g_ao [BATCH * DIM * HW];      // 32 MB

// ======================= bf16 split/pack + MMA helpers =======================
// pack: low 16 bits = bf16(v0), high 16 bits = bf16(v1)
__device__ __forceinline__ uint32_t pack_bf16(float v0, float v1) {
    uint32_t r;
    asm("cvt.rn.bf16x2.f32 %0, %1, %2;" : "=r"(r) : "f"(v1), "f"(v0));
    return r;
}
// split pair (v0,v1) into hi word + lo word (lo = residual after bf16 hi)
__device__ __forceinline__ void split_pair(float v0, float v1, uint32_t& h, uint32_t& l) {
    h = pack_bf16(v0, v1);
    float h0 = __uint_as_float(h << 16);
    float h1 = __uint_as_float(h & 0xFFFF0000u);
    l = pack_bf16(v0 - h0, v1 - h1);
}
__device__ __forceinline__ void mma_bf16(float c[4], const uint32_t a[4], const uint32_t b[2]) {
    asm volatile(
        "mma.sync.aligned.m16n8k16.row.col.f32.bf16.bf16.f32 "
        "{%0,%1,%2,%3},{%4,%5,%6,%7},{%8,%9},{%0,%1,%2,%3};"
        : "+f"(c[0]), "+f"(c[1]), "+f"(c[2]), "+f"(c[3])
        : "r"(a[0]), "r"(a[1]), "r"(a[2]), "r"(a[3]), "r"(b[0]), "r"(b[1]));
}
__device__ __forceinline__ void mma3(float c[4], const uint32_t ah[4], const uint32_t al[4],
                                     const uint32_t bh[2], const uint32_t bl[2]) {
    mma_bf16(c, ah, bh);
    mma_bf16(c, al, bh);
    mma_bf16(c, ah, bl);
}

// ======================= cp.async helpers =======================
__device__ __forceinline__ void cp16(float* smem_dst, const float* gsrc) {
    uint32_t s;
    asm("{ .reg .u64 t; cvta.to.shared.u64 t, %1; cvt.u32.u64 %0, t; }"
        : "=r"(s) : "l"(smem_dst));
    asm volatile("cp.async.ca.shared.global [%0], [%1], 16;" :: "r"(s), "l"(gsrc));
}
__device__ __forceinline__ void cp_commit() { asm volatile("cp.async.commit_group;"); }
__device__ __forceinline__ void cp_wait0()  { asm volatile("cp.async.wait_group 0;"); }

// ======================= pipelined 3xBF16 GEMM body =======================
// C[(m0+r)*ldc + n0+c] = sum_{k<ksteps} A[(m0+r)*lda + k] * B[k*ldb + n0+c]
// 256 threads, warps 2(m) x 4(n). cp.async stages raw fp32 tiles for k+1 during
// the MMAs of k; packing to bf16 hi/lo (pairs along K) reads staged smem.
template<int BM, int BN>
__device__ __forceinline__ void gemm_body(
    const float* __restrict__ A, int lda, const float* __restrict__ B, int ldb,
    float* __restrict__ C, int ldc, int ksteps, int m0, int n0, float* smem)
{
    constexpr int BK = 32;
    constexpr int LDA2 = 20;          // words per A row (16 used, conflict-free)
    constexpr int LDB2 = BN + 8;      // words per B k2-row
    constexpr int WM = BM / 2, WN = BN / 4;
    constexpr int MT = WM / 16, NT = WN / 8;

    uint32_t* Aph = (uint32_t*)smem;
    uint32_t* Apl = Aph + BM * LDA2;
    uint32_t* Bph = Apl + BM * LDA2;
    uint32_t* Bpl = Bph + (BK / 2) * LDB2;
    float*    Araw = (float*)(Bpl + (BK / 2) * LDB2);   // [BM][BK]
    float*    Braw = Araw + BM * BK;                     // [BK][BN]

    const int tid = threadIdx.x, warp = tid >> 5, lane = tid & 31;
    const int wm = warp >> 2, wn = warp & 3;
    const int lr = lane >> 2, lc = lane & 3;

    float acc[MT][NT][4];
    #pragma unroll
    for (int i = 0; i < MT; i++)
        #pragma unroll
        for (int j = 0; j < NT; j++)
            #pragma unroll
            for (int q = 0; q < 4; q++) acc[i][j][q] = 0.f;

    auto stage = [&](int k0) {
        #pragma unroll
        for (int i = tid; i < BM * (BK / 4); i += 256) {
            int r = i >> 3, c4 = (i & 7) * 4;
            cp16(&Araw[r * BK + c4], &A[(size_t)(m0 + r) * lda + k0 + c4]);
        }
        #pragma unroll
        for (int i = tid; i < BK * (BN / 4); i += 256) {
            int r = i / (BN / 4), c4 = (i % (BN / 4)) * 4;
            cp16(&Braw[r * BN + c4], &B[(size_t)(k0 + r) * ldb + n0 + c4]);
        }
        cp_commit();
    };

    stage(0);

    for (int k0 = 0; k0 < ksteps; k0 += BK) {
        cp_wait0();
        __syncthreads();   // MMA reads of packed tiles done; raw tiles landed

        // pack A: pairs along k
        #pragma unroll
        for (int i = tid; i < BM * (BK / 4); i += 256) {
            int r = i >> 3, c4 = (i & 7) * 4;
            float4 a = *(float4*)&Araw[r * BK + c4];
            uint32_t h0, l0, h1, l1;
            split_pair(a.x, a.y, h0, l0);
            split_pair(a.z, a.w, h1, l1);
            Aph[r * LDA2 + (c4 >> 1)]     = h0;  Apl[r * LDA2 + (c4 >> 1)]     = l0;
            Aph[r * LDA2 + (c4 >> 1) + 1] = h1;  Apl[r * LDA2 + (c4 >> 1) + 1] = l1;
        }
        // pack B: pairs across adjacent k rows, same n
        #pragma unroll
        for (int i = tid; i < (BK / 2) * (BN / 4); i += 256) {
            int r2 = i / (BN / 4), c4 = (i % (BN / 4)) * 4;
            float4 u = *(float4*)&Braw[(2 * r2) * BN + c4];
            float4 w = *(float4*)&Braw[(2 * r2 + 1) * BN + c4];
            uint32_t h, l;
            split_pair(u.x, w.x, h, l); Bph[r2 * LDB2 + c4]     = h; Bpl[r2 * LDB2 + c4]     = l;
            split_pair(u.y, w.y, h, l); Bph[r2 * LDB2 + c4 + 1] = h; Bpl[r2 * LDB2 + c4 + 1] = l;
            split_pair(u.z, w.z, h, l); Bph[r2 * LDB2 + c4 + 2] = h; Bpl[r2 * LDB2 + c4 + 2] = l;
            split_pair(u.w, w.w, h, l); Bph[r2 * LDB2 + c4 + 3] = h; Bpl[r2 * LDB2 + c4 + 3] = l;
        }
        __syncthreads();   // packed tiles ready; raw consumed -> safe to re-stage

        if (k0 + BK < ksteps) stage(k0 + BK);   // overlaps with MMAs below

        #pragma unroll
        for (int kk2 = 0; kk2 < BK / 2; kk2 += 8) {   // two k16 steps
            uint32_t ah[MT][4], al[MT][4];
            #pragma unroll
            for (int mt = 0; mt < MT; mt++) {
                int r = wm * WM + mt * 16 + lr;
                ah[mt][0] = Aph[r * LDA2 + kk2 + lc];
                ah[mt][1] = Aph[(r + 8) * LDA2 + kk2 + lc];
                ah[mt][2] = Aph[r * LDA2 + kk2 + lc + 4];
                ah[mt][3] = Aph[(r + 8) * LDA2 + kk2 + lc + 4];
                al[mt][0] = Apl[r * LDA2 + kk2 + lc];
                al[mt][1] = Apl[(r + 8) * LDA2 + kk2 + lc];
                al[mt][2] = Apl[r * LDA2 + kk2 + lc + 4];
                al[mt][3] = Apl[(r + 8) * LDA2 + kk2 + lc + 4];
            }
            uint32_t bh[NT][2], bl[NT][2];
            #pragma unroll
            for (int nt = 0; nt < NT; nt++) {
                int cc = wn * WN + nt * 8 + lr;
                bh[nt][0] = Bph[(kk2 + lc) * LDB2 + cc];
                bh[nt][1] = Bph[(kk2 + lc + 4) * LDB2 + cc];
                bl[nt][0] = Bpl[(kk2 + lc) * LDB2 + cc];
                bl[nt][1] = Bpl[(kk2 + lc + 4) * LDB2 + cc];
            }
            #pragma unroll
            for (int mt = 0; mt < MT; mt++)
                #pragma unroll
                for (int nt = 0; nt < NT; nt++)
                    mma3(acc[mt][nt], ah[mt], al[mt], bh[nt], bl[nt]);
        }
    }

    #pragma unroll
    for (int mt = 0; mt < MT; mt++) {
        int r = m0 + wm * WM + mt * 16 + lr;
        #pragma unroll
        for (int nt = 0; nt < NT; nt++) {
            int c = n0 + wn * WN + nt * 8 + lc * 2;
            *(float2*)&C[(size_t)r * ldc + c]       = make_float2(acc[mt][nt][0], acc[mt][nt][1]);
            *(float2*)&C[(size_t)(r + 8) * ldc + c] = make_float2(acc[mt][nt][2], acc[mt][nt][3]);
        }
    }
}

// K1/K4: 1x1 conv GEMM.  M=256, N=4096, K=256 per batch.
__global__ __launch_bounds__(256, 2)
void gemm1x1_kernel(const float* __restrict__ A, const float* __restrict__ Bg,
                    float* __restrict__ Cg) {
    extern __shared__ float smem[];
    const float* B = Bg + (size_t)blockIdx.z * DIM * HW;
    float*       C = Cg + (size_t)blockIdx.z * DIM * HW;
    gemm_body<128, 128>(A, DIM, B, HW, C, HW, DIM, blockIdx.y * 128, blockIdx.x * 128, smem);
}

// K2b: fused k&v GEMM, split-K=4. Stacked M=512 (mblk 0-3: k, 4-7: v). N=256.
__global__ __launch_bounds__(256, 3)
void kv_gemm_kernel(const float* __restrict__ Wk, const float* __restrict__ Wv,
                    const float* __restrict__ XR, float* __restrict__ Part) {
    extern __shared__ float smem[];
    const int mblk = blockIdx.y;
    const int b  = blockIdx.z & 7;
    const int ks = blockIdx.z >> 3;
    const int koff = ks * 1024;
    const float* A = (mblk < 4) ? (Wk + koff)
                                : (Wv + koff - (size_t)256 * 4096);   // un-bias stacked rows
    const float* B = XR + (size_t)b * 4096 * RHW + (size_t)koff * RHW;
    float*       C = Part + ((size_t)(ks * BATCH + b) * 512) * RHW;
    const int m0 = mblk * 64;                                          // stacked row 0..511
    gemm_body<64, 64>(A, 4096, B, RHW, C, RHW, 1024, m0, blockIdx.x * 64, smem);
}

// reduce the 4 split-K partials into g_k / g_v.
__global__ __launch_bounds__(256)
void kv_reduce_kernel(const float* __restrict__ P, float* __restrict__ Kout,
                      float* __restrict__ Vout) {
    const int idx = blockIdx.x * 256 + threadIdx.x;     // float4 index
    const float4* p = (const float4*)P;
    const int CH = 8 * 512 * RHW / 4;                    // float4 per split chunk
    float4 a = p[idx], b4 = p[idx + CH], c4 = p[idx + 2 * CH], d4 = p[idx + 3 * CH];
    float4 s = make_float4(a.x + b4.x + c4.x + d4.x, a.y + b4.y + c4.y + d4.y,
                           a.z + b4.z + c4.z + d4.z, a.w + b4.w + c4.w + d4.w);
    const int f = idx * 4;
    const int n = f & 255, m = (f >> 8) & 511, b = f >> 17;
    float* dst = (m < 256) ? (Kout + ((size_t)b * DIM + m) * RHW + n)
                           : (Vout + ((size_t)b * DIM + (m - 256)) * RHW + n);
    *(float4*)dst = s;
}

// ======================= im2col repack =======================
__global__ __launch_bounds__(256)
void repack_kernel(const float* __restrict__ X, float* __restrict__ XR) {
    __shared__ float pl[4096];
    const int ci = blockIdx.x, b = blockIdx.y, tid = threadIdx.x;
    const float* src = X + ((size_t)b * DIM + ci) * HW;
    #pragma unroll
    for (int i = tid; i < 1024; i += 256)
        ((float4*)pl)[i] = ((const float4*)src)[i];
    __syncthreads();
    const int oh = tid >> 4, ow = tid & 15;
    float* dst = XR + ((size_t)b * 4096 + ci * 16) * RHW;
    #pragma unroll
    for (int kh = 0; kh < 4; kh++)
        #pragma unroll
        for (int kw = 0; kw < 4; kw++)
            dst[(kh * 4 + kw) * RHW + tid] = pl[(oh * 4 + kh) * 64 + ow * 4 + kw];
}

// ======================= fused attention: j-tiled, bf16 MMA, cp.async staged =======================
// i-tile 64, j-tile 64 (4 tiles). smem ~71 KB -> up to 3 CTAs/SM.
__global__ __launch_bounds__(256, 3)
void attn_kernel(const float* __restrict__ Q, const float* __restrict__ Kg,
                 const float* __restrict__ Vg, float* __restrict__ O) {
    extern __shared__ float sm[];
    uint32_t* su  = (uint32_t*)sm;
    uint32_t* Qph = su;               // [64][20]  (16 words used: d pairs)
    uint32_t* Qpl = Qph + 1280;
    uint32_t* Kph = Qpl + 1280;       // [16][72]  (d2 rows, j cols)
    uint32_t* Kpl = Kph + 1152;
    uint32_t* Vph = Kpl + 1152;       // [32][36]  (d rows, j2 words)
    uint32_t* Vpl = Vph + 1152;
    uint32_t* Pph = Vpl + 1152;       // [64][36]  (i rows, j2 words)
    uint32_t* Ppl = Pph + 2304;
    float* lacc  = (float*)(Ppl + 2304);   // [4][64]
    float* li    = lacc + 256;             // [64]
    float* qraw  = li + 64;                // [32][65]
    float* kraw  = qraw + 2080;            // [32][64] cp.async target
    float* vraw  = kraw + 2048;            // [32][64]
    float* po    = (float*)Pph;            // [64][36] final staging (aliases P)

    const int tid = threadIdx.x, warp = tid >> 5, lane = tid & 31;
    const int lr = lane >> 2, lc = lane & 3;
    const int wm = warp >> 2, wn = warp & 3;      // S-phase mapping
    const int iw = (warp & 3) * 16;                // PV-phase i-strip
    const int db = (warp >> 2) * 16;               // PV-phase d-strip
    const int b = blockIdx.z, h = blockIdx.y, i0 = blockIdx.x * 64;

    const float* Qb = Q  + ((size_t)b * DIM + h * HEAD_DIM) * HW + i0;
    const float* Kb = Kg + ((size_t)b * DIM + h * HEAD_DIM) * RHW;
    const float* Vb = Vg + ((size_t)b * DIM + h * HEAD_DIM) * RHW;

    auto stageKV = [&](int j0) {
        #pragma unroll
        for (int idx = tid; idx < 512; idx += 256) {
            int d = idx >> 4, j4 = (idx & 15) * 4;
            cp16(&kraw[d * 64 + j4], &Kb[(size_t)d * RHW + j0 + j4]);
            cp16(&vraw[d * 64 + j4], &Vb[(size_t)d * RHW + j0 + j4]);
        }
        cp_commit();
    };

    stageKV(0);

    // q raw load (coalesced along i), scale
    for (int idx = tid; idx < 2048; idx += 256) {
        int d = idx >> 6, i = idx & 63;
        qraw[d * 65 + i] = Qb[(size_t)d * HW + i] * SCALE;
    }
    lacc[tid] = 0.f;
    __syncthreads();

    // pack Q: pairs along d
    for (int idx = tid; idx < 1024; idx += 256) {
        int i = idx >> 4, d2 = idx & 15;
        uint32_t hw_, lw_;
        split_pair(qraw[(2 * d2) * 65 + i], qraw[(2 * d2 + 1) * 65 + i], hw_, lw_);
        Qph[i * 20 + d2] = hw_;
        Qpl[i * 20 + d2] = lw_;
    }

    float oacc[2][4];
    #pragma unroll
    for (int nt = 0; nt < 2; nt++)
        #pragma unroll
        for (int q = 0; q < 4; q++) oacc[nt][q] = 0.f;

    for (int jt = 0; jt < 4; jt++) {
        cp_wait0();
        __syncthreads();   // raw tiles landed; prior PV reads of Vp done; Qp visible (jt=0)

        // pack K: pairs along d (rows), per j
        for (int idx = tid; idx < 1024; idx += 256) {
            int d2 = idx >> 6, j = idx & 63;
            uint32_t hw_, lw_;
            split_pair(kraw[(2 * d2) * 64 + j], kraw[(2 * d2 + 1) * 64 + j], hw_, lw_);
            Kph[d2 * 72 + j] = hw_;
            Kpl[d2 * 72 + j] = lw_;
        }
        // pack V: pairs along j, per d
        for (int idx = tid; idx < 1024; idx += 256) {
            int d = idx >> 5, j2 = idx & 31;
            float2 v = *(float2*)&vraw[d * 64 + 2 * j2];
            uint32_t hw_, lw_;
            split_pair(v.x, v.y, hw_, lw_);
            Vph[d * 36 + j2] = hw_;
            Vpl[d * 36 + j2] = lw_;
        }
        __syncthreads();   // packed; raw consumed -> safe to re-stage

        if (jt < 3) stageKV((jt + 1) * 64);   // overlaps with S/exp/PV

        // ---- S tile = Q Kᵀ : M=64(i), N=64(j), K=32(d). warp tile 32x16 ----
        float sacc[2][2][4];
        #pragma unroll
        for (int mt = 0; mt < 2; mt++)
            #pragma unroll
            for (int nt = 0; nt < 2; nt++)
                #pragma unroll
                for (int q = 0; q < 4; q++) sacc[mt][nt][q] = 0.f;

        #pragma unroll
        for (int kk2 = 0; kk2 < 16; kk2 += 8) {
            uint32_t ah[2][4], al[2][4];
            #pragma unroll
            for (int mt = 0; mt < 2; mt++) {
                int r = wm * 32 + mt * 16 + lr;
                ah[mt][0] = Qph[r * 20 + kk2 + lc];
                ah[mt][1] = Qph[(r + 8) * 20 + kk2 + lc];
                ah[mt][2] = Qph[r * 20 + kk2 + lc + 4];
                ah[mt][3] = Qph[(r + 8) * 20 + kk2 + lc + 4];
                al[mt][0] = Qpl[r * 20 + kk2 + lc];
                al[mt][1] = Qpl[(r + 8) * 20 + kk2 + lc];
                al[mt][2] = Qpl[r * 20 + kk2 + lc + 4];
                al[mt][3] = Qpl[(r + 8) * 20 + kk2 + lc + 4];
            }
            uint32_t bh[2][2], bl[2][2];
            #pragma unroll
            for (int nt = 0; nt < 2; nt++) {
                int jj = wn * 16 + nt * 8 + lr;
                bh[nt][0] = Kph[(kk2 + lc) * 72 + jj];
                bh[nt][1] = Kph[(kk2 + lc + 4) * 72 + jj];
                bl[nt][0] = Kpl[(kk2 + lc) * 72 + jj];
                bl[nt][1] = Kpl[(kk2 + lc + 4) * 72 + jj];
            }
            #pragma unroll
            for (int mt = 0; mt < 2; mt++)
                #pragma unroll
                for (int nt = 0; nt < 2; nt++)
                    mma3(sacc[mt][nt], ah[mt], al[mt], bh[nt], bl[nt]);
        }

        // ---- exp -> P (packed pairs along j), accumulate row sums ----
        #pragma unroll
        for (int mt = 0; mt < 2; mt++) {
            int r = wm * 32 + mt * 16 + lr;
            float rs0 = 0.f, rs1 = 0.f;
            #pragma unroll
            for (int nt = 0; nt < 2; nt++) {
                int j2 = wn * 8 + nt * 4 + lc;   // word index (covers cols 2*j2, 2*j2+1)
                float e0 = __expf(sacc[mt][nt][0]);
                float e1 = __expf(sacc[mt][nt][1]);
                float e2 = __expf(sacc[mt][nt][2]);
                float e3 = __expf(sacc[mt][nt][3]);
                uint32_t hw_, lw_;
                split_pair(e0, e1, hw_, lw_);
                Pph[r * 36 + j2] = hw_;  Ppl[r * 36 + j2] = lw_;
                split_pair(e2, e3, hw_, lw_);
                Pph[(r + 8) * 36 + j2] = hw_;  Ppl[(r + 8) * 36 + j2] = lw_;
                rs0 += e0 + e1;
                rs1 += e2 + e3;
            }
            rs0 += __shfl_xor_sync(0xFFFFFFFFu, rs0, 1);
            rs0 += __shfl_xor_sync(0xFFFFFFFFu, rs0, 2);
            rs1 += __shfl_xor_sync(0xFFFFFFFFu, rs1, 1);
            rs1 += __shfl_xor_sync(0xFFFFFFFFu, rs1, 2);
            if (lc == 0) {
                lacc[wn * 64 + r]     += rs0;
                lacc[wn * 64 + r + 8] += rs1;
            }
        }
        __syncthreads();

        // ---- PV accumulate: O[iw..+16][db..+16] += P_tile * V_tile (K=64 j) ----
        #pragma unroll
        for (int kk2 = 0; kk2 < 32; kk2 += 8) {
            uint32_t ah[4], al[4];
            int r = iw + lr;
            ah[0] = Pph[r * 36 + kk2 + lc];
            ah[1] = Pph[(r + 8) * 36 + kk2 + lc];
            ah[2] = Pph[r * 36 + kk2 + lc + 4];
            ah[3] = Pph[(r + 8) * 36 + kk2 + lc + 4];
            al[0] = Ppl[r * 36 + kk2 + lc];
            al[1] = Ppl[(r + 8) * 36 + kk2 + lc];
            al[2] = Ppl[r * 36 + kk2 + lc + 4];
            al[3] = Ppl[(r + 8) * 36 + kk2 + lc + 4];
            #pragma unroll
            for (int nt = 0; nt < 2; nt++) {
                int d = db + nt * 8 + lr;
                uint32_t bh[2], bl[2];
                bh[0] = Vph[d * 36 + kk2 + lc];
                bh[1] = Vph[d * 36 + kk2 + lc + 4];
                bl[0] = Vpl[d * 36 + kk2 + lc];
                bl[1] = Vpl[d * 36 + kk2 + lc + 4];
                mma3(oacc[nt], ah, al, bh, bl);
            }
        }
    }

    __syncthreads();
    if (tid < 64)
        li[tid] = 1.f / (lacc[tid] + lacc[64 + tid] + lacc[128 + tid] + lacc[192 + tid]);
    __syncthreads();

    // normalize + stage to po (aliases dead P tile)
    #pragma unroll
    for (int nt = 0; nt < 2; nt++) {
        int r = iw + lr, c = db + nt * 8 + lc * 2;
        float inv0 = li[r], inv1 = li[r + 8];
        po[r * 36 + c]           = oacc[nt][0] * inv0;
        po[r * 36 + c + 1]       = oacc[nt][1] * inv0;
        po[(r + 8) * 36 + c]     = oacc[nt][2] * inv1;
        po[(r + 8) * 36 + c + 1] = oacc[nt][3] * inv1;
    }
    __syncthreads();

    // coalesced transposed store: O[d][i]
    float* Ob = O + ((size_t)b * DIM + h * HEAD_DIM) * HW + i0;
    for (int idx = tid; idx < 64 * 32; idx += 256) {
        int d = idx >> 6, i = idx & 63;
        Ob[(size_t)d * HW + i] = po[i * 36 + d];
    }
}

// ============================================================================
extern "C" void kernel_launch(void* const* d_in, const int* in_sizes, int n_in,
                              void* d_out, int out_size) {
    const float* x    = (const float*)d_in[0];
    const float* wq   = (const float*)d_in[1];
    const float* wk   = (const float*)d_in[2];
    const float* wv   = (const float*)d_in[3];
    const float* wout = (const float*)d_in[4];
    float* out = (float*)d_out;

    float *qp, *xrp, *kvpp, *kp, *vp, *aop;
    cudaGetSymbolAddress((void**)&qp,   g_q);
    cudaGetSymbolAddress((void**)&xrp,  g_xr);
    cudaGetSymbolAddress((void**)&kvpp, g_kvp);
    cudaGetSymbolAddress((void**)&kp,   g_k);
    cudaGetSymbolAddress((void**)&vp,   g_v);
    cudaGetSymbolAddress((void**)&aop,  g_ao);

    const int g1_smem   = (2 * 128 * 20 + 2 * 16 * 136 + 128 * 32 + 32 * 128) * 4; // 70656 B
    const int kv_smem   = (2 * 64 * 20 + 2 * 16 * 72 + 64 * 32 + 32 * 64) * 4;      // 35840 B
    const int attn_smem = (2 * 1280 + 2 * 1152 + 2 * 1152 + 2 * 2304 + 256 + 64
                           + 2080 + 2048 + 2048) * 4;                                // 73088 B

    cudaFuncSetAttribute(gemm1x1_kernel, cudaFuncAttributeMaxDynamicSharedMemorySize, g1_smem);
    cudaFuncSetAttribute(kv_gemm_kernel, cudaFuncAttributeMaxDynamicSharedMemorySize, kv_smem);
    cudaFuncSetAttribute(attn_kernel,    cudaFuncAttributeMaxDynamicSharedMemorySize, attn_smem);

    // K1: q = wq @ x
    gemm1x1_kernel<<<dim3(HW / 128, DIM / 128, BATCH), 256, g1_smem>>>(wq, x, qp);
    // K2a: im2col repack
    repack_kernel<<<dim3(DIM, BATCH), 256>>>(x, xrp);
    // K2b: fused k & v GEMM, split-K=4 -> partials, then deterministic reduce
    kv_gemm_kernel<<<dim3(RHW / 64, 8, BATCH * 4), 256, kv_smem>>>(wk, wv, xrp, kvpp);
    kv_reduce_kernel<<<(8 * 512 * RHW / 4) / 256, 256>>>(kvpp, kp, vp);
    // K3: fused attention (j-tiled, bf16)
    attn_kernel<<<dim3(HW / 64, HEADS, BATCH), 256, attn_smem>>>(qp, kp, vp, aop);
    // K4: out = wout @ attn_out
    gemm1x1_kernel<<<dim3(HW / 128, DIM / 128, BATCH), 256, g1_smem>>>(wout, aop, out);
}

// round 10
// speedup vs baseline: 2.6884x; 1.0319x over previous
#include <cuda_runtime.h>
#include <math.h>
#include <stdint.h>

#define BATCH 8
#define DIM 256
#define HEADS 8
#define HEAD_DIM 32
#define HW 4096
#define RHW 256
#define SCALE 0.17677669529663687f

// -------- scratch (static device globals; no cudaMalloc allowed) --------
__device__ float    g_q  [BATCH * DIM * HW];       // 32 MB fp32 (attn packs it itself)
__device__ float    g_kvp[4 * BATCH * 512 * RHW];  // 16 MB kv split-K partials
__device__ float    g_k  [BATCH * DIM * RHW];      // 2 MB
__device__ float    g_v  [BATCH * DIM * RHW];      // 2 MB
// packed bf16 hi/lo planes (fragment-word layout)
__device__ uint32_t g_wqh[256 * 128],   g_wql[256 * 128];
__device__ uint32_t g_wkh[256 * 2048],  g_wkl[256 * 2048];
__device__ uint32_t g_wvh[256 * 2048],  g_wvl[256 * 2048];
__device__ uint32_t g_woh[256 * 128],   g_wol[256 * 128];
__device__ uint32_t g_xph[BATCH * 128 * HW],  g_xpl[BATCH * 128 * HW];   // x pairs along c
__device__ uint32_t g_xrh[BATCH * 2048 * RHW], g_xrl[BATCH * 2048 * RHW]; // im2col pairs along k
__device__ uint32_t g_aoh[BATCH * 128 * HW],  g_aol[BATCH * 128 * HW];   // attn out pairs along d

// ======================= bf16 split/pack + MMA helpers =======================
__device__ __forceinline__ uint32_t pack_bf16(float v0, float v1) {
    uint32_t r;
    asm("cvt.rn.bf16x2.f32 %0, %1, %2;" : "=r"(r) : "f"(v1), "f"(v0));
    return r;
}
__device__ __forceinline__ void split_pair(float v0, float v1, uint32_t& h, uint32_t& l) {
    h = pack_bf16(v0, v1);
    float h0 = __uint_as_float(h << 16);
    float h1 = __uint_as_float(h & 0xFFFF0000u);
    l = pack_bf16(v0 - h0, v1 - h1);
}
__device__ __forceinline__ void mma_bf16(float c[4], const uint32_t a[4], const uint32_t b[2]) {
    asm volatile(
        "mma.sync.aligned.m16n8k16.row.col.f32.bf16.bf16.f32 "
        "{%0,%1,%2,%3},{%4,%5,%6,%7},{%8,%9},{%0,%1,%2,%3};"
        : "+f"(c[0]), "+f"(c[1]), "+f"(c[2]), "+f"(c[3])
        : "r"(a[0]), "r"(a[1]), "r"(a[2]), "r"(a[3]), "r"(b[0]), "r"(b[1]));
}
__device__ __forceinline__ void mma3(float c[4], const uint32_t ah[4], const uint32_t al[4],
                                     const uint32_t bh[2], const uint32_t bl[2]) {
    mma_bf16(c, ah, bh);
    mma_bf16(c, al, bh);
    mma_bf16(c, ah, bl);
}

// ======================= cp.async helpers =======================
__device__ __forceinline__ void cp16(uint32_t* smem_dst, const uint32_t* gsrc) {
    uint32_t s;
    asm("{ .reg .u64 t; cvta.to.shared.u64 t, %1; cvt.u32.u64 %0, t; }"
        : "=r"(s) : "l"(smem_dst));
    asm volatile("cp.async.ca.shared.global [%0], [%1], 16;" :: "r"(s), "l"(gsrc));
}
__device__ __forceinline__ void cp16f(float* smem_dst, const float* gsrc) {
    uint32_t s;
    asm("{ .reg .u64 t; cvta.to.shared.u64 t, %1; cvt.u32.u64 %0, t; }"
        : "=r"(s) : "l"(smem_dst));
    asm volatile("cp.async.ca.shared.global [%0], [%1], 16;" :: "r"(s), "l"(gsrc));
}
__device__ __forceinline__ void cp_commit() { asm volatile("cp.async.commit_group;"); }
template<int N> __device__ __forceinline__ void cp_wait_n() {
    asm volatile("cp.async.wait_group %0;" :: "n"(N));
}

// ======================= packed-operand double-buffered GEMM body =======================
// C[(m0+r)*ldc + n0+c] = sum_k A[m0+r][k] * B[k][n0+c], operands pre-split into
// bf16 hi/lo planes. A plane word (r,k2) = (A[r][2k2], A[r][2k2+1]), lda2 words/row.
// B plane word (k2,n) = (B[2k2][n], B[2k2+1][n]), ldb2 words/k2-row.
// 256 threads, warps 2(m) x 4(n). 2-stage cp.async pipeline, zero in-loop conversion.
template<int BM, int BN>
__device__ __forceinline__ void gemm_packed_body(
    const uint32_t* __restrict__ Ah, const uint32_t* __restrict__ Al, int lda2,
    const uint32_t* __restrict__ Bh, const uint32_t* __restrict__ Bl, int ldb2,
    float* __restrict__ C, int ldc, int k2steps, int m0, int n0, uint32_t* smem)
{
    constexpr int BK2 = 16;              // 32 k-elements per tile
    constexpr int LDA2 = 20;             // padded words per A tile row
    constexpr int LDB2 = BN + 8;         // padded words per B tile k2-row
    constexpr int ASZ = BM * LDA2, BSZ = BK2 * LDB2;
    constexpr int STG = 2 * ASZ + 2 * BSZ;
    constexpr int WM = BM / 2, WN = BN / 4;
    constexpr int MT = WM / 16, NT = WN / 8;

    const int tid = threadIdx.x, warp = tid >> 5, lane = tid & 31;
    const int wm = warp >> 2, wn = warp & 3;
    const int lr = lane >> 2, lc = lane & 3;

    float acc[MT][NT][4];
    #pragma unroll
    for (int i = 0; i < MT; i++)
        #pragma unroll
        for (int j = 0; j < NT; j++)
            #pragma unroll
            for (int q = 0; q < 4; q++) acc[i][j][q] = 0.f;

    auto stage = [&](int k2_0, uint32_t* buf) {
        uint32_t* Aht = buf;
        uint32_t* Alt = buf + ASZ;
        uint32_t* Bht = buf + 2 * ASZ;
        uint32_t* Blt = buf + 2 * ASZ + BSZ;
        #pragma unroll
        for (int i = tid; i < BM * 4; i += 256) {          // BK2/4 = 4 chunks per row
            int r = i >> 2, c4 = (i & 3) * 4;
            cp16(&Aht[r * LDA2 + c4], &Ah[(size_t)(m0 + r) * lda2 + k2_0 + c4]);
            cp16(&Alt[r * LDA2 + c4], &Al[(size_t)(m0 + r) * lda2 + k2_0 + c4]);
        }
        #pragma unroll
        for (int i = tid; i < BK2 * (BN / 4); i += 256) {
            int r = i / (BN / 4), c4 = (i % (BN / 4)) * 4;
            cp16(&Bht[r * LDB2 + c4], &Bh[(size_t)(k2_0 + r) * ldb2 + n0 + c4]);
            cp16(&Blt[r * LDB2 + c4], &Bl[(size_t)(k2_0 + r) * ldb2 + n0 + c4]);
        }
        cp_commit();
    };

    const int nit = k2steps / BK2;
    stage(0, smem);

    for (int it = 0; it < nit; it++) {
        uint32_t* buf = smem + (it & 1) * STG;
        __syncthreads();                               // MMA reads of other buffer done
        if (it + 1 < nit) {
            stage((it + 1) * BK2, smem + ((it + 1) & 1) * STG);
            cp_wait_n<1>();                            // stage 'it' landed
        } else {
            cp_wait_n<0>();
        }
        __syncthreads();                               // tile visible to all warps

        uint32_t* Aht = buf;
        uint32_t* Alt = buf + ASZ;
        uint32_t* Bht = buf + 2 * ASZ;
        uint32_t* Blt = buf + 2 * ASZ + BSZ;

        #pragma unroll
        for (int kk2 = 0; kk2 < BK2; kk2 += 8) {       // two k16 steps per tile
            uint32_t ah[MT][4], al[MT][4];
            #pragma unroll
            for (int mt = 0; mt < MT; mt++) {
                int r = wm * WM + mt * 16 + lr;
                ah[mt][0] = Aht[r * LDA2 + kk2 + lc];
                ah[mt][1] = Aht[(r + 8) * LDA2 + kk2 + lc];
                ah[mt][2] = Aht[r * LDA2 + kk2 + lc + 4];
                ah[mt][3] = Aht[(r + 8) * LDA2 + kk2 + lc + 4];
                al[mt][0] = Alt[r * LDA2 + kk2 + lc];
                al[mt][1] = Alt[(r + 8) * LDA2 + kk2 + lc];
                al[mt][2] = Alt[r * LDA2 + kk2 + lc + 4];
                al[mt][3] = Alt[(r + 8) * LDA2 + kk2 + lc + 4];
            }
            uint32_t bh[NT][2], bl[NT][2];
            #pragma unroll
            for (int nt = 0; nt < NT; nt++) {
                int cc = wn * WN + nt * 8 + lr;
                bh[nt][0] = Bht[(kk2 + lc) * LDB2 + cc];
                bh[nt][1] = Bht[(kk2 + lc + 4) * LDB2 + cc];
                bl[nt][0] = Blt[(kk2 + lc) * LDB2 + cc];
                bl[nt][1] = Blt[(kk2 + lc + 4) * LDB2 + cc];
            }
            #pragma unroll
            for (int mt = 0; mt < MT; mt++)
                #pragma unroll
                for (int nt = 0; nt < NT; nt++)
                    mma3(acc[mt][nt], ah[mt], al[mt], bh[nt], bl[nt]);
        }
    }

    #pragma unroll
    for (int mt = 0; mt < MT; mt++) {
        int r = m0 + wm * WM + mt * 16 + lr;
        #pragma unroll
        for (int nt = 0; nt < NT; nt++) {
            int c = n0 + wn * WN + nt * 8 + lc * 2;
            *(float2*)&C[(size_t)r * ldc + c]       = make_float2(acc[mt][nt][0], acc[mt][nt][1]);
            *(float2*)&C[(size_t)(r + 8) * ldc + c] = make_float2(acc[mt][nt][2], acc[mt][nt][3]);
        }
    }
}

// ======================= pack kernels =======================
// contiguous adjacent-pair pack (weights: pairs along K within a row)
__global__ __launch_bounds__(256)
void pack_pairs_kernel(const float* __restrict__ src, uint32_t* __restrict__ h,
                       uint32_t* __restrict__ l, int npairs) {
    int idx = blockIdx.x * 256 + threadIdx.x;
    if (idx >= npairs) return;
    float2 v = ((const float2*)src)[idx];
    uint32_t hw_, lw_;
    split_pair(v.x, v.y, hw_, lw_);
    h[idx] = hw_;
    l[idx] = lw_;
}

// x pack: word(b,c2,n) = (x[b][2c2][n], x[b][2c2+1][n])
__global__ __launch_bounds__(256)
void pack_x_kernel(const float* __restrict__ X, uint32_t* __restrict__ h,
                   uint32_t* __restrict__ l) {
    const int n = blockIdx.x * 256 + threadIdx.x;
    const int c2 = blockIdx.y, b = blockIdx.z;
    const float* r0 = X + ((size_t)b * DIM + 2 * c2) * HW;
    uint32_t hw_, lw_;
    split_pair(r0[n], r0[HW + n], hw_, lw_);
    const size_t o = ((size_t)b * 128 + c2) * HW + n;
    h[o] = hw_;
    l[o] = lw_;
}

// im2col repack -> packed planes: k = ci*16 + kh*4 + kw; pairs = adjacent kw
__global__ __launch_bounds__(256)
void repack_kernel(const float* __restrict__ X, uint32_t* __restrict__ h,
                   uint32_t* __restrict__ l) {
    __shared__ float pl[4096];
    const int ci = blockIdx.x, b = blockIdx.y, tid = threadIdx.x;
    const float* src = X + ((size_t)b * DIM + ci) * HW;
    #pragma unroll
    for (int i = tid; i < 1024; i += 256)
        ((float4*)pl)[i] = ((const float4*)src)[i];
    __syncthreads();
    const int oh = tid >> 4, ow = tid & 15;
    #pragma unroll
    for (int kh = 0; kh < 4; kh++)
        #pragma unroll
        for (int kw2 = 0; kw2 < 2; kw2++) {
            float v0 = pl[(oh * 4 + kh) * 64 + ow * 4 + 2 * kw2];
            float v1 = pl[(oh * 4 + kh) * 64 + ow * 4 + 2 * kw2 + 1];
            uint32_t hw_, lw_;
            split_pair(v0, v1, hw_, lw_);
            const size_t o = ((size_t)b * 2048 + ci * 8 + kh * 2 + kw2) * RHW + tid;
            h[o] = hw_;
            l[o] = lw_;
        }
}

// ======================= GEMM kernels =======================
// K1: q = wq @ x (M=256, N=4096, K=256). B planes: ldb2=HW, per-batch 128*HW.
__global__ __launch_bounds__(256, 2)
void gemm_q_kernel(const uint32_t* __restrict__ Ah, const uint32_t* __restrict__ Al,
                   const uint32_t* __restrict__ Bh, const uint32_t* __restrict__ Bl,
                   float* __restrict__ Cg) {
    extern __shared__ uint32_t smem[];
    const size_t bo = (size_t)blockIdx.z * 128 * HW;
    float* C = Cg + (size_t)blockIdx.z * DIM * HW;
    gemm_packed_body<128, 128>(Ah, Al, 128, Bh + bo, Bl + bo, HW,
                               C, HW, 128, blockIdx.y * 128, blockIdx.x * 128, smem);
}

// K4: out = wout @ ao (packed planes from attn)
__global__ __launch_bounds__(256, 2)
void gemm_o_kernel(const uint32_t* __restrict__ Ah, const uint32_t* __restrict__ Al,
                   const uint32_t* __restrict__ Bh, const uint32_t* __restrict__ Bl,
                   float* __restrict__ Cg) {
    extern __shared__ uint32_t smem[];
    const size_t bo = (size_t)blockIdx.z * 128 * HW;
    float* C = Cg + (size_t)blockIdx.z * DIM * HW;
    gemm_packed_body<128, 128>(Ah, Al, 128, Bh + bo, Bl + bo, HW,
                               C, HW, 128, blockIdx.y * 128, blockIdx.x * 128, smem);
}

// K2b: fused k&v GEMM, split-K=4, stacked M=512. k2steps=512 per chunk.
__global__ __launch_bounds__(256, 3)
void kv_gemm_kernel(float* __restrict__ Part) {
    extern __shared__ uint32_t smem[];
    const int mblk = blockIdx.y;
    const int b  = blockIdx.z & 7;
    const int ks = blockIdx.z >> 3;
    const int koff2 = ks * 512;
    const uint32_t* Ah = (mblk < 4) ? (g_wkh + koff2) : (g_wvh + koff2 - (size_t)256 * 2048);
    const uint32_t* Al = (mblk < 4) ? (g_wkl + koff2) : (g_wvl + koff2 - (size_t)256 * 2048);
    const uint32_t* Bh = g_xrh + ((size_t)b * 2048 + koff2) * RHW;
    const uint32_t* Bl = g_xrl + ((size_t)b * 2048 + koff2) * RHW;
    float* C = g_kvp + ((size_t)(ks * BATCH + b) * 512) * RHW;
    gemm_packed_body<64, 64>(Ah, Al, 2048, Bh, Bl, RHW,
                             C, RHW, 512, mblk * 64, blockIdx.x * 64, smem);
}

// reduce the 4 split-K partials into g_k / g_v.
__global__ __launch_bounds__(256)
void kv_reduce_kernel(const float* __restrict__ P, float* __restrict__ Kout,
                      float* __restrict__ Vout) {
    const int idx = blockIdx.x * 256 + threadIdx.x;
    const float4* p = (const float4*)P;
    const int CH = 8 * 512 * RHW / 4;
    float4 a = p[idx], b4 = p[idx + CH], c4 = p[idx + 2 * CH], d4 = p[idx + 3 * CH];
    float4 s = make_float4(a.x + b4.x + c4.x + d4.x, a.y + b4.y + c4.y + d4.y,
                           a.z + b4.z + c4.z + d4.z, a.w + b4.w + c4.w + d4.w);
    const int f = idx * 4;
    const int n = f & 255, m = (f >> 8) & 511, b = f >> 17;
    float* dst = (m < 256) ? (Kout + ((size_t)b * DIM + m) * RHW + n)
                           : (Vout + ((size_t)b * DIM + (m - 256)) * RHW + n);
    *(float4*)dst = s;
}

// ======================= fused attention (R9 design; packed-plane output) =======================
__global__ __launch_bounds__(256, 3)
void attn_kernel(const float* __restrict__ Q, const float* __restrict__ Kg,
                 const float* __restrict__ Vg,
                 uint32_t* __restrict__ Oh, uint32_t* __restrict__ Ol) {
    extern __shared__ float sm[];
    uint32_t* su  = (uint32_t*)sm;
    uint32_t* Qph = su;               // [64][20]
    uint32_t* Qpl = Qph + 1280;
    uint32_t* Kph = Qpl + 1280;       // [16][72]
    uint32_t* Kpl = Kph + 1152;
    uint32_t* Vph = Kpl + 1152;       // [32][36]
    uint32_t* Vpl = Vph + 1152;
    uint32_t* Pph = Vpl + 1152;       // [64][36]
    uint32_t* Ppl = Pph + 2304;
    float* lacc  = (float*)(Ppl + 2304);   // [4][64]
    float* li    = lacc + 256;             // [64]
    float* qraw  = li + 64;                // [32][65]
    float* kraw  = qraw + 2080;            // [32][64]
    float* vraw  = kraw + 2048;            // [32][64]
    float* po    = (float*)Pph;            // [64][36] final staging (aliases P)

    const int tid = threadIdx.x, warp = tid >> 5, lane = tid & 31;
    const int lr = lane >> 2, lc = lane & 3;
    const int wm = warp >> 2, wn = warp & 3;
    const int iw = (warp & 3) * 16;
    const int db = (warp >> 2) * 16;
    const int b = blockIdx.z, h = blockIdx.y, i0 = blockIdx.x * 64;

    const float* Qb = Q  + ((size_t)b * DIM + h * HEAD_DIM) * HW + i0;
    const float* Kb = Kg + ((size_t)b * DIM + h * HEAD_DIM) * RHW;
    const float* Vb = Vg + ((size_t)b * DIM + h * HEAD_DIM) * RHW;

    auto stageKV = [&](int j0) {
        #pragma unroll
        for (int idx = tid; idx < 512; idx += 256) {
            int d = idx >> 4, j4 = (idx & 15) * 4;
            cp16f(&kraw[d * 64 + j4], &Kb[(size_t)d * RHW + j0 + j4]);
            cp16f(&vraw[d * 64 + j4], &Vb[(size_t)d * RHW + j0 + j4]);
        }
        cp_commit();
    };

    stageKV(0);

    for (int idx = tid; idx < 2048; idx += 256) {
        int d = idx >> 6, i = idx & 63;
        qraw[d * 65 + i] = Qb[(size_t)d * HW + i] * SCALE;
    }
    lacc[tid] = 0.f;
    __syncthreads();

    for (int idx = tid; idx < 1024; idx += 256) {
        int i = idx >> 4, d2 = idx & 15;
        uint32_t hw_, lw_;
        split_pair(qraw[(2 * d2) * 65 + i], qraw[(2 * d2 + 1) * 65 + i], hw_, lw_);
        Qph[i * 20 + d2] = hw_;
        Qpl[i * 20 + d2] = lw_;
    }

    float oacc[2][4];
    #pragma unroll
    for (int nt = 0; nt < 2; nt++)
        #pragma unroll
        for (int q = 0; q < 4; q++) oacc[nt][q] = 0.f;

    for (int jt = 0; jt < 4; jt++) {
        cp_wait_n<0>();
        __syncthreads();

        for (int idx = tid; idx < 1024; idx += 256) {
            int d2 = idx >> 6, j = idx & 63;
            uint32_t hw_, lw_;
            split_pair(kraw[(2 * d2) * 64 + j], kraw[(2 * d2 + 1) * 64 + j], hw_, lw_);
            Kph[d2 * 72 + j] = hw_;
            Kpl[d2 * 72 + j] = lw_;
        }
        for (int idx = tid; idx < 1024; idx += 256) {
            int d = idx >> 5, j2 = idx & 31;
            float2 v = *(float2*)&vraw[d * 64 + 2 * j2];
            uint32_t hw_, lw_;
            split_pair(v.x, v.y, hw_, lw_);
            Vph[d * 36 + j2] = hw_;
            Vpl[d * 36 + j2] = lw_;
        }
        __syncthreads();

        if (jt < 3) stageKV((jt + 1) * 64);

        float sacc[2][2][4];
        #pragma unroll
        for (int mt = 0; mt < 2; mt++)
            #pragma unroll
            for (int nt = 0; nt < 2; nt++)
                #pragma unroll
                for (int q = 0; q < 4; q++) sacc[mt][nt][q] = 0.f;

        #pragma unroll
        for (int kk2 = 0; kk2 < 16; kk2 += 8) {
            uint32_t ah[2][4], al[2][4];
            #pragma unroll
            for (int mt = 0; mt < 2; mt++) {
                int r = wm * 32 + mt * 16 + lr;
                ah[mt][0] = Qph[r * 20 + kk2 + lc];
                ah[mt][1] = Qph[(r + 8) * 20 + kk2 + lc];
                ah[mt][2] = Qph[r * 20 + kk2 + lc + 4];
                ah[mt][3] = Qph[(r + 8) * 20 + kk2 + lc + 4];
                al[mt][0] = Qpl[r * 20 + kk2 + lc];
                al[mt][1] = Qpl[(r + 8) * 20 + kk2 + lc];
                al[mt][2] = Qpl[r * 20 + kk2 + lc + 4];
                al[mt][3] = Qpl[(r + 8) * 20 + kk2 + lc + 4];
            }
            uint32_t bh[2][2], bl[2][2];
            #pragma unroll
            for (int nt = 0; nt < 2; nt++) {
                int jj = wn * 16 + nt * 8 + lr;
                bh[nt][0] = Kph[(kk2 + lc) * 72 + jj];
                bh[nt][1] = Kph[(kk2 + lc + 4) * 72 + jj];
                bl[nt][0] = Kpl[(kk2 + lc) * 72 + jj];
                bl[nt][1] = Kpl[(kk2 + lc + 4) * 72 + jj];
            }
            #pragma unroll
            for (int mt = 0; mt < 2; mt++)
                #pragma unroll
                for (int nt = 0; nt < 2; nt++)
                    mma3(sacc[mt][nt], ah[mt], al[mt], bh[nt], bl[nt]);
        }

        #pragma unroll
        for (int mt = 0; mt < 2; mt++) {
            int r = wm * 32 + mt * 16 + lr;
            float rs0 = 0.f, rs1 = 0.f;
            #pragma unroll
            for (int nt = 0; nt < 2; nt++) {
                int j2 = wn * 8 + nt * 4 + lc;
                float e0 = __expf(sacc[mt][nt][0]);
                float e1 = __expf(sacc[mt][nt][1]);
                float e2 = __expf(sacc[mt][nt][2]);
                float e3 = __expf(sacc[mt][nt][3]);
                uint32_t hw_, lw_;
                split_pair(e0, e1, hw_, lw_);
                Pph[r * 36 + j2] = hw_;  Ppl[r * 36 + j2] = lw_;
                split_pair(e2, e3, hw_, lw_);
                Pph[(r + 8) * 36 + j2] = hw_;  Ppl[(r + 8) * 36 + j2] = lw_;
                rs0 += e0 + e1;
                rs1 += e2 + e3;
            }
            rs0 += __shfl_xor_sync(0xFFFFFFFFu, rs0, 1);
            rs0 += __shfl_xor_sync(0xFFFFFFFFu, rs0, 2);
            rs1 += __shfl_xor_sync(0xFFFFFFFFu, rs1, 1);
            rs1 += __shfl_xor_sync(0xFFFFFFFFu, rs1, 2);
            if (lc == 0) {
                lacc[wn * 64 + r]     += rs0;
                lacc[wn * 64 + r + 8] += rs1;
            }
        }
        __syncthreads();

        #pragma unroll
        for (int kk2 = 0; kk2 < 32; kk2 += 8) {
            uint32_t ah[4], al[4];
            int r = iw + lr;
            ah[0] = Pph[r * 36 + kk2 + lc];
            ah[1] = Pph[(r + 8) * 36 + kk2 + lc];
            ah[2] = Pph[r * 36 + kk2 + lc + 4];
            ah[3] = Pph[(r + 8) * 36 + kk2 + lc + 4];
            al[0] = Ppl[r * 36 + kk2 + lc];
            al[1] = Ppl[(r + 8) * 36 + kk2 + lc];
            al[2] = Ppl[r * 36 + kk2 + lc + 4];
            al[3] = Ppl[(r + 8) * 36 + kk2 + lc + 4];
            #pragma unroll
            for (int nt = 0; nt < 2; nt++) {
                int d = db + nt * 8 + lr;
                uint32_t bh[2], bl[2];
                bh[0] = Vph[d * 36 + kk2 + lc];
                bh[1] = Vph[d * 36 + kk2 + lc + 4];
                bl[0] = Vpl[d * 36 + kk2 + lc];
                bl[1] = Vpl[d * 36 + kk2 + lc + 4];
                mma3(oacc[nt], ah, al, bh, bl);
            }
        }
    }

    __syncthreads();
    if (tid < 64)
        li[tid] = 1.f / (lacc[tid] + lacc[64 + tid] + lacc[128 + tid] + lacc[192 + tid]);
    __syncthreads();

    // normalize + stage to po (aliases dead P tile)
    #pragma unroll
    for (int nt = 0; nt < 2; nt++) {
        int r = iw + lr, c = db + nt * 8 + lc * 2;
        float inv0 = li[r], inv1 = li[r + 8];
        po[r * 36 + c]           = oacc[nt][0] * inv0;
        po[r * 36 + c + 1]       = oacc[nt][1] * inv0;
        po[(r + 8) * 36 + c]     = oacc[nt][2] * inv1;
        po[(r + 8) * 36 + c + 1] = oacc[nt][3] * inv1;
    }
    __syncthreads();

    // packed-plane store: word(d2, i) = (O[2d2][i], O[2d2+1][i]); coalesced along i
    for (int idx = tid; idx < 1024; idx += 256) {
        int d2 = idx >> 6, i = idx & 63;
        uint32_t hw_, lw_;
        split_pair(po[i * 36 + 2 * d2], po[i * 36 + 2 * d2 + 1], hw_, lw_);
        const size_t o = ((size_t)b * 128 + h * 16 + d2) * HW + i0 + i;
        Oh[o] = hw_;
        Ol[o] = lw_;
    }
}

// ============================================================================
extern "C" void kernel_launch(void* const* d_in, const int* in_sizes, int n_in,
                              void* d_out, int out_size) {
    const float* x    = (const float*)d_in[0];
    const float* wq   = (const float*)d_in[1];
    const float* wk   = (const float*)d_in[2];
    const float* wv   = (const float*)d_in[3];
    const float* wout = (const float*)d_in[4];
    float* out = (float*)d_out;

    float *qp, *kvpp, *kp, *vp;
    uint32_t *wqh, *wql, *wkh, *wkl, *wvh, *wvl, *woh, *wol;
    uint32_t *xph, *xpl, *xrh, *xrl, *aoh, *aol;
    cudaGetSymbolAddress((void**)&qp,   g_q);
    cudaGetSymbolAddress((void**)&kvpp, g_kvp);
    cudaGetSymbolAddress((void**)&kp,   g_k);
    cudaGetSymbolAddress((void**)&vp,   g_v);
    cudaGetSymbolAddress((void**)&wqh,  g_wqh);  cudaGetSymbolAddress((void**)&wql, g_wql);
    cudaGetSymbolAddress((void**)&wkh,  g_wkh);  cudaGetSymbolAddress((void**)&wkl, g_wkl);
    cudaGetSymbolAddress((void**)&wvh,  g_wvh);  cudaGetSymbolAddress((void**)&wvl, g_wvl);
    cudaGetSymbolAddress((void**)&woh,  g_woh);  cudaGetSymbolAddress((void**)&wol, g_wol);
    cudaGetSymbolAddress((void**)&xph,  g_xph);  cudaGetSymbolAddress((void**)&xpl, g_xpl);
    cudaGetSymbolAddress((void**)&xrh,  g_xrh);  cudaGetSymbolAddress((void**)&xrl, g_xrl);
    cudaGetSymbolAddress((void**)&aoh,  g_aoh);  cudaGetSymbolAddress((void**)&aol, g_aol);

    const int g1_smem   = 2 * (2 * 128 * 20 + 2 * 16 * 136) * 4;   // 75776 B
    const int kv_smem   = 2 * (2 * 64 * 20 + 2 * 16 * 72) * 4;     // 38912 B
    const int attn_smem = (2 * 1280 + 2 * 1152 + 2 * 1152 + 2 * 2304 + 256 + 64
                           + 2080 + 2048 + 2048) * 4;               // 73088 B

    cudaFuncSetAttribute(gemm_q_kernel,  cudaFuncAttributeMaxDynamicSharedMemorySize, g1_smem);
    cudaFuncSetAttribute(gemm_o_kernel,  cudaFuncAttributeMaxDynamicSharedMemorySize, g1_smem);
    cudaFuncSetAttribute(kv_gemm_kernel, cudaFuncAttributeMaxDynamicSharedMemorySize, kv_smem);
    cudaFuncSetAttribute(attn_kernel,    cudaFuncAttributeMaxDynamicSharedMemorySize, attn_smem);

    // P0: one-time packs
    pack_pairs_kernel<<<128,  256>>>(wq,   wqh, wql, 256 * 128);
    pack_pairs_kernel<<<2048, 256>>>(wk,   wkh, wkl, 256 * 2048);
    pack_pairs_kernel<<<2048, 256>>>(wv,   wvh, wvl, 256 * 2048);
    pack_pairs_kernel<<<128,  256>>>(wout, woh, wol, 256 * 128);
    pack_x_kernel<<<dim3(HW / 256, 128, BATCH), 256>>>(x, xph, xpl);
    repack_kernel<<<dim3(DIM, BATCH), 256>>>(x, xrh, xrl);

    // K1: q = wq @ x
    gemm_q_kernel<<<dim3(HW / 128, 2, BATCH), 256, g1_smem>>>(wqh, wql, xph, xpl, qp);
    // K2: fused k & v GEMM (split-K=4) + reduce
    kv_gemm_kernel<<<dim3(4, 8, BATCH * 4), 256, kv_smem>>>(kvpp);
    kv_reduce_kernel<<<(8 * 512 * RHW / 4) / 256, 256>>>(kvpp, kp, vp);
    // K3: fused attention -> packed ao planes
    attn_kernel<<<dim3(HW / 64, HEADS, BATCH), 256, attn_smem>>>(qp, kp, vp, aoh, aol);
    // K4: out = wout @ ao
    gemm_o_kernel<<<dim3(HW / 128, 2, BATCH), 256, g1_smem>>>(woh, wol, aoh, aol, out);
}

// round 13
// speedup vs baseline: 2.8302x; 1.0527x over previous
#include <cuda_runtime.h>
#include <math.h>
#include <stdint.h>

#define BATCH 8
#define DIM 256
#define HEADS 8
#define HEAD_DIM 32
#define HW 4096
#define RHW 256
#define SCALE 0.17677669529663687f

// -------- scratch (static device globals; no cudaMalloc allowed) --------
__device__ float    g_q  [BATCH * DIM * HW];       // 32 MB fp32 q
__device__ float    g_kvp[4 * BATCH * 512 * RHW];  // 16 MB kv split-K partials
// packed bf16 hi/lo planes
__device__ uint32_t g_wqh[256 * 128],   g_wql[256 * 128];
__device__ uint32_t g_wkh[256 * 2048],  g_wkl[256 * 2048];
__device__ uint32_t g_wvh[256 * 2048],  g_wvl[256 * 2048];
__device__ uint32_t g_woh[256 * 128],   g_wol[256 * 128];
__device__ uint32_t g_xph[BATCH * 128 * HW],  g_xpl[BATCH * 128 * HW];    // x pairs along c
__device__ uint32_t g_xrh[BATCH * 2048 * RHW], g_xrl[BATCH * 2048 * RHW]; // im2col pairs along k
__device__ uint32_t g_aoh[BATCH * 128 * HW],  g_aol[BATCH * 128 * HW];    // ao pairs along d
// pre-packed K/V in attention fragment layouts
__device__ uint32_t g_kph[BATCH * HEADS * 16 * 256], g_kpl[BATCH * HEADS * 16 * 256]; // [bh][d2][j]
__device__ uint32_t g_vph[BATCH * HEADS * 32 * 128], g_vpl[BATCH * HEADS * 32 * 128]; // [bh][d][j2]

extern __shared__ char dynsmem[];

// ======================= bf16 split/pack + MMA helpers =======================
__device__ __forceinline__ uint32_t pack_bf16(float v0, float v1) {
    uint32_t r;
    asm("cvt.rn.bf16x2.f32 %0, %1, %2;" : "=r"(r) : "f"(v1), "f"(v0));
    return r;
}
__device__ __forceinline__ void split_pair(float v0, float v1, uint32_t& h, uint32_t& l) {
    h = pack_bf16(v0, v1);
    float h0 = __uint_as_float(h << 16);
    float h1 = __uint_as_float(h & 0xFFFF0000u);
    l = pack_bf16(v0 - h0, v1 - h1);
}
__device__ __forceinline__ void mma_bf16(float c[4], const uint32_t a[4], const uint32_t b[2]) {
    asm volatile(
        "mma.sync.aligned.m16n8k16.row.col.f32.bf16.bf16.f32 "
        "{%0,%1,%2,%3},{%4,%5,%6,%7},{%8,%9},{%0,%1,%2,%3};"
        : "+f"(c[0]), "+f"(c[1]), "+f"(c[2]), "+f"(c[3])
        : "r"(a[0]), "r"(a[1]), "r"(a[2]), "r"(a[3]), "r"(b[0]), "r"(b[1]));
}
__device__ __forceinline__ void mma3(float c[4], const uint32_t ah[4], const uint32_t al[4],
                                     const uint32_t bh[2], const uint32_t bl[2]) {
    mma_bf16(c, ah, bh);
    mma_bf16(c, al, bh);
    mma_bf16(c, ah, bl);
}

// ======================= cp.async helpers =======================
__device__ __forceinline__ void cp16(uint32_t* smem_dst, const uint32_t* gsrc) {
    uint32_t s;
    asm("{ .reg .u64 t; cvta.to.shared.u64 t, %1; cvt.u32.u64 %0, t; }"
        : "=r"(s) : "l"(smem_dst));
    asm volatile("cp.async.ca.shared.global [%0], [%1], 16;" :: "r"(s), "l"(gsrc));
}
__device__ __forceinline__ void cp_commit() { asm volatile("cp.async.commit_group;"); }
template<int N> __device__ __forceinline__ void cp_wait_n() {
    asm volatile("cp.async.wait_group %0;" :: "n"(N));
}

// ======================= packed-operand double-buffered GEMM body =======================
// (as validated in R10) A plane word (r,k2)=(A[r][2k2],A[r][2k2+1]); B plane word (k2,n).
template<int BM, int BN>
__device__ __forceinline__ void gemm_packed_body(
    const uint32_t* __restrict__ Ah, const uint32_t* __restrict__ Al, int lda2,
    const uint32_t* __restrict__ Bh, const uint32_t* __restrict__ Bl, int ldb2,
    float* __restrict__ C, int ldc, int k2steps, int m0, int n0, uint32_t* smem)
{
    constexpr int BK2 = 16;
    constexpr int LDA2 = 20;
    constexpr int LDB2 = BN + 8;
    constexpr int ASZ = BM * LDA2, BSZ = BK2 * LDB2;
    constexpr int STG = 2 * ASZ + 2 * BSZ;
    constexpr int WM = BM / 2, WN = BN / 4;
    constexpr int MT = WM / 16, NT = WN / 8;

    const int tid = threadIdx.x, warp = tid >> 5, lane = tid & 31;
    const int wm = warp >> 2, wn = warp & 3;
    const int lr = lane >> 2, lc = lane & 3;

    float acc[MT][NT][4];
    #pragma unroll
    for (int i = 0; i < MT; i++)
        #pragma unroll
        for (int j = 0; j < NT; j++)
            #pragma unroll
            for (int q = 0; q < 4; q++) acc[i][j][q] = 0.f;

    auto stage = [&](int k2_0, uint32_t* buf) {
        uint32_t* Aht = buf;
        uint32_t* Alt = buf + ASZ;
        uint32_t* Bht = buf + 2 * ASZ;
        uint32_t* Blt = buf + 2 * ASZ + BSZ;
        #pragma unroll
        for (int i = tid; i < BM * 4; i += 256) {
            int r = i >> 2, c4 = (i & 3) * 4;
            cp16(&Aht[r * LDA2 + c4], &Ah[(size_t)(m0 + r) * lda2 + k2_0 + c4]);
            cp16(&Alt[r * LDA2 + c4], &Al[(size_t)(m0 + r) * lda2 + k2_0 + c4]);
        }
        #pragma unroll
        for (int i = tid; i < BK2 * (BN / 4); i += 256) {
            int r = i / (BN / 4), c4 = (i % (BN / 4)) * 4;
            cp16(&Bht[r * LDB2 + c4], &Bh[(size_t)(k2_0 + r) * ldb2 + n0 + c4]);
            cp16(&Blt[r * LDB2 + c4], &Bl[(size_t)(k2_0 + r) * ldb2 + n0 + c4]);
        }
        cp_commit();
    };

    const int nit = k2steps / BK2;
    stage(0, smem);

    for (int it = 0; it < nit; it++) {
        uint32_t* buf = smem + (it & 1) * STG;
        __syncthreads();
        if (it + 1 < nit) {
            stage((it + 1) * BK2, smem + ((it + 1) & 1) * STG);
            cp_wait_n<1>();
        } else {
            cp_wait_n<0>();
        }
        __syncthreads();

        uint32_t* Aht = buf;
        uint32_t* Alt = buf + ASZ;
        uint32_t* Bht = buf + 2 * ASZ;
        uint32_t* Blt = buf + 2 * ASZ + BSZ;

        #pragma unroll
        for (int kk2 = 0; kk2 < BK2; kk2 += 8) {
            uint32_t ah[MT][4], al[MT][4];
            #pragma unroll
            for (int mt = 0; mt < MT; mt++) {
                int r = wm * WM + mt * 16 + lr;
                ah[mt][0] = Aht[r * LDA2 + kk2 + lc];
                ah[mt][1] = Aht[(r + 8) * LDA2 + kk2 + lc];
                ah[mt][2] = Aht[r * LDA2 + kk2 + lc + 4];
                ah[mt][3] = Aht[(r + 8) * LDA2 + kk2 + lc + 4];
                al[mt][0] = Alt[r * LDA2 + kk2 + lc];
                al[mt][1] = Alt[(r + 8) * LDA2 + kk2 + lc];
                al[mt][2] = Alt[r * LDA2 + kk2 + lc + 4];
                al[mt][3] = Alt[(r + 8) * LDA2 + kk2 + lc + 4];
            }
            uint32_t bh[NT][2], bl[NT][2];
            #pragma unroll
            for (int nt = 0; nt < NT; nt++) {
                int cc = wn * WN + nt * 8 + lr;
                bh[nt][0] = Bht[(kk2 + lc) * LDB2 + cc];
                bh[nt][1] = Bht[(kk2 + lc + 4) * LDB2 + cc];
                bl[nt][0] = Blt[(kk2 + lc) * LDB2 + cc];
                bl[nt][1] = Blt[(kk2 + lc + 4) * LDB2 + cc];
            }
            #pragma unroll
            for (int mt = 0; mt < MT; mt++)
                #pragma unroll
                for (int nt = 0; nt < NT; nt++)
                    mma3(acc[mt][nt], ah[mt], al[mt], bh[nt], bl[nt]);
        }
    }

    #pragma unroll
    for (int mt = 0; mt < MT; mt++) {
        int r = m0 + wm * WM + mt * 16 + lr;
        #pragma unroll
        for (int nt = 0; nt < NT; nt++) {
            int c = n0 + wn * WN + nt * 8 + lc * 2;
            *(float2*)&C[(size_t)r * ldc + c]       = make_float2(acc[mt][nt][0], acc[mt][nt][1]);
            *(float2*)&C[(size_t)(r + 8) * ldc + c] = make_float2(acc[mt][nt][2], acc[mt][nt][3]);
        }
    }
}

// ======================= pack kernels =======================
__global__ __launch_bounds__(256)
void pack_pairs_kernel(const float* __restrict__ src, uint32_t* __restrict__ h,
                       uint32_t* __restrict__ l, int npairs) {
    int idx = blockIdx.x * 256 + threadIdx.x;
    if (idx >= npairs) return;
    float2 v = ((const float2*)src)[idx];
    uint32_t hw_, lw_;
    split_pair(v.x, v.y, hw_, lw_);
    h[idx] = hw_;
    l[idx] = lw_;
}

// x pack: word(b,c2,n) = (x[b][2c2][n], x[b][2c2+1][n])
__global__ __launch_bounds__(256)
void pack_x_kernel(const float* __restrict__ X, uint32_t* __restrict__ h,
                   uint32_t* __restrict__ l) {
    const int n = blockIdx.x * 256 + threadIdx.x;
    const int c2 = blockIdx.y, b = blockIdx.z;
    const float* r0 = X + ((size_t)b * DIM + 2 * c2) * HW;
    uint32_t hw_, lw_;
    split_pair(r0[n], r0[HW + n], hw_, lw_);
    const size_t o = ((size_t)b * 128 + c2) * HW + n;
    h[o] = hw_;
    l[o] = lw_;
}

// im2col repack -> packed planes (kv path)
__global__ __launch_bounds__(256)
void repack_kernel(const float* __restrict__ X, uint32_t* __restrict__ h,
                   uint32_t* __restrict__ l) {
    float* pl = (float*)dynsmem;   // [4096]
    const int ci = blockIdx.x, b = blockIdx.y, tid = threadIdx.x;
    const float* src = X + ((size_t)b * DIM + ci) * HW;
    #pragma unroll
    for (int i = tid; i < 1024; i += 256)
        ((float4*)pl)[i] = ((const float4*)src)[i];
    __syncthreads();
    const int oh = tid >> 4, ow = tid & 15;
    #pragma unroll
    for (int kh = 0; kh < 4; kh++)
        #pragma unroll
        for (int kw2 = 0; kw2 < 2; kw2++) {
            float v0 = pl[(oh * 4 + kh) * 64 + ow * 4 + 2 * kw2];
            float v1 = pl[(oh * 4 + kh) * 64 + ow * 4 + 2 * kw2 + 1];
            uint32_t hw_, lw_;
            split_pair(v0, v1, hw_, lw_);
            const size_t o = ((size_t)b * 2048 + ci * 8 + kh * 2 + kw2) * RHW + tid;
            h[o] = hw_;
            l[o] = lw_;
        }
}

// ======================= kv GEMM (split-K=4) =======================
__global__ __launch_bounds__(256, 3)
void kv_gemm_kernel(float* __restrict__ Part) {
    uint32_t* smem = (uint32_t*)dynsmem;
    const int mblk = blockIdx.y;
    const int b  = blockIdx.z & 7;
    const int ks = blockIdx.z >> 3;
    const int koff2 = ks * 512;
    const uint32_t* Ah = (mblk < 4) ? (g_wkh + koff2) : (g_wvh + koff2 - (size_t)256 * 2048);
    const uint32_t* Al = (mblk < 4) ? (g_wkl + koff2) : (g_wvl + koff2 - (size_t)256 * 2048);
    const uint32_t* Bh = g_xrh + ((size_t)b * 2048 + koff2) * RHW;
    const uint32_t* Bl = g_xrl + ((size_t)b * 2048 + koff2) * RHW;
    float* C = g_kvp + ((size_t)(ks * BATCH + b) * 512) * RHW;
    gemm_packed_body<64, 64>(Ah, Al, 2048, Bh, Bl, RHW,
                             C, RHW, 512, mblk * 64, blockIdx.x * 64, smem);
}

// reduce split-K partials AND emit packed K/V planes in attention fragment layouts.
// blocks [0,256): K region — thread = (b, m2 in 0..127, j4 in 0..63).
//   Kp word(bh, d2, j) = split(K[2*m2][j], K[2*m2+1][j]); h = m2>>4, d2 = m2&15.
// blocks [256,768): V region — thread = (b, m in 0..255, j4 in 0..63) -> 2 words.
//   Vp word(bh, d, j2) = split(V[m][2j2], V[m][2j2+1]); h = m>>5, d = m&31.
__global__ __launch_bounds__(256)
void kv_reduce_pack_kernel(const float* __restrict__ P,
                           uint32_t* __restrict__ Kph, uint32_t* __restrict__ Kpl,
                           uint32_t* __restrict__ Vph, uint32_t* __restrict__ Vpl) {
    const size_t CH = (size_t)8 * 512 * RHW;   // floats per split chunk
    if (blockIdx.x < 256) {
        int t = blockIdx.x * 256 + threadIdx.x;          // 0..65535
        int j4 = (t & 63) * 4;
        int m2 = (t >> 6) & 127;
        int b  = t >> 13;
        const float* p0 = P + ((size_t)b * 512 + 2 * m2) * RHW + j4;
        const float* p1 = p0 + RHW;
        float4 r0 = *(const float4*)p0, r1 = *(const float4*)p1;
        #pragma unroll
        for (int ks = 1; ks < 4; ks++) {
            float4 a = *(const float4*)(p0 + ks * CH);
            float4 c = *(const float4*)(p1 + ks * CH);
            r0.x += a.x; r0.y += a.y; r0.z += a.z; r0.w += a.w;
            r1.x += c.x; r1.y += c.y; r1.z += c.z; r1.w += c.w;
        }
        const int h = m2 >> 4, d2 = m2 & 15;
        const size_t o = (((size_t)(b * 8 + h) * 16 + d2) * 256) + j4;
        uint32_t hw_, lw_;
        split_pair(r0.x, r1.x, hw_, lw_); Kph[o]     = hw_; Kpl[o]     = lw_;
        split_pair(r0.y, r1.y, hw_, lw_); Kph[o + 1] = hw_; Kpl[o + 1] = lw_;
        split_pair(r0.z, r1.z, hw_, lw_); Kph[o + 2] = hw_; Kpl[o + 2] = lw_;
        split_pair(r0.w, r1.w, hw_, lw_); Kph[o + 3] = hw_; Kpl[o + 3] = lw_;
    } else {
        int t = (blockIdx.x - 256) * 256 + threadIdx.x;  // 0..131071
        int j4 = (t & 63) * 4;
        int m  = (t >> 6) & 255;
        int b  = t >> 14;
        const float* p0 = P + ((size_t)b * 512 + 256 + m) * RHW + j4;
        float4 v = *(const float4*)p0;
        #pragma unroll
        for (int ks = 1; ks < 4; ks++) {
            float4 a = *(const float4*)(p0 + ks * CH);
            v.x += a.x; v.y += a.y; v.z += a.z; v.w += a.w;
        }
        const int h = m >> 5, d = m & 31;
        const size_t o = (((size_t)(b * 8 + h) * 32 + d) * 128) + (j4 >> 1);
        uint32_t hw_, lw_;
        split_pair(v.x, v.y, hw_, lw_); Vph[o]     = hw_; Vpl[o]     = lw_;
        split_pair(v.z, v.w, hw_, lw_); Vph[o + 1] = hw_; Vpl[o + 1] = lw_;
    }
}

// ======================= GEMM kernels (legacy path; R10-validated) =======================
__global__ __launch_bounds__(256, 2)
void gemm_q_kernel(const uint32_t* __restrict__ Ah, const uint32_t* __restrict__ Al,
                   const uint32_t* __restrict__ Bh, const uint32_t* __restrict__ Bl,
                   float* __restrict__ Cg) {
    uint32_t* smem = (uint32_t*)dynsmem;
    const size_t bo = (size_t)blockIdx.z * 128 * HW;
    float* C = Cg + (size_t)blockIdx.z * DIM * HW;
    gemm_packed_body<128, 128>(Ah, Al, 128, Bh + bo, Bl + bo, HW,
                               C, HW, 128, blockIdx.y * 128, blockIdx.x * 128, smem);
}

// ======================= fused attention: pre-packed K/V, double-buffered =======================
// smem (words): Qph 1280 | Qpl 1280 | kvbuf 2x4608 | Pph 2304 | Ppl 2304 | lacc 256 | li 64 | qraw 2080
__global__ __launch_bounds__(256, 3)
void attn_kernel(const float* __restrict__ Q,
                 uint32_t* __restrict__ Oh, uint32_t* __restrict__ Ol) {
    uint32_t* su  = (uint32_t*)dynsmem;
    uint32_t* Qph = su;
    uint32_t* Qpl = Qph + 1280;
    uint32_t* kvbuf = Qpl + 1280;          // 2 x [Kh 1152 | Kl 1152 | Vh 1152 | Vl 1152]
    uint32_t* Pph = kvbuf + 2 * 4608;
    uint32_t* Ppl = Pph + 2304;
    float* lacc  = (float*)(Ppl + 2304);   // [4][64]
    float* li    = lacc + 256;             // [64]
    float* qraw  = li + 64;                // [32][65]
    float* po    = (float*)Pph;            // [64][36] final staging (aliases P)

    const int tid = threadIdx.x, warp = tid >> 5, lane = tid & 31;
    const int lr = lane >> 2, lc = lane & 3;
    const int wm = warp >> 2, wn = warp & 3;
    const int iw = (warp & 3) * 16;
    const int db = (warp >> 2) * 16;
    const int b = blockIdx.z, h = blockIdx.y, i0 = blockIdx.x * 64;

    const float* Qb = Q + ((size_t)b * DIM + h * HEAD_DIM) * HW + i0;
    const uint32_t* Kgh = g_kph + (size_t)(b * 8 + h) * 16 * 256;
    const uint32_t* Kgl = g_kpl + (size_t)(b * 8 + h) * 16 * 256;
    const uint32_t* Vgh = g_vph + (size_t)(b * 8 + h) * 32 * 128;
    const uint32_t* Vgl = g_vpl + (size_t)(b * 8 + h) * 32 * 128;

    auto stageKV = [&](int jt, int bufsel) {
        uint32_t* Kh = kvbuf + bufsel * 4608;
        uint32_t* Kl = Kh + 1152;
        uint32_t* Vh = Kl + 1152;
        uint32_t* Vl = Vh + 1152;
        const int j0 = jt * 64, jw0 = jt * 32;
        {   // K: 16 rows x 64 words = 256 chunks per plane; 1 per thread
            int r = tid >> 4, c4 = (tid & 15) * 4;
            cp16(&Kh[r * 72 + c4], &Kgh[r * 256 + j0 + c4]);
            cp16(&Kl[r * 72 + c4], &Kgl[r * 256 + j0 + c4]);
        }
        {   // V: 32 rows x 32 words = 256 chunks per plane
            int r = tid >> 3, c4 = (tid & 7) * 4;
            cp16(&Vh[r * 36 + c4], &Vgh[r * 128 + jw0 + c4]);
            cp16(&Vl[r * 36 + c4], &Vgl[r * 128 + jw0 + c4]);
        }
        cp_commit();
    };

    stageKV(0, 0);

    for (int idx = tid; idx < 2048; idx += 256) {
        int d = idx >> 6, i = idx & 63;
        qraw[d * 65 + i] = Qb[(size_t)d * HW + i] * SCALE;
    }
    lacc[tid] = 0.f;
    __syncthreads();

    for (int idx = tid; idx < 1024; idx += 256) {
        int i = idx >> 4, d2 = idx & 15;
        uint32_t hw_, lw_;
        split_pair(qraw[(2 * d2) * 65 + i], qraw[(2 * d2 + 1) * 65 + i], hw_, lw_);
        Qph[i * 20 + d2] = hw_;
        Qpl[i * 20 + d2] = lw_;
    }

    float oacc[2][4];
    #pragma unroll
    for (int nt = 0; nt < 2; nt++)
        #pragma unroll
        for (int q = 0; q < 4; q++) oacc[nt][q] = 0.f;

    for (int jt = 0; jt < 4; jt++) {
        cp_wait_n<0>();
        __syncthreads();   // buf[jt&1] ready; PV of jt-1 done; Q pack visible (jt=0)

        if (jt < 3) stageKV(jt + 1, (jt + 1) & 1);   // overlaps with S/exp/PV

        uint32_t* Kph = kvbuf + (jt & 1) * 4608;
        uint32_t* Kpl = Kph + 1152;
        uint32_t* Vph = Kpl + 1152;
        uint32_t* Vpl = Vph + 1152;

        // ---- S = Q K^T : M=64(i), N=64(j), K=32(d). warp tile 32x16 ----
        float sacc[2][2][4];
        #pragma unroll
        for (int mt = 0; mt < 2; mt++)
            #pragma unroll
            for (int nt = 0; nt < 2; nt++)
                #pragma unroll
                for (int q = 0; q < 4; q++) sacc[mt][nt][q] = 0.f;

        #pragma unroll
        for (int kk2 = 0; kk2 < 16; kk2 += 8) {
            uint32_t ah[2][4], al[2][4];
            #pragma unroll
            for (int mt = 0; mt < 2; mt++) {
                int r = wm * 32 + mt * 16 + lr;
                ah[mt][0] = Qph[r * 20 + kk2 + lc];
                ah[mt][1] = Qph[(r + 8) * 20 + kk2 + lc];
                ah[mt][2] = Qph[r * 20 + kk2 + lc + 4];
                ah[mt][3] = Qph[(r + 8) * 20 + kk2 + lc + 4];
                al[mt][0] = Qpl[r * 20 + kk2 + lc];
                al[mt][1] = Qpl[(r + 8) * 20 + kk2 + lc];
                al[mt][2] = Qpl[r * 20 + kk2 + lc + 4];
                al[mt][3] = Qpl[(r + 8) * 20 + kk2 + lc + 4];
            }
            uint32_t bh[2][2], bl[2][2];
            #pragma unroll
            for (int nt = 0; nt < 2; nt++) {
                int jj = wn * 16 + nt * 8 + lr;
                bh[nt][0] = Kph[(kk2 + lc) * 72 + jj];
                bh[nt][1] = Kph[(kk2 + lc + 4) * 72 + jj];
                bl[nt][0] = Kpl[(kk2 + lc) * 72 + jj];
                bl[nt][1] = Kpl[(kk2 + lc + 4) * 72 + jj];
            }
            #pragma unroll
            for (int mt = 0; mt < 2; mt++)
                #pragma unroll
                for (int nt = 0; nt < 2; nt++)
                    mma3(sacc[mt][nt], ah[mt], al[mt], bh[nt], bl[nt]);
        }

        // ---- exp -> P (packed pairs along j), accumulate row sums ----
        #pragma unroll
        for (int mt = 0; mt < 2; mt++) {
            int r = wm * 32 + mt * 16 + lr;
            float rs0 = 0.f, rs1 = 0.f;
            #pragma unroll
            for (int nt = 0; nt < 2; nt++) {
                int j2 = wn * 8 + nt * 4 + lc;
                float e0 = __expf(sacc[mt][nt][0]);
                float e1 = __expf(sacc[mt][nt][1]);
                float e2 = __expf(sacc[mt][nt][2]);
                float e3 = __expf(sacc[mt][nt][3]);
                uint32_t hw_, lw_;
                split_pair(e0, e1, hw_, lw_);
                Pph[r * 36 + j2] = hw_;  Ppl[r * 36 + j2] = lw_;
                split_pair(e2, e3, hw_, lw_);
                Pph[(r + 8) * 36 + j2] = hw_;  Ppl[(r + 8) * 36 + j2] = lw_;
                rs0 += e0 + e1;
                rs1 += e2 + e3;
            }
            rs0 += __shfl_xor_sync(0xFFFFFFFFu, rs0, 1);
            rs0 += __shfl_xor_sync(0xFFFFFFFFu, rs0, 2);
            rs1 += __shfl_xor_sync(0xFFFFFFFFu, rs1, 1);
            rs1 += __shfl_xor_sync(0xFFFFFFFFu, rs1, 2);
            if (lc == 0) {
                lacc[wn * 64 + r]     += rs0;
                lacc[wn * 64 + r + 8] += rs1;
            }
        }
        __syncthreads();

        // ---- PV accumulate: O[iw..+16][db..+16] += P_tile * V_tile (K=64 j) ----
        #pragma unroll
        for (int kk2 = 0; kk2 < 32; kk2 += 8) {
            uint32_t ah[4], al[4];
            int r = iw + lr;
            ah[0] = Pph[r * 36 + kk2 + lc];
            ah[1] = Pph[(r + 8) * 36 + kk2 + lc];
            ah[2] = Pph[r * 36 + kk2 + lc + 4];
            ah[3] = Pph[(r + 8) * 36 + kk2 + lc + 4];
            al[0] = Ppl[r * 36 + kk2 + lc];
            al[1] = Ppl[(r + 8) * 36 + kk2 + lc];
            al[2] = Ppl[r * 36 + kk2 + lc + 4];
            al[3] = Ppl[(r + 8) * 36 + kk2 + lc + 4];
            #pragma unroll
            for (int nt = 0; nt < 2; nt++) {
                int d = db + nt * 8 + lr;
                uint32_t bh[2], bl[2];
                bh[0] = Vph[d * 36 + kk2 + lc];
                bh[1] = Vph[d * 36 + kk2 + lc + 4];
                bl[0] = Vpl[d * 36 + kk2 + lc];
                bl[1] = Vpl[d * 36 + kk2 + lc + 4];
                mma3(oacc[nt], ah, al, bh, bl);
            }
        }
    }

    __syncthreads();
    if (tid < 64)
        li[tid] = 1.f / (lacc[tid] + lacc[64 + tid] + lacc[128 + tid] + lacc[192 + tid]);
    __syncthreads();

    #pragma unroll
    for (int nt = 0; nt < 2; nt++) {
        int r = iw + lr, c = db + nt * 8 + lc * 2;
        float inv0 = li[r], inv1 = li[r + 8];
        po[r * 36 + c]           = oacc[nt][0] * inv0;
        po[r * 36 + c + 1]       = oacc[nt][1] * inv0;
        po[(r + 8) * 36 + c]     = oacc[nt][2] * inv1;
        po[(r + 8) * 36 + c + 1] = oacc[nt][3] * inv1;
    }
    __syncthreads();

    // packed-plane store: word(b, h*16+d2, i0+i) = (O[2d2][i], O[2d2+1][i]); coalesced along i
    for (int idx = tid; idx < 1024; idx += 256) {
        int d2 = idx >> 6, i = idx & 63;
        uint32_t hw_, lw_;
        split_pair(po[i * 36 + 2 * d2], po[i * 36 + 2 * d2 + 1], hw_, lw_);
        const size_t o = ((size_t)b * 128 + h * 16 + d2) * HW + i0 + i;
        Oh[o] = hw_;
        Ol[o] = lw_;
    }
}

// ============================================================================
extern "C" void kernel_launch(void* const* d_in, const int* in_sizes, int n_in,
                              void* d_out, int out_size) {
    const float* x    = (const float*)d_in[0];
    const float* wq   = (const float*)d_in[1];
    const float* wk   = (const float*)d_in[2];
    const float* wv   = (const float*)d_in[3];
    const float* wout = (const float*)d_in[4];
    float* out = (float*)d_out;

    float *qp, *kvpp;
    uint32_t *wqh, *wql, *wkh, *wkl, *wvh, *wvl, *woh, *wol;
    uint32_t *xph, *xpl, *xrh, *xrl, *aoh, *aol, *kph, *kpl, *vph, *vpl;
    cudaGetSymbolAddress((void**)&qp,   g_q);
    cudaGetSymbolAddress((void**)&kvpp, g_kvp);
    cudaGetSymbolAddress((void**)&wqh,  g_wqh);  cudaGetSymbolAddress((void**)&wql, g_wql);
    cudaGetSymbolAddress((void**)&wkh,  g_wkh);  cudaGetSymbolAddress((void**)&wkl, g_wkl);
    cudaGetSymbolAddress((void**)&wvh,  g_wvh);  cudaGetSymbolAddress((void**)&wvl, g_wvl);
    cudaGetSymbolAddress((void**)&woh,  g_woh);  cudaGetSymbolAddress((void**)&wol, g_wol);
    cudaGetSymbolAddress((void**)&xph,  g_xph);  cudaGetSymbolAddress((void**)&xpl, g_xpl);
    cudaGetSymbolAddress((void**)&xrh,  g_xrh);  cudaGetSymbolAddress((void**)&xrl, g_xrl);
    cudaGetSymbolAddress((void**)&aoh,  g_aoh);  cudaGetSymbolAddress((void**)&aol, g_aol);
    cudaGetSymbolAddress((void**)&kph,  g_kph);  cudaGetSymbolAddress((void**)&kpl, g_kpl);
    cudaGetSymbolAddress((void**)&vph,  g_vph);  cudaGetSymbolAddress((void**)&vpl, g_vpl);

    const int g1_smem   = 2 * (2 * 128 * 20 + 2 * 16 * 136) * 4;   // 75776 B
    const int kv_smem   = 2 * (2 * 64 * 20 + 2 * 16 * 72) * 4;     // 38912 B
    const int attn_smem = (1280 * 2 + 2 * 4608 + 2 * 2304 + 256 + 64 + 2080) * 4; // 75136 B
    const int rp_smem   = 4096 * 4;

    cudaFuncSetAttribute(gemm_q_kernel,  cudaFuncAttributeMaxDynamicSharedMemorySize, g1_smem);
    cudaFuncSetAttribute(kv_gemm_kernel, cudaFuncAttributeMaxDynamicSharedMemorySize, kv_smem);
    cudaFuncSetAttribute(attn_kernel,    cudaFuncAttributeMaxDynamicSharedMemorySize, attn_smem);
    cudaFuncSetAttribute(repack_kernel,  cudaFuncAttributeMaxDynamicSharedMemorySize, rp_smem);

    // P0: one-time packs
    pack_pairs_kernel<<<128,  256>>>(wq,   wqh, wql, 256 * 128);
    pack_pairs_kernel<<<2048, 256>>>(wk,   wkh, wkl, 256 * 2048);
    pack_pairs_kernel<<<2048, 256>>>(wv,   wvh, wvl, 256 * 2048);
    pack_pairs_kernel<<<128,  256>>>(wout, woh, wol, 256 * 128);
    pack_x_kernel<<<dim3(HW / 256, 128, BATCH), 256>>>(x, xph, xpl);
    repack_kernel<<<dim3(DIM, BATCH), 256, rp_smem>>>(x, xrh, xrl);

    // K1: q = wq @ x
    gemm_q_kernel<<<dim3(HW / 128, 2, BATCH), 256, g1_smem>>>(wqh, wql, xph, xpl, qp);
    // K2: fused k & v GEMM (split-K=4) + reduce-and-pack into attention layouts
    kv_gemm_kernel<<<dim3(4, 8, BATCH * 4), 256, kv_smem>>>(kvpp);
    kv_reduce_pack_kernel<<<768, 256>>>(kvpp, kph, kpl, vph, vpl);
    // K3: fused attention (pre-packed K/V, double-buffered) -> packed ao planes
    attn_kernel<<<dim3(HW / 64, HEADS, BATCH), 256, attn_smem>>>(qp, aoh, aol);
    // K4: out = wout @ ao
    gemm_q_kernel<<<dim3(HW / 128, 2, BATCH), 256, g1_smem>>>(woh, wol, aoh, aol, out);
}

// round 14
// speedup vs baseline: 2.9266x; 1.0341x over previous
#include <cuda_runtime.h>
#include <math.h>
#include <stdint.h>

#define BATCH 8
#define DIM 256
#define HEADS 8
#define HEAD_DIM 32
#define HW 4096
#define RHW 256
#define SCALE 0.17677669529663687f

// -------- scratch (static device globals; no cudaMalloc allowed) --------
__device__ float    g_q  [BATCH * DIM * HW];       // 32 MB fp32 q
__device__ float    g_kvp[4 * BATCH * 512 * RHW];  // 16 MB kv split-K partials
// packed bf16 hi/lo planes
__device__ uint32_t g_wqh[256 * 128],   g_wql[256 * 128];
__device__ uint32_t g_wkh[256 * 2048],  g_wkl[256 * 2048];
__device__ uint32_t g_wvh[256 * 2048],  g_wvl[256 * 2048];
__device__ uint32_t g_woh[256 * 128],   g_wol[256 * 128];
__device__ uint32_t g_xph[BATCH * 128 * HW],  g_xpl[BATCH * 128 * HW];    // x pairs along c
__device__ uint32_t g_xrh[BATCH * 2048 * RHW], g_xrl[BATCH * 2048 * RHW]; // im2col pairs along k
__device__ uint32_t g_aoh[BATCH * 128 * HW],  g_aol[BATCH * 128 * HW];    // ao pairs along d
// pre-packed K/V in attention fragment layouts
__device__ uint32_t g_kph[BATCH * HEADS * 16 * 256], g_kpl[BATCH * HEADS * 16 * 256]; // [bh][d2][j]
__device__ uint32_t g_vph[BATCH * HEADS * 32 * 128], g_vpl[BATCH * HEADS * 32 * 128]; // [bh][d][j2]

extern __shared__ char dynsmem[];

// ======================= bf16 split/pack + MMA helpers =======================
__device__ __forceinline__ uint32_t pack_bf16(float v0, float v1) {
    uint32_t r;
    asm("cvt.rn.bf16x2.f32 %0, %1, %2;" : "=r"(r) : "f"(v1), "f"(v0));
    return r;
}
__device__ __forceinline__ void split_pair(float v0, float v1, uint32_t& h, uint32_t& l) {
    h = pack_bf16(v0, v1);
    float h0 = __uint_as_float(h << 16);
    float h1 = __uint_as_float(h & 0xFFFF0000u);
    l = pack_bf16(v0 - h0, v1 - h1);
}
__device__ __forceinline__ void mma_bf16(float c[4], const uint32_t a[4], const uint32_t b[2]) {
    asm volatile(
        "mma.sync.aligned.m16n8k16.row.col.f32.bf16.bf16.f32 "
        "{%0,%1,%2,%3},{%4,%5,%6,%7},{%8,%9},{%0,%1,%2,%3};"
        : "+f"(c[0]), "+f"(c[1]), "+f"(c[2]), "+f"(c[3])
        : "r"(a[0]), "r"(a[1]), "r"(a[2]), "r"(a[3]), "r"(b[0]), "r"(b[1]));
}
__device__ __forceinline__ void mma3(float c[4], const uint32_t ah[4], const uint32_t al[4],
                                     const uint32_t bh[2], const uint32_t bl[2]) {
    mma_bf16(c, ah, bh);
    mma_bf16(c, al, bh);
    mma_bf16(c, ah, bl);
}
// ldmatrix x4: loads 4 m8n8 b16 fragments (A-operand layout)
__device__ __forceinline__ void ldsm_x4(uint32_t r[4], uint32_t saddr) {
    asm volatile("ldmatrix.sync.aligned.m8n8.x4.shared.b16 {%0,%1,%2,%3}, [%4];"
        : "=r"(r[0]), "=r"(r[1]), "=r"(r[2]), "=r"(r[3]) : "r"(saddr));
}

// ======================= cp.async helpers =======================
__device__ __forceinline__ void cp16(uint32_t* smem_dst, const uint32_t* gsrc) {
    uint32_t s;
    asm("{ .reg .u64 t; cvta.to.shared.u64 t, %1; cvt.u32.u64 %0, t; }"
        : "=r"(s) : "l"(smem_dst));
    asm volatile("cp.async.ca.shared.global [%0], [%1], 16;" :: "r"(s), "l"(gsrc));
}
__device__ __forceinline__ void cp_commit() { asm volatile("cp.async.commit_group;"); }
template<int N> __device__ __forceinline__ void cp_wait_n() {
    asm volatile("cp.async.wait_group %0;" :: "n"(N));
}
__device__ __forceinline__ uint32_t smem_u32(const void* p) {
    uint32_t a;
    asm("{ .reg .u64 t; cvta.to.shared.u64 t, %1; cvt.u32.u64 %0, t; }" : "=r"(a) : "l"(p));
    return a;
}

// ======================= packed-operand double-buffered GEMM body =======================
// A plane word (r,k2)=(A[r][2k2],A[r][2k2+1]); B plane word (k2,n).
// A fragments via ldmatrix.x4; B fragments scalar LDS.
template<int BM, int BN>
__device__ __forceinline__ void gemm_packed_body(
    const uint32_t* __restrict__ Ah, const uint32_t* __restrict__ Al, int lda2,
    const uint32_t* __restrict__ Bh, const uint32_t* __restrict__ Bl, int ldb2,
    float* __restrict__ C, int ldc, int k2steps, int m0, int n0, uint32_t* smem)
{
    constexpr int BK2 = 16;
    constexpr int LDA2 = 20;
    constexpr int LDB2 = BN + 8;
    constexpr int ASZ = BM * LDA2, BSZ = BK2 * LDB2;
    constexpr int STG = 2 * ASZ + 2 * BSZ;
    constexpr int WM = BM / 2, WN = BN / 4;
    constexpr int MT = WM / 16, NT = WN / 8;

    const int tid = threadIdx.x, warp = tid >> 5, lane = tid & 31;
    const int wm = warp >> 2, wn = warp & 3;
    const int lr = lane >> 2, lc = lane & 3;
    const int lrow = lane & 15, lcol = (lane >> 4) << 2;   // ldmatrix lane mapping

    const uint32_t sA = smem_u32(smem);
    // lane-dependent, loop-invariant byte offset into A tile for ldmatrix
    const uint32_t a_lo = (uint32_t)(((wm * WM + lrow) * LDA2 + lcol) * 4);

    float acc[MT][NT][4];
    #pragma unroll
    for (int i = 0; i < MT; i++)
        #pragma unroll
        for (int j = 0; j < NT; j++)
            #pragma unroll
            for (int q = 0; q < 4; q++) acc[i][j][q] = 0.f;

    auto stage = [&](int k2_0, uint32_t* buf) {
        uint32_t* Aht = buf;
        uint32_t* Alt = buf + ASZ;
        uint32_t* Bht = buf + 2 * ASZ;
        uint32_t* Blt = buf + 2 * ASZ + BSZ;
        #pragma unroll
        for (int i = tid; i < BM * 4; i += 256) {
            int r = i >> 2, c4 = (i & 3) * 4;
            cp16(&Aht[r * LDA2 + c4], &Ah[(size_t)(m0 + r) * lda2 + k2_0 + c4]);
            cp16(&Alt[r * LDA2 + c4], &Al[(size_t)(m0 + r) * lda2 + k2_0 + c4]);
        }
        #pragma unroll
        for (int i = tid; i < BK2 * (BN / 4); i += 256) {
            int r = i / (BN / 4), c4 = (i % (BN / 4)) * 4;
            cp16(&Bht[r * LDB2 + c4], &Bh[(size_t)(k2_0 + r) * ldb2 + n0 + c4]);
            cp16(&Blt[r * LDB2 + c4], &Bl[(size_t)(k2_0 + r) * ldb2 + n0 + c4]);
        }
        cp_commit();
    };

    const int nit = k2steps / BK2;
    stage(0, smem);

    for (int it = 0; it < nit; it++) {
        uint32_t* buf = smem + (it & 1) * STG;
        const uint32_t abase = sA + (uint32_t)((it & 1) * STG) * 4;
        __syncthreads();
        if (it + 1 < nit) {
            stage((it + 1) * BK2, smem + ((it + 1) & 1) * STG);
            cp_wait_n<1>();
        } else {
            cp_wait_n<0>();
        }
        __syncthreads();

        uint32_t* Bht = buf + 2 * ASZ;
        uint32_t* Blt = buf + 2 * ASZ + BSZ;

        #pragma unroll
        for (int kk2 = 0; kk2 < BK2; kk2 += 8) {
            uint32_t ah[MT][4], al[MT][4];
            #pragma unroll
            for (int mt = 0; mt < MT; mt++) {
                uint32_t addr = abase + a_lo + (uint32_t)((mt * 16 * LDA2 + kk2) * 4);
                ldsm_x4(ah[mt], addr);
                ldsm_x4(al[mt], addr + ASZ * 4);
            }
            uint32_t bh[NT][2], bl[NT][2];
            #pragma unroll
            for (int nt = 0; nt < NT; nt++) {
                int cc = wn * WN + nt * 8 + lr;
                bh[nt][0] = Bht[(kk2 + lc) * LDB2 + cc];
                bh[nt][1] = Bht[(kk2 + lc + 4) * LDB2 + cc];
                bl[nt][0] = Blt[(kk2 + lc) * LDB2 + cc];
                bl[nt][1] = Blt[(kk2 + lc + 4) * LDB2 + cc];
            }
            #pragma unroll
            for (int mt = 0; mt < MT; mt++)
                #pragma unroll
                for (int nt = 0; nt < NT; nt++)
                    mma3(acc[mt][nt], ah[mt], al[mt], bh[nt], bl[nt]);
        }
    }

    #pragma unroll
    for (int mt = 0; mt < MT; mt++) {
        int r = m0 + wm * WM + mt * 16 + lr;
        #pragma unroll
        for (int nt = 0; nt < NT; nt++) {
            int c = n0 + wn * WN + nt * 8 + lc * 2;
            *(float2*)&C[(size_t)r * ldc + c]       = make_float2(acc[mt][nt][0], acc[mt][nt][1]);
            *(float2*)&C[(size_t)(r + 8) * ldc + c] = make_float2(acc[mt][nt][2], acc[mt][nt][3]);
        }
    }
}

// ======================= pack kernels =======================
__global__ __launch_bounds__(256)
void pack_pairs_kernel(const float* __restrict__ src, uint32_t* __restrict__ h,
                       uint32_t* __restrict__ l, int npairs) {
    int idx = blockIdx.x * 256 + threadIdx.x;
    if (idx >= npairs) return;
    float2 v = ((const float2*)src)[idx];
    uint32_t hw_, lw_;
    split_pair(v.x, v.y, hw_, lw_);
    h[idx] = hw_;
    l[idx] = lw_;
}

// x pack: word(b,c2,n) = (x[b][2c2][n], x[b][2c2+1][n])
__global__ __launch_bounds__(256)
void pack_x_kernel(const float* __restrict__ X, uint32_t* __restrict__ h,
                   uint32_t* __restrict__ l) {
    const int n = blockIdx.x * 256 + threadIdx.x;
    const int c2 = blockIdx.y, b = blockIdx.z;
    const float* r0 = X + ((size_t)b * DIM + 2 * c2) * HW;
    uint32_t hw_, lw_;
    split_pair(r0[n], r0[HW + n], hw_, lw_);
    const size_t o = ((size_t)b * 128 + c2) * HW + n;
    h[o] = hw_;
    l[o] = lw_;
}

// im2col repack -> packed planes (kv path)
__global__ __launch_bounds__(256)
void repack_kernel(const float* __restrict__ X, uint32_t* __restrict__ h,
                   uint32_t* __restrict__ l) {
    float* pl = (float*)dynsmem;   // [4096]
    const int ci = blockIdx.x, b = blockIdx.y, tid = threadIdx.x;
    const float* src = X + ((size_t)b * DIM + ci) * HW;
    #pragma unroll
    for (int i = tid; i < 1024; i += 256)
        ((float4*)pl)[i] = ((const float4*)src)[i];
    __syncthreads();
    const int oh = tid >> 4, ow = tid & 15;
    #pragma unroll
    for (int kh = 0; kh < 4; kh++)
        #pragma unroll
        for (int kw2 = 0; kw2 < 2; kw2++) {
            float v0 = pl[(oh * 4 + kh) * 64 + ow * 4 + 2 * kw2];
            float v1 = pl[(oh * 4 + kh) * 64 + ow * 4 + 2 * kw2 + 1];
            uint32_t hw_, lw_;
            split_pair(v0, v1, hw_, lw_);
            const size_t o = ((size_t)b * 2048 + ci * 8 + kh * 2 + kw2) * RHW + tid;
            h[o] = hw_;
            l[o] = lw_;
        }
}

// ======================= kv GEMM (split-K=4) =======================
__global__ __launch_bounds__(256, 3)
void kv_gemm_kernel(float* __restrict__ Part) {
    uint32_t* smem = (uint32_t*)dynsmem;
    const int mblk = blockIdx.y;
    const int b  = blockIdx.z & 7;
    const int ks = blockIdx.z >> 3;
    const int koff2 = ks * 512;
    const uint32_t* Ah = (mblk < 4) ? (g_wkh + koff2) : (g_wvh + koff2 - (size_t)256 * 2048);
    const uint32_t* Al = (mblk < 4) ? (g_wkl + koff2) : (g_wvl + koff2 - (size_t)256 * 2048);
    const uint32_t* Bh = g_xrh + ((size_t)b * 2048 + koff2) * RHW;
    const uint32_t* Bl = g_xrl + ((size_t)b * 2048 + koff2) * RHW;
    float* C = g_kvp + ((size_t)(ks * BATCH + b) * 512) * RHW;
    gemm_packed_body<64, 64>(Ah, Al, 2048, Bh, Bl, RHW,
                             C, RHW, 512, mblk * 64, blockIdx.x * 64, smem);
}

// reduce split-K partials AND emit packed K/V planes in attention fragment layouts.
__global__ __launch_bounds__(256)
void kv_reduce_pack_kernel(const float* __restrict__ P,
                           uint32_t* __restrict__ Kph, uint32_t* __restrict__ Kpl,
                           uint32_t* __restrict__ Vph, uint32_t* __restrict__ Vpl) {
    const size_t CH = (size_t)8 * 512 * RHW;   // floats per split chunk
    if (blockIdx.x < 256) {
        int t = blockIdx.x * 256 + threadIdx.x;          // 0..65535
        int j4 = (t & 63) * 4;
        int m2 = (t >> 6) & 127;
        int b  = t >> 13;
        const float* p0 = P + ((size_t)b * 512 + 2 * m2) * RHW + j4;
        const float* p1 = p0 + RHW;
        float4 r0 = *(const float4*)p0, r1 = *(const float4*)p1;
        #pragma unroll
        for (int ks = 1; ks < 4; ks++) {
            float4 a = *(const float4*)(p0 + ks * CH);
            float4 c = *(const float4*)(p1 + ks * CH);
            r0.x += a.x; r0.y += a.y; r0.z += a.z; r0.w += a.w;
            r1.x += c.x; r1.y += c.y; r1.z += c.z; r1.w += c.w;
        }
        const int h = m2 >> 4, d2 = m2 & 15;
        const size_t o = (((size_t)(b * 8 + h) * 16 + d2) * 256) + j4;
        uint32_t hw_, lw_;
        split_pair(r0.x, r1.x, hw_, lw_); Kph[o]     = hw_; Kpl[o]     = lw_;
        split_pair(r0.y, r1.y, hw_, lw_); Kph[o + 1] = hw_; Kpl[o + 1] = lw_;
        split_pair(r0.z, r1.z, hw_, lw_); Kph[o + 2] = hw_; Kpl[o + 2] = lw_;
        split_pair(r0.w, r1.w, hw_, lw_); Kph[o + 3] = hw_; Kpl[o + 3] = lw_;
    } else {
        int t = (blockIdx.x - 256) * 256 + threadIdx.x;  // 0..131071
        int j4 = (t & 63) * 4;
        int m  = (t >> 6) & 255;
        int b  = t >> 14;
        const float* p0 = P + ((size_t)b * 512 + 256 + m) * RHW + j4;
        float4 v = *(const float4*)p0;
        #pragma unroll
        for (int ks = 1; ks < 4; ks++) {
            float4 a = *(const float4*)(p0 + ks * CH);
            v.x += a.x; v.y += a.y; v.z += a.z; v.w += a.w;
        }
        const int h = m >> 5, d = m & 31;
        const size_t o = (((size_t)(b * 8 + h) * 32 + d) * 128) + (j4 >> 1);
        uint32_t hw_, lw_;
        split_pair(v.x, v.y, hw_, lw_); Vph[o]     = hw_; Vpl[o]     = lw_;
        split_pair(v.z, v.w, hw_, lw_); Vph[o + 1] = hw_; Vpl[o + 1] = lw_;
    }
}

// ======================= 1x1-conv GEMMs =======================
__global__ __launch_bounds__(256, 2)
void gemm_q_kernel(const uint32_t* __restrict__ Ah, const uint32_t* __restrict__ Al,
                   const uint32_t* __restrict__ Bh, const uint32_t* __restrict__ Bl,
                   float* __restrict__ Cg) {
    uint32_t* smem = (uint32_t*)dynsmem;
    const size_t bo = (size_t)blockIdx.z * 128 * HW;
    float* C = Cg + (size_t)blockIdx.z * DIM * HW;
    gemm_packed_body<128, 128>(Ah, Al, 128, Bh + bo, Bl + bo, HW,
                               C, HW, 128, blockIdx.y * 128, blockIdx.x * 128, smem);
}

// ======================= fused attention: pre-packed K/V, double-buffered, LDSM =======================
__global__ __launch_bounds__(256, 3)
void attn_kernel(const float* __restrict__ Q,
                 uint32_t* __restrict__ Oh, uint32_t* __restrict__ Ol) {
    uint32_t* su  = (uint32_t*)dynsmem;
    uint32_t* Qph = su;
    uint32_t* Qpl = Qph + 1280;
    uint32_t* kvbuf = Qpl + 1280;          // 2 x [Kh 1152 | Kl 1152 | Vh 1152 | Vl 1152]
    uint32_t* Pph = kvbuf + 2 * 4608;
    uint32_t* Ppl = Pph + 2304;
    float* lacc  = (float*)(Ppl + 2304);   // [4][64]
    float* li    = lacc + 256;             // [64]
    float* qraw  = li + 64;                // [32][65]
    float* po    = (float*)Pph;            // [64][36] final staging (aliases P)

    const int tid = threadIdx.x, warp = tid >> 5, lane = tid & 31;
    const int lr = lane >> 2, lc = lane & 3;
    const int wm = warp >> 2, wn = warp & 3;
    const int iw = (warp & 3) * 16;
    const int db = (warp >> 2) * 16;
    const int lrow = lane & 15, lcol = (lane >> 4) << 2;
    const int b = blockIdx.z, h = blockIdx.y, i0 = blockIdx.x * 64;

    const uint32_t qbase = smem_u32(Qph);
    const uint32_t pbase = smem_u32(Pph);
    const uint32_t q_lo = (uint32_t)(((wm * 32 + lrow) * 20 + lcol) * 4);
    const uint32_t p_lo = (uint32_t)(((iw + lrow) * 36 + lcol) * 4);

    const float* Qb = Q + ((size_t)b * DIM + h * HEAD_DIM) * HW + i0;
    const uint32_t* Kgh = g_kph + (size_t)(b * 8 + h) * 16 * 256;
    const uint32_t* Kgl = g_kpl + (size_t)(b * 8 + h) * 16 * 256;
    const uint32_t* Vgh = g_vph + (size_t)(b * 8 + h) * 32 * 128;
    const uint32_t* Vgl = g_vpl + (size_t)(b * 8 + h) * 32 * 128;

    auto stageKV = [&](int jt, int bufsel) {
        uint32_t* Kh = kvbuf + bufsel * 4608;
        uint32_t* Kl = Kh + 1152;
        uint32_t* Vh = Kl + 1152;
        uint32_t* Vl = Vh + 1152;
        const int j0 = jt * 64, jw0 = jt * 32;
        {
            int r = tid >> 4, c4 = (tid & 15) * 4;
            cp16(&Kh[r * 72 + c4], &Kgh[r * 256 + j0 + c4]);
            cp16(&Kl[r * 72 + c4], &Kgl[r * 256 + j0 + c4]);
        }
        {
            int r = tid >> 3, c4 = (tid & 7) * 4;
            cp16(&Vh[r * 36 + c4], &Vgh[r * 128 + jw0 + c4]);
            cp16(&Vl[r * 36 + c4], &Vgl[r * 128 + jw0 + c4]);
        }
        cp_commit();
    };

    stageKV(0, 0);

    for (int idx = tid; idx < 2048; idx += 256) {
        int d = idx >> 6, i = idx & 63;
        qraw[d * 65 + i] = Qb[(size_t)d * HW + i] * SCALE;
    }
    lacc[tid] = 0.f;
    __syncthreads();

    for (int idx = tid; idx < 1024; idx += 256) {
        int i = idx >> 4, d2 = idx & 15;
        uint32_t hw_, lw_;
        split_pair(qraw[(2 * d2) * 65 + i], qraw[(2 * d2 + 1) * 65 + i], hw_, lw_);
        Qph[i * 20 + d2] = hw_;
        Qpl[i * 20 + d2] = lw_;
    }

    float oacc[2][4];
    #pragma unroll
    for (int nt = 0; nt < 2; nt++)
        #pragma unroll
        for (int q = 0; q < 4; q++) oacc[nt][q] = 0.f;

    for (int jt = 0; jt < 4; jt++) {
        cp_wait_n<0>();
        __syncthreads();   // buf[jt&1] ready; PV of jt-1 done; Q pack visible (jt=0)

        if (jt < 3) stageKV(jt + 1, (jt + 1) & 1);   // overlaps with S/exp/PV

        uint32_t* Kpw = kvbuf + (jt & 1) * 4608;
        uint32_t* Klw = Kpw + 1152;
        uint32_t* Vpw = Klw + 1152;
        uint32_t* Vlw = Vpw + 1152;

        // ---- S = Q K^T : M=64(i), N=64(j), K=32(d). warp tile 32x16. Q via LDSM ----
        float sacc[2][2][4];
        #pragma unroll
        for (int mt = 0; mt < 2; mt++)
            #pragma unroll
            for (int nt = 0; nt < 2; nt++)
                #pragma unroll
                for (int q = 0; q < 4; q++) sacc[mt][nt][q] = 0.f;

        #pragma unroll
        for (int kk2 = 0; kk2 < 16; kk2 += 8) {
            uint32_t ah[2][4], al[2][4];
            #pragma unroll
            for (int mt = 0; mt < 2; mt++) {
                uint32_t addr = qbase + q_lo + (uint32_t)((mt * 16 * 20 + kk2) * 4);
                ldsm_x4(ah[mt], addr);
                ldsm_x4(al[mt], addr + 1280 * 4);
            }
            uint32_t bh[2][2], bl[2][2];
            #pragma unroll
            for (int nt = 0; nt < 2; nt++) {
                int jj = wn * 16 + nt * 8 + lr;
                bh[nt][0] = Kpw[(kk2 + lc) * 72 + jj];
                bh[nt][1] = Kpw[(kk2 + lc + 4) * 72 + jj];
                bl[nt][0] = Klw[(kk2 + lc) * 72 + jj];
                bl[nt][1] = Klw[(kk2 + lc + 4) * 72 + jj];
            }
            #pragma unroll
            for (int mt = 0; mt < 2; mt++)
                #pragma unroll
                for (int nt = 0; nt < 2; nt++)
                    mma3(sacc[mt][nt], ah[mt], al[mt], bh[nt], bl[nt]);
        }

        // ---- exp -> P (packed pairs along j), accumulate row sums ----
        #pragma unroll
        for (int mt = 0; mt < 2; mt++) {
            int r = wm * 32 + mt * 16 + lr;
            float rs0 = 0.f, rs1 = 0.f;
            #pragma unroll
            for (int nt = 0; nt < 2; nt++) {
                int j2 = wn * 8 + nt * 4 + lc;
                float e0 = __expf(sacc[mt][nt][0]);
                float e1 = __expf(sacc[mt][nt][1]);
                float e2 = __expf(sacc[mt][nt][2]);
                float e3 = __expf(sacc[mt][nt][3]);
                uint32_t hw_, lw_;
                split_pair(e0, e1, hw_, lw_);
                Pph[r * 36 + j2] = hw_;  Ppl[r * 36 + j2] = lw_;
                split_pair(e2, e3, hw_, lw_);
                Pph[(r + 8) * 36 + j2] = hw_;  Ppl[(r + 8) * 36 + j2] = lw_;
                rs0 += e0 + e1;
                rs1 += e2 + e3;
            }
            rs0 += __shfl_xor_sync(0xFFFFFFFFu, rs0, 1);
            rs0 += __shfl_xor_sync(0xFFFFFFFFu, rs0, 2);
            rs1 += __shfl_xor_sync(0xFFFFFFFFu, rs1, 1);
            rs1 += __shfl_xor_sync(0xFFFFFFFFu, rs1, 2);
            if (lc == 0) {
                lacc[wn * 64 + r]     += rs0;
                lacc[wn * 64 + r + 8] += rs1;
            }
        }
        __syncthreads();

        // ---- PV accumulate: O[iw..+16][db..+16] += P_tile * V_tile. P via LDSM ----
        #pragma unroll
        for (int kk2 = 0; kk2 < 32; kk2 += 8) {
            uint32_t ah[4], al[4];
            uint32_t addr = pbase + p_lo + (uint32_t)(kk2 * 4);
            ldsm_x4(ah, addr);
            ldsm_x4(al, addr + 2304 * 4);
            #pragma unroll
            for (int nt = 0; nt < 2; nt++) {
                int d = db + nt * 8 + lr;
                uint32_t bh[2], bl[2];
                bh[0] = Vpw[d * 36 + kk2 + lc];
                bh[1] = Vpw[d * 36 + kk2 + lc + 4];
                bl[0] = Vlw[d * 36 + kk2 + lc];
                bl[1] = Vlw[d * 36 + kk2 + lc + 4];
                mma3(oacc[nt], ah, al, bh, bl);
            }
        }
    }

    __syncthreads();
    if (tid < 64)
        li[tid] = 1.f / (lacc[tid] + lacc[64 + tid] + lacc[128 + tid] + lacc[192 + tid]);
    __syncthreads();

    #pragma unroll
    for (int nt = 0; nt < 2; nt++) {
        int r = iw + lr, c = db + nt * 8 + lc * 2;
        float inv0 = li[r], inv1 = li[r + 8];
        po[r * 36 + c]           = oacc[nt][0] * inv0;
        po[r * 36 + c + 1]       = oacc[nt][1] * inv0;
        po[(r + 8) * 36 + c]     = oacc[nt][2] * inv1;
        po[(r + 8) * 36 + c + 1] = oacc[nt][3] * inv1;
    }
    __syncthreads();

    // packed-plane store: word(b, h*16+d2, i0+i) = (O[2d2][i], O[2d2+1][i]); coalesced along i
    for (int idx = tid; idx < 1024; idx += 256) {
        int d2 = idx >> 6, i = idx & 63;
        uint32_t hw_, lw_;
        split_pair(po[i * 36 + 2 * d2], po[i * 36 + 2 * d2 + 1], hw_, lw_);
        const size_t o = ((size_t)b * 128 + h * 16 + d2) * HW + i0 + i;
        Oh[o] = hw_;
        Ol[o] = lw_;
    }
}

// ============================================================================
extern "C" void kernel_launch(void* const* d_in, const int* in_sizes, int n_in,
                              void* d_out, int out_size) {
    const float* x    = (const float*)d_in[0];
    const float* wq   = (const float*)d_in[1];
    const float* wk   = (const float*)d_in[2];
    const float* wv   = (const float*)d_in[3];
    const float* wout = (const float*)d_in[4];
    float* out = (float*)d_out;

    float *qp, *kvpp;
    uint32_t *wqh, *wql, *wkh, *wkl, *wvh, *wvl, *woh, *wol;
    uint32_t *xph, *xpl, *xrh, *xrl, *aoh, *aol, *kph, *kpl, *vph, *vpl;
    cudaGetSymbolAddress((void**)&qp,   g_q);
    cudaGetSymbolAddress((void**)&kvpp, g_kvp);
    cudaGetSymbolAddress((void**)&wqh,  g_wqh);  cudaGetSymbolAddress((void**)&wql, g_wql);
    cudaGetSymbolAddress((void**)&wkh,  g_wkh);  cudaGetSymbolAddress((void**)&wkl, g_wkl);
    cudaGetSymbolAddress((void**)&wvh,  g_wvh);  cudaGetSymbolAddress((void**)&wvl, g_wvl);
    cudaGetSymbolAddress((void**)&woh,  g_woh);  cudaGetSymbolAddress((void**)&wol, g_wol);
    cudaGetSymbolAddress((void**)&xph,  g_xph);  cudaGetSymbolAddress((void**)&xpl, g_xpl);
    cudaGetSymbolAddress((void**)&xrh,  g_xrh);  cudaGetSymbolAddress((void**)&xrl, g_xrl);
    cudaGetSymbolAddress((void**)&aoh,  g_aoh);  cudaGetSymbolAddress((void**)&aol, g_aol);
    cudaGetSymbolAddress((void**)&kph,  g_kph);  cudaGetSymbolAddress((void**)&kpl, g_kpl);
    cudaGetSymbolAddress((void**)&vph,  g_vph);  cudaGetSymbolAddress((void**)&vpl, g_vpl);

    const int g1_smem   = 2 * (2 * 128 * 20 + 2 * 16 * 136) * 4;   // 75776 B
    const int kv_smem   = 2 * (2 * 64 * 20 + 2 * 16 * 72) * 4;     // 38912 B
    const int attn_smem = (1280 * 2 + 2 * 4608 + 2 * 2304 + 256 + 64 + 2080) * 4; // 75136 B
    const int rp_smem   = 4096 * 4;

    cudaFuncSetAttribute(gemm_q_kernel,  cudaFuncAttributeMaxDynamicSharedMemorySize, g1_smem);
    cudaFuncSetAttribute(kv_gemm_kernel, cudaFuncAttributeMaxDynamicSharedMemorySize, kv_smem);
    cudaFuncSetAttribute(attn_kernel,    cudaFuncAttributeMaxDynamicSharedMemorySize, attn_smem);
    cudaFuncSetAttribute(repack_kernel,  cudaFuncAttributeMaxDynamicSharedMemorySize, rp_smem);

    // P0: one-time packs
    pack_pairs_kernel<<<128,  256>>>(wq,   wqh, wql, 256 * 128);
    pack_pairs_kernel<<<2048, 256>>>(wk,   wkh, wkl, 256 * 2048);
    pack_pairs_kernel<<<2048, 256>>>(wv,   wvh, wvl, 256 * 2048);
    pack_pairs_kernel<<<128,  256>>>(wout, woh, wol, 256 * 128);
    pack_x_kernel<<<dim3(HW / 256, 128, BATCH), 256>>>(x, xph, xpl);
    repack_kernel<<<dim3(DIM, BATCH), 256, rp_smem>>>(x, xrh, xrl);

    // K1: q = wq @ x
    gemm_q_kernel<<<dim3(HW / 128, 2, BATCH), 256, g1_smem>>>(wqh, wql, xph, xpl, qp);
    // K2: fused k & v GEMM (split-K=4) + reduce-and-pack into attention layouts
    kv_gemm_kernel<<<dim3(4, 8, BATCH * 4), 256, kv_smem>>>(kvpp);
    kv_reduce_pack_kernel<<<768, 256>>>(kvpp, kph, kpl, vph, vpl);
    // K3: fused attention (pre-packed K/V, double-buffered, LDSM) -> packed ao planes
    attn_kernel<<<dim3(HW / 64, HEADS, BATCH), 256, attn_smem>>>(qp, aoh, aol);
    // K4: out = wout @ ao
    gemm_q_kernel<<<dim3(HW / 128, 2, BATCH), 256, g1_smem>>>(woh, wol, aoh, aol, out);
}

// round 15
// speedup vs baseline: 2.9670x; 1.0138x over previous
#include <cuda_runtime.h>
#include <math.h>
#include <stdint.h>

#define BATCH 8
#define DIM 256
#define HEADS 8
#define HEAD_DIM 32
#define HW 4096
#define RHW 256
#define SCALE 0.17677669529663687f

// -------- scratch (static device globals; no cudaMalloc allowed) --------
__device__ float    g_kvp[4 * BATCH * 512 * RHW];  // 16 MB kv split-K partials
// packed bf16 hi/lo planes
__device__ uint32_t g_wqh[256 * 128],   g_wql[256 * 128];
__device__ uint32_t g_wkh[256 * 2048],  g_wkl[256 * 2048];
__device__ uint32_t g_wvh[256 * 2048],  g_wvl[256 * 2048];
__device__ uint32_t g_woh[256 * 128],   g_wol[256 * 128];
__device__ uint32_t g_xph[BATCH * 128 * HW],  g_xpl[BATCH * 128 * HW];    // x pairs along c
__device__ uint32_t g_xrh[BATCH * 2048 * RHW], g_xrl[BATCH * 2048 * RHW]; // im2col pairs along k
__device__ uint32_t g_qph[BATCH * HW * 128],  g_qpl[BATCH * HW * 128];    // q: [b][i][d2] pairs along d
__device__ uint32_t g_aoh[BATCH * 128 * HW],  g_aol[BATCH * 128 * HW];    // ao pairs along d
// pre-packed K/V in attention fragment layouts
__device__ uint32_t g_kph[BATCH * HEADS * 16 * 256], g_kpl[BATCH * HEADS * 16 * 256]; // [bh][d2][j]
__device__ uint32_t g_vph[BATCH * HEADS * 32 * 128], g_vpl[BATCH * HEADS * 32 * 128]; // [bh][d][j2]

extern __shared__ char dynsmem[];

// ======================= bf16 split/pack + MMA helpers =======================
__device__ __forceinline__ uint32_t pack_bf16(float v0, float v1) {
    uint32_t r;
    asm("cvt.rn.bf16x2.f32 %0, %1, %2;" : "=r"(r) : "f"(v1), "f"(v0));
    return r;
}
__device__ __forceinline__ void split_pair(float v0, float v1, uint32_t& h, uint32_t& l) {
    h = pack_bf16(v0, v1);
    float h0 = __uint_as_float(h << 16);
    float h1 = __uint_as_float(h & 0xFFFF0000u);
    l = pack_bf16(v0 - h0, v1 - h1);
}
__device__ __forceinline__ void mma_bf16(float c[4], const uint32_t a[4], const uint32_t b[2]) {
    asm volatile(
        "mma.sync.aligned.m16n8k16.row.col.f32.bf16.bf16.f32 "
        "{%0,%1,%2,%3},{%4,%5,%6,%7},{%8,%9},{%0,%1,%2,%3};"
        : "+f"(c[0]), "+f"(c[1]), "+f"(c[2]), "+f"(c[3])
        : "r"(a[0]), "r"(a[1]), "r"(a[2]), "r"(a[3]), "r"(b[0]), "r"(b[1]));
}
__device__ __forceinline__ void mma3(float c[4], const uint32_t ah[4], const uint32_t al[4],
                                     const uint32_t bh[2], const uint32_t bl[2]) {
    mma_bf16(c, ah, bh);
    mma_bf16(c, al, bh);
    mma_bf16(c, ah, bl);
}
__device__ __forceinline__ void ldsm_x4(uint32_t r[4], uint32_t saddr) {
    asm volatile("ldmatrix.sync.aligned.m8n8.x4.shared.b16 {%0,%1,%2,%3}, [%4];"
        : "=r"(r[0]), "=r"(r[1]), "=r"(r[2]), "=r"(r[3]) : "r"(saddr));
}

// ======================= cp.async helpers =======================
__device__ __forceinline__ void cp16(uint32_t* smem_dst, const uint32_t* gsrc) {
    uint32_t s;
    asm("{ .reg .u64 t; cvta.to.shared.u64 t, %1; cvt.u32.u64 %0, t; }"
        : "=r"(s) : "l"(smem_dst));
    asm volatile("cp.async.ca.shared.global [%0], [%1], 16;" :: "r"(s), "l"(gsrc));
}
__device__ __forceinline__ void cp_commit() { asm volatile("cp.async.commit_group;"); }
template<int N> __device__ __forceinline__ void cp_wait_n() {
    asm volatile("cp.async.wait_group %0;" :: "n"(N));
}
__device__ __forceinline__ uint32_t smem_u32(const void* p) {
    uint32_t a;
    asm("{ .reg .u64 t; cvta.to.shared.u64 t, %1; cvt.u32.u64 %0, t; }" : "=r"(a) : "l"(p));
    return a;
}

// ======================= packed-operand double-buffered GEMM body =======================
// A plane word (r,k2)=(A[r][2k2],A[r][2k2+1]); B plane word (k2,n).
// A fragments via ldmatrix.x4; B fragments scalar LDS.
// PACK=true: instead of fp32 C, emit packed bf16 planes POh/POl at
// word(prowbase + i_local)*128 + m0/2 + d2 (pairs along M).
template<int BM, int BN, bool PACK>
__device__ __forceinline__ void gemm_packed_body(
    const uint32_t* __restrict__ Ah, const uint32_t* __restrict__ Al, int lda2,
    const uint32_t* __restrict__ Bh, const uint32_t* __restrict__ Bl, int ldb2,
    float* __restrict__ C, int ldc, int k2steps, int m0, int n0, uint32_t* smem,
    uint32_t* __restrict__ POh, uint32_t* __restrict__ POl, size_t prowbase)
{
    constexpr int BK2 = 16;
    constexpr int LDA2 = 20;
    constexpr int LDB2 = BN + 8;
    constexpr int ASZ = BM * LDA2, BSZ = BK2 * LDB2;
    constexpr int STG = 2 * ASZ + 2 * BSZ;
    constexpr int WM = BM / 2, WN = BN / 4;
    constexpr int MT = WM / 16, NT = WN / 8;

    const int tid = threadIdx.x, warp = tid >> 5, lane = tid & 31;
    const int wm = warp >> 2, wn = warp & 3;
    const int lr = lane >> 2, lc = lane & 3;
    const int lrow = lane & 15, lcol = (lane >> 4) << 2;

    const uint32_t sA = smem_u32(smem);
    const uint32_t a_lo = (uint32_t)(((wm * WM + lrow) * LDA2 + lcol) * 4);

    float acc[MT][NT][4];
    #pragma unroll
    for (int i = 0; i < MT; i++)
        #pragma unroll
        for (int j = 0; j < NT; j++)
            #pragma unroll
            for (int q = 0; q < 4; q++) acc[i][j][q] = 0.f;

    auto stage = [&](int k2_0, uint32_t* buf) {
        uint32_t* Aht = buf;
        uint32_t* Alt = buf + ASZ;
        uint32_t* Bht = buf + 2 * ASZ;
        uint32_t* Blt = buf + 2 * ASZ + BSZ;
        #pragma unroll
        for (int i = tid; i < BM * 4; i += 256) {
            int r = i >> 2, c4 = (i & 3) * 4;
            cp16(&Aht[r * LDA2 + c4], &Ah[(size_t)(m0 + r) * lda2 + k2_0 + c4]);
            cp16(&Alt[r * LDA2 + c4], &Al[(size_t)(m0 + r) * lda2 + k2_0 + c4]);
        }
        #pragma unroll
        for (int i = tid; i < BK2 * (BN / 4); i += 256) {
            int r = i / (BN / 4), c4 = (i % (BN / 4)) * 4;
            cp16(&Bht[r * LDB2 + c4], &Bh[(size_t)(k2_0 + r) * ldb2 + n0 + c4]);
            cp16(&Blt[r * LDB2 + c4], &Bl[(size_t)(k2_0 + r) * ldb2 + n0 + c4]);
        }
        cp_commit();
    };

    const int nit = k2steps / BK2;
    stage(0, smem);

    for (int it = 0; it < nit; it++) {
        uint32_t* buf = smem + (it & 1) * STG;
        const uint32_t abase = sA + (uint32_t)((it & 1) * STG) * 4;
        __syncthreads();
        if (it + 1 < nit) {
            stage((it + 1) * BK2, smem + ((it + 1) & 1) * STG);
            cp_wait_n<1>();
        } else {
            cp_wait_n<0>();
        }
        __syncthreads();

        uint32_t* Bht = buf + 2 * ASZ;
        uint32_t* Blt = buf + 2 * ASZ + BSZ;

        #pragma unroll
        for (int kk2 = 0; kk2 < BK2; kk2 += 8) {
            uint32_t ah[MT][4], al[MT][4];
            #pragma unroll
            for (int mt = 0; mt < MT; mt++) {
                uint32_t addr = abase + a_lo + (uint32_t)((mt * 16 * LDA2 + kk2) * 4);
                ldsm_x4(ah[mt], addr);
                ldsm_x4(al[mt], addr + ASZ * 4);
            }
            uint32_t bh[NT][2], bl[NT][2];
            #pragma unroll
            for (int nt = 0; nt < NT; nt++) {
                int cc = wn * WN + nt * 8 + lr;
                bh[nt][0] = Bht[(kk2 + lc) * LDB2 + cc];
                bh[nt][1] = Bht[(kk2 + lc + 4) * LDB2 + cc];
                bl[nt][0] = Blt[(kk2 + lc) * LDB2 + cc];
                bl[nt][1] = Blt[(kk2 + lc + 4) * LDB2 + cc];
            }
            #pragma unroll
            for (int mt = 0; mt < MT; mt++)
                #pragma unroll
                for (int nt = 0; nt < NT; nt++)
                    mma3(acc[mt][nt], ah[mt], al[mt], bh[nt], bl[nt]);
        }
    }

    if (PACK) {
        // epilogue: stage fp32 tile in smem, pack pairs along M, coalesced global write
        float* Tf = (float*)smem;            // [BM][133] reuse pipeline buffers
        __syncthreads();
        #pragma unroll
        for (int mt = 0; mt < MT; mt++) {
            int r = wm * WM + mt * 16 + lr;
            #pragma unroll
            for (int nt = 0; nt < NT; nt++) {
                int c = wn * WN + nt * 8 + lc * 2;
                Tf[r * 133 + c]           = acc[mt][nt][0];
                Tf[r * 133 + c + 1]       = acc[mt][nt][1];
                Tf[(r + 8) * 133 + c]     = acc[mt][nt][2];
                Tf[(r + 8) * 133 + c + 1] = acc[mt][nt][3];
            }
        }
        __syncthreads();
        const int d2off = m0 >> 1;
        for (int idx = tid; idx < (BM / 2) * BN; idx += 256) {
            int d2 = idx & (BM / 2 - 1), i = idx / (BM / 2);
            uint32_t hw_, lw_;
            split_pair(Tf[(2 * d2) * 133 + i], Tf[(2 * d2 + 1) * 133 + i], hw_, lw_);
            const size_t o = (prowbase + i) * 128 + d2off + d2;
            POh[o] = hw_;
            POl[o] = lw_;
        }
    } else {
        #pragma unroll
        for (int mt = 0; mt < MT; mt++) {
            int r = m0 + wm * WM + mt * 16 + lr;
            #pragma unroll
            for (int nt = 0; nt < NT; nt++) {
                int c = n0 + wn * WN + nt * 8 + lc * 2;
                *(float2*)&C[(size_t)r * ldc + c]       = make_float2(acc[mt][nt][0], acc[mt][nt][1]);
                *(float2*)&C[(size_t)(r + 8) * ldc + c] = make_float2(acc[mt][nt][2], acc[mt][nt][3]);
            }
        }
    }
}

// ======================= pack kernels =======================
__global__ __launch_bounds__(256)
void pack_pairs_kernel(const float* __restrict__ src, uint32_t* __restrict__ h,
                       uint32_t* __restrict__ l, int npairs, float scale) {
    int idx = blockIdx.x * 256 + threadIdx.x;
    if (idx >= npairs) return;
    float2 v = ((const float2*)src)[idx];
    uint32_t hw_, lw_;
    split_pair(v.x * scale, v.y * scale, hw_, lw_);
    h[idx] = hw_;
    l[idx] = lw_;
}

// x pack: word(b,c2,n) = (x[b][2c2][n], x[b][2c2+1][n])
__global__ __launch_bounds__(256)
void pack_x_kernel(const float* __restrict__ X, uint32_t* __restrict__ h,
                   uint32_t* __restrict__ l) {
    const int n = blockIdx.x * 256 + threadIdx.x;
    const int c2 = blockIdx.y, b = blockIdx.z;
    const float* r0 = X + ((size_t)b * DIM + 2 * c2) * HW;
    uint32_t hw_, lw_;
    split_pair(r0[n], r0[HW + n], hw_, lw_);
    const size_t o = ((size_t)b * 128 + c2) * HW + n;
    h[o] = hw_;
    l[o] = lw_;
}

// im2col repack -> packed planes (kv path)
__global__ __launch_bounds__(256)
void repack_kernel(const float* __restrict__ X, uint32_t* __restrict__ h,
                   uint32_t* __restrict__ l) {
    float* pl = (float*)dynsmem;   // [4096]
    const int ci = blockIdx.x, b = blockIdx.y, tid = threadIdx.x;
    const float* src = X + ((size_t)b * DIM + ci) * HW;
    #pragma unroll
    for (int i = tid; i < 1024; i += 256)
        ((float4*)pl)[i] = ((const float4*)src)[i];
    __syncthreads();
    const int oh = tid >> 4, ow = tid & 15;
    #pragma unroll
    for (int kh = 0; kh < 4; kh++)
        #pragma unroll
        for (int kw2 = 0; kw2 < 2; kw2++) {
            float v0 = pl[(oh * 4 + kh) * 64 + ow * 4 + 2 * kw2];
            float v1 = pl[(oh * 4 + kh) * 64 + ow * 4 + 2 * kw2 + 1];
            uint32_t hw_, lw_;
            split_pair(v0, v1, hw_, lw_);
            const size_t o = ((size_t)b * 2048 + ci * 8 + kh * 2 + kw2) * RHW + tid;
            h[o] = hw_;
            l[o] = lw_;
        }
}

// ======================= kv GEMM (split-K=4) =======================
__global__ __launch_bounds__(256, 3)
void kv_gemm_kernel(float* __restrict__ Part) {
    uint32_t* smem = (uint32_t*)dynsmem;
    const int mblk = blockIdx.y;
    const int b  = blockIdx.z & 7;
    const int ks = blockIdx.z >> 3;
    const int koff2 = ks * 512;
    const uint32_t* Ah = (mblk < 4) ? (g_wkh + koff2) : (g_wvh + koff2 - (size_t)256 * 2048);
    const uint32_t* Al = (mblk < 4) ? (g_wkl + koff2) : (g_wvl + koff2 - (size_t)256 * 2048);
    const uint32_t* Bh = g_xrh + ((size_t)b * 2048 + koff2) * RHW;
    const uint32_t* Bl = g_xrl + ((size_t)b * 2048 + koff2) * RHW;
    float* C = g_kvp + ((size_t)(ks * BATCH + b) * 512) * RHW;
    gemm_packed_body<64, 64, false>(Ah, Al, 2048, Bh, Bl, RHW,
                                    C, RHW, 512, mblk * 64, blockIdx.x * 64, smem,
                                    nullptr, nullptr, 0);
}

// reduce split-K partials AND emit packed K/V planes in attention fragment layouts.
__global__ __launch_bounds__(256)
void kv_reduce_pack_kernel(const float* __restrict__ P,
                           uint32_t* __restrict__ Kph, uint32_t* __restrict__ Kpl,
                           uint32_t* __restrict__ Vph, uint32_t* __restrict__ Vpl) {
    const size_t CH = (size_t)8 * 512 * RHW;   // floats per split chunk
    if (blockIdx.x < 256) {
        int t = blockIdx.x * 256 + threadIdx.x;          // 0..65535
        int j4 = (t & 63) * 4;
        int m2 = (t >> 6) & 127;
        int b  = t >> 13;
        const float* p0 = P + ((size_t)b * 512 + 2 * m2) * RHW + j4;
        const float* p1 = p0 + RHW;
        float4 r0 = *(const float4*)p0, r1 = *(const float4*)p1;
        #pragma unroll
        for (int ks = 1; ks < 4; ks++) {
            float4 a = *(const float4*)(p0 + ks * CH);
            float4 c = *(const float4*)(p1 + ks * CH);
            r0.x += a.x; r0.y += a.y; r0.z += a.z; r0.w += a.w;
            r1.x += c.x; r1.y += c.y; r1.z += c.z; r1.w += c.w;
        }
        const int h = m2 >> 4, d2 = m2 & 15;
        const size_t o = (((size_t)(b * 8 + h) * 16 + d2) * 256) + j4;
        uint32_t hw_, lw_;
        split_pair(r0.x, r1.x, hw_, lw_); Kph[o]     = hw_; Kpl[o]     = lw_;
        split_pair(r0.y, r1.y, hw_, lw_); Kph[o + 1] = hw_; Kpl[o + 1] = lw_;
        split_pair(r0.z, r1.z, hw_, lw_); Kph[o + 2] = hw_; Kpl[o + 2] = lw_;
        split_pair(r0.w, r1.w, hw_, lw_); Kph[o + 3] = hw_; Kpl[o + 3] = lw_;
    } else {
        int t = (blockIdx.x - 256) * 256 + threadIdx.x;  // 0..131071
        int j4 = (t & 63) * 4;
        int m  = (t >> 6) & 255;
        int b  = t >> 14;
        const float* p0 = P + ((size_t)b * 512 + 256 + m) * RHW + j4;
        float4 v = *(const float4*)p0;
        #pragma unroll
        for (int ks = 1; ks < 4; ks++) {
            float4 a = *(const float4*)(p0 + ks * CH);
            v.x += a.x; v.y += a.y; v.z += a.z; v.w += a.w;
        }
        const int h = m >> 5, d = m & 31;
        const size_t o = (((size_t)(b * 8 + h) * 32 + d) * 128) + (j4 >> 1);
        uint32_t hw_, lw_;
        split_pair(v.x, v.y, hw_, lw_); Vph[o]     = hw_; Vpl[o]     = lw_;
        split_pair(v.z, v.w, hw_, lw_); Vph[o + 1] = hw_; Vpl[o + 1] = lw_;
    }
}

// ======================= 1x1-conv GEMMs =======================
// K1: q = (wq*SCALE) @ x -> packed planes [b][i][d2]
__global__ __launch_bounds__(256, 2)
void gemm_q_kernel(const uint32_t* __restrict__ Ah, const uint32_t* __restrict__ Al,
                   const uint32_t* __restrict__ Bh, const uint32_t* __restrict__ Bl,
                   uint32_t* __restrict__ Qh, uint32_t* __restrict__ Ql) {
    uint32_t* smem = (uint32_t*)dynsmem;
    const size_t bo = (size_t)blockIdx.z * 128 * HW;
    const int n0 = blockIdx.x * 128;
    gemm_packed_body<128, 128, true>(Ah, Al, 128, Bh + bo, Bl + bo, HW,
                                     nullptr, 0, 128, blockIdx.y * 128, n0, smem,
                                     Qh, Ql, (size_t)blockIdx.z * HW + n0);
}

// K4: out = wout @ ao -> fp32
__global__ __launch_bounds__(256, 2)
void gemm_o_kernel(const uint32_t* __restrict__ Ah, const uint32_t* __restrict__ Al,
                   const uint32_t* __restrict__ Bh, const uint32_t* __restrict__ Bl,
                   float* __restrict__ Cg) {
    uint32_t* smem = (uint32_t*)dynsmem;
    const size_t bo = (size_t)blockIdx.z * 128 * HW;
    float* C = Cg + (size_t)blockIdx.z * DIM * HW;
    gemm_packed_body<128, 128, false>(Ah, Al, 128, Bh + bo, Bl + bo, HW,
                                      C, HW, 128, blockIdx.y * 128, blockIdx.x * 128, smem,
                                      nullptr, nullptr, 0);
}

// ======================= fused attention: all operands pre-packed =======================
__global__ __launch_bounds__(256, 3)
void attn_kernel(uint32_t* __restrict__ Oh, uint32_t* __restrict__ Ol) {
    uint32_t* su  = (uint32_t*)dynsmem;
    uint32_t* Qph = su;                    // [64][20]
    uint32_t* Qpl = Qph + 1280;
    uint32_t* kvbuf = Qpl + 1280;          // 2 x [Kh 1152 | Kl 1152 | Vh 1152 | Vl 1152]
    uint32_t* Pph = kvbuf + 2 * 4608;
    uint32_t* Ppl = Pph + 2304;
    float* lacc  = (float*)(Ppl + 2304);   // [4][64]
    float* li    = lacc + 256;             // [64]
    float* po    = (float*)Pph;            // [64][36] final staging (aliases P)

    const int tid = threadIdx.x, warp = tid >> 5, lane = tid & 31;
    const int lr = lane >> 2, lc = lane & 3;
    const int wm = warp >> 2, wn = warp & 3;
    const int iw = (warp & 3) * 16;
    const int db = (warp >> 2) * 16;
    const int lrow = lane & 15, lcol = (lane >> 4) << 2;
    const int b = blockIdx.z, h = blockIdx.y, i0 = blockIdx.x * 64;

    const uint32_t qbase = smem_u32(Qph);
    const uint32_t pbase = smem_u32(Pph);
    const uint32_t q_lo = (uint32_t)(((wm * 32 + lrow) * 20 + lcol) * 4);
    const uint32_t p_lo = (uint32_t)(((iw + lrow) * 36 + lcol) * 4);

    const uint32_t* Qgh = g_qph + ((size_t)b * HW + i0) * 128 + h * 16;
    const uint32_t* Qgl = g_qpl + ((size_t)b * HW + i0) * 128 + h * 16;
    const uint32_t* Kgh = g_kph + (size_t)(b * 8 + h) * 16 * 256;
    const uint32_t* Kgl = g_kpl + (size_t)(b * 8 + h) * 16 * 256;
    const uint32_t* Vgh = g_vph + (size_t)(b * 8 + h) * 32 * 128;
    const uint32_t* Vgl = g_vpl + (size_t)(b * 8 + h) * 32 * 128;

    auto stageKV = [&](int jt, int bufsel) {
        uint32_t* Kh = kvbuf + bufsel * 4608;
        uint32_t* Kl = Kh + 1152;
        uint32_t* Vh = Kl + 1152;
        uint32_t* Vl = Vh + 1152;
        const int j0 = jt * 64, jw0 = jt * 32;
        {
            int r = tid >> 4, c4 = (tid & 15) * 4;
            cp16(&Kh[r * 72 + c4], &Kgh[r * 256 + j0 + c4]);
            cp16(&Kl[r * 72 + c4], &Kgl[r * 256 + j0 + c4]);
        }
        {
            int r = tid >> 3, c4 = (tid & 7) * 4;
            cp16(&Vh[r * 36 + c4], &Vgh[r * 128 + jw0 + c4]);
            cp16(&Vl[r * 36 + c4], &Vgl[r * 128 + jw0 + c4]);
        }
        cp_commit();
    };

    // stage Q (pre-packed) + first KV tile
    {
        int r = tid >> 2, c4 = (tid & 3) * 4;   // 64 rows x 4 chunks
        cp16(&Qph[r * 20 + c4], &Qgh[(size_t)r * 128 + c4]);
        cp16(&Qpl[r * 20 + c4], &Qgl[(size_t)r * 128 + c4]);
    }
    stageKV(0, 0);
    lacc[tid] = 0.f;

    float oacc[2][4];
    #pragma unroll
    for (int nt = 0; nt < 2; nt++)
        #pragma unroll
        for (int q = 0; q < 4; q++) oacc[nt][q] = 0.f;

    for (int jt = 0; jt < 4; jt++) {
        cp_wait_n<0>();
        __syncthreads();   // buf[jt&1] + Q ready; PV of jt-1 done

        if (jt < 3) stageKV(jt + 1, (jt + 1) & 1);   // overlaps with S/exp/PV

        uint32_t* Kpw = kvbuf + (jt & 1) * 4608;
        uint32_t* Klw = Kpw + 1152;
        uint32_t* Vpw = Klw + 1152;
        uint32_t* Vlw = Vpw + 1152;

        // ---- S = Q K^T : M=64(i), N=64(j), K=32(d). warp tile 32x16. Q via LDSM ----
        float sacc[2][2][4];
        #pragma unroll
        for (int mt = 0; mt < 2; mt++)
            #pragma unroll
            for (int nt = 0; nt < 2; nt++)
                #pragma unroll
                for (int q = 0; q < 4; q++) sacc[mt][nt][q] = 0.f;

        #pragma unroll
        for (int kk2 = 0; kk2 < 16; kk2 += 8) {
            uint32_t ah[2][4], al[2][4];
            #pragma unroll
            for (int mt = 0; mt < 2; mt++) {
                uint32_t addr = qbase + q_lo + (uint32_t)((mt * 16 * 20 + kk2) * 4);
                ldsm_x4(ah[mt], addr);
                ldsm_x4(al[mt], addr + 1280 * 4);
            }
            uint32_t bh[2][2], bl[2][2];
            #pragma unroll
            for (int nt = 0; nt < 2; nt++) {
                int jj = wn * 16 + nt * 8 + lr;
                bh[nt][0] = Kpw[(kk2 + lc) * 72 + jj];
                bh[nt][1] = Kpw[(kk2 + lc + 4) * 72 + jj];
                bl[nt][0] = Klw[(kk2 + lc) * 72 + jj];
                bl[nt][1] = Klw[(kk2 + lc + 4) * 72 + jj];
            }
            #pragma unroll
            for (int mt = 0; mt < 2; mt++)
                #pragma unroll
                for (int nt = 0; nt < 2; nt++)
                    mma3(sacc[mt][nt], ah[mt], al[mt], bh[nt], bl[nt]);
        }

        // ---- exp -> P (packed pairs along j), accumulate row sums ----
        #pragma unroll
        for (int mt = 0; mt < 2; mt++) {
            int r = wm * 32 + mt * 16 + lr;
            float rs0 = 0.f, rs1 = 0.f;
            #pragma unroll
            for (int nt = 0; nt < 2; nt++) {
                int j2 = wn * 8 + nt * 4 + lc;
                float e0 = __expf(sacc[mt][nt][0]);
                float e1 = __expf(sacc[mt][nt][1]);
                float e2 = __expf(sacc[mt][nt][2]);
                float e3 = __expf(sacc[mt][nt][3]);
                uint32_t hw_, lw_;
                split_pair(e0, e1, hw_, lw_);
                Pph[r * 36 + j2] = hw_;  Ppl[r * 36 + j2] = lw_;
                split_pair(e2, e3, hw_, lw_);
                Pph[(r + 8) * 36 + j2] = hw_;  Ppl[(r + 8) * 36 + j2] = lw_;
                rs0 += e0 + e1;
                rs1 += e2 + e3;
            }
            rs0 += __shfl_xor_sync(0xFFFFFFFFu, rs0, 1);
            rs0 += __shfl_xor_sync(0xFFFFFFFFu, rs0, 2);
            rs1 += __shfl_xor_sync(0xFFFFFFFFu, rs1, 1);
            rs1 += __shfl_xor_sync(0xFFFFFFFFu, rs1, 2);
            if (lc == 0) {
                lacc[wn * 64 + r]     += rs0;
                lacc[wn * 64 + r + 8] += rs1;
            }
        }
        __syncthreads();

        // ---- PV accumulate: O[iw..+16][db..+16] += P_tile * V_tile. P via LDSM ----
        #pragma unroll
        for (int kk2 = 0; kk2 < 32; kk2 += 8) {
            uint32_t ah[4], al[4];
            uint32_t addr = pbase + p_lo + (uint32_t)(kk2 * 4);
            ldsm_x4(ah, addr);
            ldsm_x4(al, addr + 2304 * 4);
            #pragma unroll
            for (int nt = 0; nt < 2; nt++) {
                int d = db + nt * 8 + lr;
                uint32_t bh[2], bl[2];
                bh[0] = Vpw[d * 36 + kk2 + lc];
                bh[1] = Vpw[d * 36 + kk2 + lc + 4];
                bl[0] = Vlw[d * 36 + kk2 + lc];
                bl[1] = Vlw[d * 36 + kk2 + lc + 4];
                mma3(oacc[nt], ah, al, bh, bl);
            }
        }
    }

    __syncthreads();
    if (tid < 64)
        li[tid] = 1.f / (lacc[tid] + lacc[64 + tid] + lacc[128 + tid] + lacc[192 + tid]);
    __syncthreads();

    #pragma unroll
    for (int nt = 0; nt < 2; nt++) {
        int r = iw + lr, c = db + nt * 8 + lc * 2;
        float inv0 = li[r], inv1 = li[r + 8];
        po[r * 36 + c]           = oacc[nt][0] * inv0;
        po[r * 36 + c + 1]       = oacc[nt][1] * inv0;
        po[(r + 8) * 36 + c]     = oacc[nt][2] * inv1;
        po[(r + 8) * 36 + c + 1] = oacc[nt][3] * inv1;
    }
    __syncthreads();

    // packed-plane store: word(b, h*16+d2, i0+i) = (O[2d2][i], O[2d2+1][i]); coalesced along i
    for (int idx = tid; idx < 1024; idx += 256) {
        int d2 = idx >> 6, i = idx & 63;
        uint32_t hw_, lw_;
        split_pair(po[i * 36 + 2 * d2], po[i * 36 + 2 * d2 + 1], hw_, lw_);
        const size_t o = ((size_t)b * 128 + h * 16 + d2) * HW + i0 + i;
        Oh[o] = hw_;
        Ol[o] = lw_;
    }
}

// ============================================================================
extern "C" void kernel_launch(void* const* d_in, const int* in_sizes, int n_in,
                              void* d_out, int out_size) {
    const float* x    = (const float*)d_in[0];
    const float* wq   = (const float*)d_in[1];
    const float* wk   = (const float*)d_in[2];
    const float* wv   = (const float*)d_in[3];
    const float* wout = (const float*)d_in[4];
    float* out = (float*)d_out;

    float *kvpp;
    uint32_t *wqh, *wql, *wkh, *wkl, *wvh, *wvl, *woh, *wol;
    uint32_t *xph, *xpl, *xrh, *xrl, *qph, *qpl, *aoh, *aol, *kph, *kpl, *vph, *vpl;
    cudaGetSymbolAddress((void**)&kvpp, g_kvp);
    cudaGetSymbolAddress((void**)&wqh,  g_wqh);  cudaGetSymbolAddress((void**)&wql, g_wql);
    cudaGetSymbolAddress((void**)&wkh,  g_wkh);  cudaGetSymbolAddress((void**)&wkl, g_wkl);
    cudaGetSymbolAddress((void**)&wvh,  g_wvh);  cudaGetSymbolAddress((void**)&wvl, g_wvl);
    cudaGetSymbolAddress((void**)&woh,  g_woh);  cudaGetSymbolAddress((void**)&wol, g_wol);
    cudaGetSymbolAddress((void**)&xph,  g_xph);  cudaGetSymbolAddress((void**)&xpl, g_xpl);
    cudaGetSymbolAddress((void**)&xrh,  g_xrh);  cudaGetSymbolAddress((void**)&xrl, g_xrl);
    cudaGetSymbolAddress((void**)&qph,  g_qph);  cudaGetSymbolAddress((void**)&qpl, g_qpl);
    cudaGetSymbolAddress((void**)&aoh,  g_aoh);  cudaGetSymbolAddress((void**)&aol, g_aol);
    cudaGetSymbolAddress((void**)&kph,  g_kph);  cudaGetSymbolAddress((void**)&kpl, g_kpl);
    cudaGetSymbolAddress((void**)&vph,  g_vph);  cudaGetSymbolAddress((void**)&vpl, g_vpl);

    const int g1_smem   = 2 * (2 * 128 * 20 + 2 * 16 * 136) * 4;   // 75776 B (>= 128*133*4 pack tile)
    const int kv_smem   = 2 * (2 * 64 * 20 + 2 * 16 * 72) * 4;     // 38912 B
    const int attn_smem = (1280 * 2 + 2 * 4608 + 2 * 2304 + 256 + 64) * 4; // 66816 B
    const int rp_smem   = 4096 * 4;

    cudaFuncSetAttribute(gemm_q_kernel,  cudaFuncAttributeMaxDynamicSharedMemorySize, g1_smem);
    cudaFuncSetAttribute(gemm_o_kernel,  cudaFuncAttributeMaxDynamicSharedMemorySize, g1_smem);
    cudaFuncSetAttribute(kv_gemm_kernel, cudaFuncAttributeMaxDynamicSharedMemorySize, kv_smem);
    cudaFuncSetAttribute(attn_kernel,    cudaFuncAttributeMaxDynamicSharedMemorySize, attn_smem);
    cudaFuncSetAttribute(repack_kernel,  cudaFuncAttributeMaxDynamicSharedMemorySize, rp_smem);

    // P0: one-time packs (SCALE folded into wq)
    pack_pairs_kernel<<<128,  256>>>(wq,   wqh, wql, 256 * 128, SCALE);
    pack_pairs_kernel<<<2048, 256>>>(wk,   wkh, wkl, 256 * 2048, 1.0f);
    pack_pairs_kernel<<<2048, 256>>>(wv,   wvh, wvl, 256 * 2048, 1.0f);
    pack_pairs_kernel<<<128,  256>>>(wout, woh, wol, 256 * 128, 1.0f);
    pack_x_kernel<<<dim3(HW / 256, 128, BATCH), 256>>>(x, xph, xpl);
    repack_kernel<<<dim3(DIM, BATCH), 256, rp_smem>>>(x, xrh, xrl);

    // K1: q = (wq*SCALE) @ x -> packed planes
    gemm_q_kernel<<<dim3(HW / 128, 2, BATCH), 256, g1_smem>>>(wqh, wql, xph, xpl, qph, qpl);
    // K2: fused k & v GEMM (split-K=4) + reduce-and-pack into attention layouts
    kv_gemm_kernel<<<dim3(4, 8, BATCH * 4), 256, kv_smem>>>(kvpp);
    kv_reduce_pack_kernel<<<768, 256>>>(kvpp, kph, kpl, vph, vpl);
    // K3: fused attention (all operands pre-packed) -> packed ao planes
    attn_kernel<<<dim3(HW / 64, HEADS, BATCH), 256, attn_smem>>>(aoh, aol);
    // K4: out = wout @ ao
    gemm_o_kernel<<<dim3(HW / 128, 2, BATCH), 256, g1_smem>>>(woh, wol, aoh, aol, out);
}

// round 16
// speedup vs baseline: 3.0831x; 1.0391x over previous
#include <cuda_runtime.h>
#include <math.h>
#include <stdint.h>

#define BATCH 8
#define DIM 256
#define HEADS 8
#define HEAD_DIM 32
#define HW 4096
#define RHW 256
#define SCALE 0.17677669529663687f

// -------- scratch (static device globals; no cudaMalloc allowed) --------
__device__ float    g_kvp[4 * BATCH * 512 * RHW];  // 16 MB kv split-K partials
// packed bf16 hi/lo planes
__device__ uint32_t g_wqh[256 * 128],   g_wql[256 * 128];
__device__ uint32_t g_wkh[256 * 2048],  g_wkl[256 * 2048];
__device__ uint32_t g_wvh[256 * 2048],  g_wvl[256 * 2048];
__device__ uint32_t g_woh[256 * 128],   g_wol[256 * 128];
__device__ uint32_t g_xph[BATCH * 128 * HW],  g_xpl[BATCH * 128 * HW];    // x pairs along c
__device__ uint32_t g_xrh[BATCH * 2048 * RHW], g_xrl[BATCH * 2048 * RHW]; // im2col pairs along k
__device__ uint32_t g_qph[BATCH * HW * 128],  g_qpl[BATCH * HW * 128];    // q: [b][i][d2]
__device__ uint32_t g_aoh[BATCH * 128 * HW],  g_aol[BATCH * 128 * HW];    // ao pairs along d
// pre-packed K/V in attention fragment layouts
__device__ uint32_t g_kph[BATCH * HEADS * 16 * 256], g_kpl[BATCH * HEADS * 16 * 256]; // [bh][d2][j]
__device__ uint32_t g_vph[BATCH * HEADS * 32 * 128], g_vpl[BATCH * HEADS * 32 * 128]; // [bh][d][j2]

extern __shared__ char dynsmem[];

// ======================= bf16 split/pack + MMA helpers =======================
__device__ __forceinline__ uint32_t pack_bf16(float v0, float v1) {
    uint32_t r;
    asm("cvt.rn.bf16x2.f32 %0, %1, %2;" : "=r"(r) : "f"(v1), "f"(v0));
    return r;
}
__device__ __forceinline__ void split_pair(float v0, float v1, uint32_t& h, uint32_t& l) {
    h = pack_bf16(v0, v1);
    float h0 = __uint_as_float(h << 16);
    float h1 = __uint_as_float(h & 0xFFFF0000u);
    l = pack_bf16(v0 - h0, v1 - h1);
}
__device__ __forceinline__ void mma_bf16(float c[4], const uint32_t a[4], const uint32_t b[2]) {
    asm volatile(
        "mma.sync.aligned.m16n8k16.row.col.f32.bf16.bf16.f32 "
        "{%0,%1,%2,%3},{%4,%5,%6,%7},{%8,%9},{%0,%1,%2,%3};"
        : "+f"(c[0]), "+f"(c[1]), "+f"(c[2]), "+f"(c[3])
        : "r"(a[0]), "r"(a[1]), "r"(a[2]), "r"(a[3]), "r"(b[0]), "r"(b[1]));
}
__device__ __forceinline__ void mma3(float c[4], const uint32_t ah[4], const uint32_t al[4],
                                     const uint32_t bh[2], const uint32_t bl[2]) {
    mma_bf16(c, ah, bh);
    mma_bf16(c, al, bh);
    mma_bf16(c, ah, bl);
}
__device__ __forceinline__ void ldsm_x4(uint32_t r[4], uint32_t saddr) {
    asm volatile("ldmatrix.sync.aligned.m8n8.x4.shared.b16 {%0,%1,%2,%3}, [%4];"
        : "=r"(r[0]), "=r"(r[1]), "=r"(r[2]), "=r"(r[3]) : "r"(saddr));
}

// ======================= cp.async helpers =======================
__device__ __forceinline__ void cp16(uint32_t* smem_dst, const uint32_t* gsrc) {
    uint32_t s;
    asm("{ .reg .u64 t; cvta.to.shared.u64 t, %1; cvt.u32.u64 %0, t; }"
        : "=r"(s) : "l"(smem_dst));
    asm volatile("cp.async.ca.shared.global [%0], [%1], 16;" :: "r"(s), "l"(gsrc));
}
__device__ __forceinline__ void cp_commit() { asm volatile("cp.async.commit_group;"); }
template<int N> __device__ __forceinline__ void cp_wait_n() {
    asm volatile("cp.async.wait_group %0;" :: "n"(N));
}
__device__ __forceinline__ uint32_t smem_u32(const void* p) {
    uint32_t a;
    asm("{ .reg .u64 t; cvta.to.shared.u64 t, %1; cvt.u32.u64 %0, t; }" : "=r"(a) : "l"(p));
    return a;
}

// ======================= packed-operand double-buffered GEMM body =======================
template<int BM, int BN, bool PACK>
__device__ __forceinline__ void gemm_packed_body(
    const uint32_t* __restrict__ Ah, const uint32_t* __restrict__ Al, int lda2,
    const uint32_t* __restrict__ Bh, const uint32_t* __restrict__ Bl, int ldb2,
    float* __restrict__ C, int ldc, int k2steps, int m0, int n0, uint32_t* smem,
    uint32_t* __restrict__ POh, uint32_t* __restrict__ POl, size_t prowbase)
{
    constexpr int BK2 = 16;
    constexpr int LDA2 = 20;
    constexpr int LDB2 = BN + 8;
    constexpr int ASZ = BM * LDA2, BSZ = BK2 * LDB2;
    constexpr int STG = 2 * ASZ + 2 * BSZ;
    constexpr int WM = BM / 2, WN = BN / 4;
    constexpr int MT = WM / 16, NT = WN / 8;

    const int tid = threadIdx.x, warp = tid >> 5, lane = tid & 31;
    const int wm = warp >> 2, wn = warp & 3;
    const int lr = lane >> 2, lc = lane & 3;
    const int lrow = lane & 15, lcol = (lane >> 4) << 2;

    const uint32_t sA = smem_u32(smem);
    const uint32_t a_lo = (uint32_t)(((wm * WM + lrow) * LDA2 + lcol) * 4);

    float acc[MT][NT][4];
    #pragma unroll
    for (int i = 0; i < MT; i++)
        #pragma unroll
        for (int j = 0; j < NT; j++)
            #pragma unroll
            for (int q = 0; q < 4; q++) acc[i][j][q] = 0.f;

    auto stage = [&](int k2_0, uint32_t* buf) {
        uint32_t* Aht = buf;
        uint32_t* Alt = buf + ASZ;
        uint32_t* Bht = buf + 2 * ASZ;
        uint32_t* Blt = buf + 2 * ASZ + BSZ;
        #pragma unroll
        for (int i = tid; i < BM * 4; i += 256) {
            int r = i >> 2, c4 = (i & 3) * 4;
            cp16(&Aht[r * LDA2 + c4], &Ah[(size_t)(m0 + r) * lda2 + k2_0 + c4]);
            cp16(&Alt[r * LDA2 + c4], &Al[(size_t)(m0 + r) * lda2 + k2_0 + c4]);
        }
        #pragma unroll
        for (int i = tid; i < BK2 * (BN / 4); i += 256) {
            int r = i / (BN / 4), c4 = (i % (BN / 4)) * 4;
            cp16(&Bht[r * LDB2 + c4], &Bh[(size_t)(k2_0 + r) * ldb2 + n0 + c4]);
            cp16(&Blt[r * LDB2 + c4], &Bl[(size_t)(k2_0 + r) * ldb2 + n0 + c4]);
        }
        cp_commit();
    };

    const int nit = k2steps / BK2;
    stage(0, smem);

    for (int it = 0; it < nit; it++) {
        uint32_t* buf = smem + (it & 1) * STG;
        const uint32_t abase = sA + (uint32_t)((it & 1) * STG) * 4;
        __syncthreads();
        if (it + 1 < nit) {
            stage((it + 1) * BK2, smem + ((it + 1) & 1) * STG);
            cp_wait_n<1>();
        } else {
            cp_wait_n<0>();
        }
        __syncthreads();

        uint32_t* Bht = buf + 2 * ASZ;
        uint32_t* Blt = buf + 2 * ASZ + BSZ;

        #pragma unroll
        for (int kk2 = 0; kk2 < BK2; kk2 += 8) {
            uint32_t ah[MT][4], al[MT][4];
            #pragma unroll
            for (int mt = 0; mt < MT; mt++) {
                uint32_t addr = abase + a_lo + (uint32_t)((mt * 16 * LDA2 + kk2) * 4);
                ldsm_x4(ah[mt], addr);
                ldsm_x4(al[mt], addr + ASZ * 4);
            }
            uint32_t bh[NT][2], bl[NT][2];
            #pragma unroll
            for (int nt = 0; nt < NT; nt++) {
                int cc = wn * WN + nt * 8 + lr;
                bh[nt][0] = Bht[(kk2 + lc) * LDB2 + cc];
                bh[nt][1] = Bht[(kk2 + lc + 4) * LDB2 + cc];
                bl[nt][0] = Blt[(kk2 + lc) * LDB2 + cc];
                bl[nt][1] = Blt[(kk2 + lc + 4) * LDB2 + cc];
            }
            #pragma unroll
            for (int mt = 0; mt < MT; mt++)
                #pragma unroll
                for (int nt = 0; nt < NT; nt++)
                    mma3(acc[mt][nt], ah[mt], al[mt], bh[nt], bl[nt]);
        }
    }

    if (PACK) {
        float* Tf = (float*)smem;            // [BM][133] reuse pipeline buffers
        __syncthreads();
        #pragma unroll
        for (int mt = 0; mt < MT; mt++) {
            int r = wm * WM + mt * 16 + lr;
            #pragma unroll
            for (int nt = 0; nt < NT; nt++) {
                int c = wn * WN + nt * 8 + lc * 2;
                Tf[r * 133 + c]           = acc[mt][nt][0];
                Tf[r * 133 + c + 1]       = acc[mt][nt][1];
                Tf[(r + 8) * 133 + c]     = acc[mt][nt][2];
                Tf[(r + 8) * 133 + c + 1] = acc[mt][nt][3];
            }
        }
        __syncthreads();
        const int d2off = m0 >> 1;
        for (int idx = tid; idx < (BM / 2) * BN; idx += 256) {
            int d2 = idx & (BM / 2 - 1), i = idx / (BM / 2);
            uint32_t hw_, lw_;
            split_pair(Tf[(2 * d2) * 133 + i], Tf[(2 * d2 + 1) * 133 + i], hw_, lw_);
            const size_t o = (prowbase + i) * 128 + d2off + d2;
            POh[o] = hw_;
            POl[o] = lw_;
        }
    } else {
        #pragma unroll
        for (int mt = 0; mt < MT; mt++) {
            int r = m0 + wm * WM + mt * 16 + lr;
            #pragma unroll
            for (int nt = 0; nt < NT; nt++) {
                int c = n0 + wn * WN + nt * 8 + lc * 2;
                *(float2*)&C[(size_t)r * ldc + c]       = make_float2(acc[mt][nt][0], acc[mt][nt][1]);
                *(float2*)&C[(size_t)(r + 8) * ldc + c] = make_float2(acc[mt][nt][2], acc[mt][nt][3]);
            }
        }
    }
}

// ======================= pack kernels =======================
__global__ __launch_bounds__(256)
void pack_pairs_kernel(const float* __restrict__ src, uint32_t* __restrict__ h,
                       uint32_t* __restrict__ l, int npairs, float scale) {
    int idx = blockIdx.x * 256 + threadIdx.x;
    if (idx >= npairs) return;
    float2 v = ((const float2*)src)[idx];
    uint32_t hw_, lw_;
    split_pair(v.x * scale, v.y * scale, hw_, lw_);
    h[idx] = hw_;
    l[idx] = lw_;
}

__global__ __launch_bounds__(256)
void pack_x_kernel(const float* __restrict__ X, uint32_t* __restrict__ h,
                   uint32_t* __restrict__ l) {
    const int n = blockIdx.x * 256 + threadIdx.x;
    const int c2 = blockIdx.y, b = blockIdx.z;
    const float* r0 = X + ((size_t)b * DIM + 2 * c2) * HW;
    uint32_t hw_, lw_;
    split_pair(r0[n], r0[HW + n], hw_, lw_);
    const size_t o = ((size_t)b * 128 + c2) * HW + n;
    h[o] = hw_;
    l[o] = lw_;
}

__global__ __launch_bounds__(256)
void repack_kernel(const float* __restrict__ X, uint32_t* __restrict__ h,
                   uint32_t* __restrict__ l) {
    float* pl = (float*)dynsmem;   // [4096]
    const int ci = blockIdx.x, b = blockIdx.y, tid = threadIdx.x;
    const float* src = X + ((size_t)b * DIM + ci) * HW;
    #pragma unroll
    for (int i = tid; i < 1024; i += 256)
        ((float4*)pl)[i] = ((const float4*)src)[i];
    __syncthreads();
    const int oh = tid >> 4, ow = tid & 15;
    #pragma unroll
    for (int kh = 0; kh < 4; kh++)
        #pragma unroll
        for (int kw2 = 0; kw2 < 2; kw2++) {
            float v0 = pl[(oh * 4 + kh) * 64 + ow * 4 + 2 * kw2];
            float v1 = pl[(oh * 4 + kh) * 64 + ow * 4 + 2 * kw2 + 1];
            uint32_t hw_, lw_;
            split_pair(v0, v1, hw_, lw_);
            const size_t o = ((size_t)b * 2048 + ci * 8 + kh * 2 + kw2) * RHW + tid;
            h[o] = hw_;
            l[o] = lw_;
        }
}

// ======================= kv GEMM (split-K=4, 128x64 tiles) =======================
__global__ __launch_bounds__(256, 2)
void kv_gemm_kernel(float* __restrict__ Part) {
    uint32_t* smem = (uint32_t*)dynsmem;
    const int mblk = blockIdx.y;              // 0..3, 128 stacked rows each
    const int b  = blockIdx.z & 7;
    const int ks = blockIdx.z >> 3;
    const int koff2 = ks * 512;
    const uint32_t* Ah = (mblk < 2) ? (g_wkh + koff2) : (g_wvh + koff2 - (size_t)256 * 2048);
    const uint32_t* Al = (mblk < 2) ? (g_wkl + koff2) : (g_wvl + koff2 - (size_t)256 * 2048);
    const uint32_t* Bh = g_xrh + ((size_t)b * 2048 + koff2) * RHW;
    const uint32_t* Bl = g_xrl + ((size_t)b * 2048 + koff2) * RHW;
    float* C = g_kvp + ((size_t)(ks * BATCH + b) * 512) * RHW;
    gemm_packed_body<128, 64, false>(Ah, Al, 2048, Bh, Bl, RHW,
                                     C, RHW, 512, mblk * 128, blockIdx.x * 64, smem,
                                     nullptr, nullptr, 0);
}

// reduce split-K partials AND emit packed K/V planes in attention fragment layouts.
__global__ __launch_bounds__(256)
void kv_reduce_pack_kernel(const float* __restrict__ P,
                           uint32_t* __restrict__ Kph, uint32_t* __restrict__ Kpl,
                           uint32_t* __restrict__ Vph, uint32_t* __restrict__ Vpl) {
    const size_t CH = (size_t)8 * 512 * RHW;
    if (blockIdx.x < 256) {
        int t = blockIdx.x * 256 + threadIdx.x;
        int j4 = (t & 63) * 4;
        int m2 = (t >> 6) & 127;
        int b  = t >> 13;
        const float* p0 = P + ((size_t)b * 512 + 2 * m2) * RHW + j4;
        const float* p1 = p0 + RHW;
        float4 r0 = *(const float4*)p0, r1 = *(const float4*)p1;
        #pragma unroll
        for (int ks = 1; ks < 4; ks++) {
            float4 a = *(const float4*)(p0 + ks * CH);
            float4 c = *(const float4*)(p1 + ks * CH);
            r0.x += a.x; r0.y += a.y; r0.z += a.z; r0.w += a.w;
            r1.x += c.x; r1.y += c.y; r1.z += c.z; r1.w += c.w;
        }
        const int h = m2 >> 4, d2 = m2 & 15;
        const size_t o = (((size_t)(b * 8 + h) * 16 + d2) * 256) + j4;
        uint32_t hw_, lw_;
        split_pair(r0.x, r1.x, hw_, lw_); Kph[o]     = hw_; Kpl[o]     = lw_;
        split_pair(r0.y, r1.y, hw_, lw_); Kph[o + 1] = hw_; Kpl[o + 1] = lw_;
        split_pair(r0.z, r1.z, hw_, lw_); Kph[o + 2] = hw_; Kpl[o + 2] = lw_;
        split_pair(r0.w, r1.w, hw_, lw_); Kph[o + 3] = hw_; Kpl[o + 3] = lw_;
    } else {
        int t = (blockIdx.x - 256) * 256 + threadIdx.x;
        int j4 = (t & 63) * 4;
        int m  = (t >> 6) & 255;
        int b  = t >> 14;
        const float* p0 = P + ((size_t)b * 512 + 256 + m) * RHW + j4;
        float4 v = *(const float4*)p0;
        #pragma unroll
        for (int ks = 1; ks < 4; ks++) {
            float4 a = *(const float4*)(p0 + ks * CH);
            v.x += a.x; v.y += a.y; v.z += a.z; v.w += a.w;
        }
        const int h = m >> 5, d = m & 31;
        const size_t o = (((size_t)(b * 8 + h) * 32 + d) * 128) + (j4 >> 1);
        uint32_t hw_, lw_;
        split_pair(v.x, v.y, hw_, lw_); Vph[o]     = hw_; Vpl[o]     = lw_;
        split_pair(v.z, v.w, hw_, lw_); Vph[o + 1] = hw_; Vpl[o + 1] = lw_;
    }
}

// ======================= 1x1-conv GEMMs =======================
__global__ __launch_bounds__(256, 2)
void gemm_q_kernel(const uint32_t* __restrict__ Ah, const uint32_t* __restrict__ Al,
                   const uint32_t* __restrict__ Bh, const uint32_t* __restrict__ Bl,
                   uint32_t* __restrict__ Qh, uint32_t* __restrict__ Ql) {
    uint32_t* smem = (uint32_t*)dynsmem;
    const size_t bo = (size_t)blockIdx.z * 128 * HW;
    const int n0 = blockIdx.x * 128;
    gemm_packed_body<128, 128, true>(Ah, Al, 128, Bh + bo, Bl + bo, HW,
                                     nullptr, 0, 128, blockIdx.y * 128, n0, smem,
                                     Qh, Ql, (size_t)blockIdx.z * HW + n0);
}

__global__ __launch_bounds__(256, 2)
void gemm_o_kernel(const uint32_t* __restrict__ Ah, const uint32_t* __restrict__ Al,
                   const uint32_t* __restrict__ Bh, const uint32_t* __restrict__ Bl,
                   float* __restrict__ Cg) {
    uint32_t* smem = (uint32_t*)dynsmem;
    const size_t bo = (size_t)blockIdx.z * 128 * HW;
    float* C = Cg + (size_t)blockIdx.z * DIM * HW;
    gemm_packed_body<128, 128, false>(Ah, Al, 128, Bh + bo, Bl + bo, HW,
                                      C, HW, 128, blockIdx.y * 128, blockIdx.x * 128, smem,
                                      nullptr, nullptr, 0);
}

// ======================= fused attention: i-tile 128, all operands pre-packed =======================
// smem words: Qph/Qpl 2x2560 | kvbuf 2x4608 | Pph/Ppl 2x4608 | lacc 256 | li 128
__global__ __launch_bounds__(256, 2)
void attn_kernel(uint32_t* __restrict__ Oh, uint32_t* __restrict__ Ol) {
    uint32_t* su  = (uint32_t*)dynsmem;
    uint32_t* Qph = su;                    // [128][20]
    uint32_t* Qpl = Qph + 2560;
    uint32_t* kvbuf = Qpl + 2560;          // 2 x [Kh 1152 | Kl 1152 | Vh 1152 | Vl 1152]
    uint32_t* Pph = kvbuf + 2 * 4608;      // [128][36]
    uint32_t* Ppl = Pph + 4608;
    float* lacc  = (float*)(Ppl + 4608);   // [2][128]
    float* li    = lacc + 256;             // [128]
    float* po    = (float*)Pph;            // [128][36] final staging (aliases P)

    const int tid = threadIdx.x, warp = tid >> 5, lane = tid & 31;
    const int lr = lane >> 2, lc = lane & 3;
    const int wm = warp >> 1, wn = warp & 1;   // S phase: 4(m) x 2(n)
    const int iw = warp * 16;                   // PV phase: 8 i-strips
    const int lrow = lane & 15, lcol = (lane >> 4) << 2;
    const int b = blockIdx.z, h = blockIdx.y, i0 = blockIdx.x * 128;

    const uint32_t qbase = smem_u32(Qph);
    const uint32_t pbase = smem_u32(Pph);
    const uint32_t q_lo = (uint32_t)(((wm * 32 + lrow) * 20 + lcol) * 4);
    const uint32_t p_lo = (uint32_t)(((iw + lrow) * 36 + lcol) * 4);

    const uint32_t* Qgh = g_qph + ((size_t)b * HW + i0) * 128 + h * 16;
    const uint32_t* Qgl = g_qpl + ((size_t)b * HW + i0) * 128 + h * 16;
    const uint32_t* Kgh = g_kph + (size_t)(b * 8 + h) * 16 * 256;
    const uint32_t* Kgl = g_kpl + (size_t)(b * 8 + h) * 16 * 256;
    const uint32_t* Vgh = g_vph + (size_t)(b * 8 + h) * 32 * 128;
    const uint32_t* Vgl = g_vpl + (size_t)(b * 8 + h) * 32 * 128;

    auto stageKV = [&](int jt, int bufsel) {
        uint32_t* Kh = kvbuf + bufsel * 4608;
        uint32_t* Kl = Kh + 1152;
        uint32_t* Vh = Kl + 1152;
        uint32_t* Vl = Vh + 1152;
        const int j0 = jt * 64, jw0 = jt * 32;
        {
            int r = tid >> 4, c4 = (tid & 15) * 4;
            cp16(&Kh[r * 72 + c4], &Kgh[r * 256 + j0 + c4]);
            cp16(&Kl[r * 72 + c4], &Kgl[r * 256 + j0 + c4]);
        }
        {
            int r = tid >> 3, c4 = (tid & 7) * 4;
            cp16(&Vh[r * 36 + c4], &Vgh[r * 128 + jw0 + c4]);
            cp16(&Vl[r * 36 + c4], &Vgl[r * 128 + jw0 + c4]);
        }
        cp_commit();
    };

    // stage Q (pre-packed, 128 rows x 4 chunks per plane) + first KV tile
    #pragma unroll
    for (int idx = tid; idx < 512; idx += 256) {
        int r = idx >> 2, c4 = (idx & 3) * 4;
        cp16(&Qph[r * 20 + c4], &Qgh[(size_t)r * 128 + c4]);
        cp16(&Qpl[r * 20 + c4], &Qgl[(size_t)r * 128 + c4]);
    }
    stageKV(0, 0);
    lacc[tid] = 0.f;

    float oacc[4][4];
    #pragma unroll
    for (int nt = 0; nt < 4; nt++)
        #pragma unroll
        for (int q = 0; q < 4; q++) oacc[nt][q] = 0.f;

    for (int jt = 0; jt < 4; jt++) {
        cp_wait_n<0>();
        __syncthreads();   // buf[jt&1] + Q ready; PV of jt-1 done

        if (jt < 3) stageKV(jt + 1, (jt + 1) & 1);

        uint32_t* Kpw = kvbuf + (jt & 1) * 4608;
        uint32_t* Klw = Kpw + 1152;
        uint32_t* Vpw = Klw + 1152;
        uint32_t* Vlw = Vpw + 1152;

        // ---- S = Q K^T : M=128(i), N=64(j), K=32(d). warp tile 32x32 ----
        float sacc[2][4][4];
        #pragma unroll
        for (int mt = 0; mt < 2; mt++)
            #pragma unroll
            for (int nt = 0; nt < 4; nt++)
                #pragma unroll
                for (int q = 0; q < 4; q++) sacc[mt][nt][q] = 0.f;

        #pragma unroll
        for (int kk2 = 0; kk2 < 16; kk2 += 8) {
            uint32_t ah[2][4], al[2][4];
            #pragma unroll
            for (int mt = 0; mt < 2; mt++) {
                uint32_t addr = qbase + q_lo + (uint32_t)((mt * 16 * 20 + kk2) * 4);
                ldsm_x4(ah[mt], addr);
                ldsm_x4(al[mt], addr + 2560 * 4);
            }
            uint32_t bh[4][2], bl[4][2];
            #pragma unroll
            for (int nt = 0; nt < 4; nt++) {
                int jj = wn * 32 + nt * 8 + lr;
                bh[nt][0] = Kpw[(kk2 + lc) * 72 + jj];
                bh[nt][1] = Kpw[(kk2 + lc + 4) * 72 + jj];
                bl[nt][0] = Klw[(kk2 + lc) * 72 + jj];
                bl[nt][1] = Klw[(kk2 + lc + 4) * 72 + jj];
            }
            #pragma unroll
            for (int mt = 0; mt < 2; mt++)
                #pragma unroll
                for (int nt = 0; nt < 4; nt++)
                    mma3(sacc[mt][nt], ah[mt], al[mt], bh[nt], bl[nt]);
        }

        // ---- exp -> P (packed pairs along j), accumulate row sums ----
        #pragma unroll
        for (int mt = 0; mt < 2; mt++) {
            int r = wm * 32 + mt * 16 + lr;
            float rs0 = 0.f, rs1 = 0.f;
            #pragma unroll
            for (int nt = 0; nt < 4; nt++) {
                int j2 = wn * 16 + nt * 4 + lc;
                float e0 = __expf(sacc[mt][nt][0]);
                float e1 = __expf(sacc[mt][nt][1]);
                float e2 = __expf(sacc[mt][nt][2]);
                float e3 = __expf(sacc[mt][nt][3]);
                uint32_t hw_, lw_;
                split_pair(e0, e1, hw_, lw_);
                Pph[r * 36 + j2] = hw_;  Ppl[r * 36 + j2] = lw_;
                split_pair(e2, e3, hw_, lw_);
                Pph[(r + 8) * 36 + j2] = hw_;  Ppl[(r + 8) * 36 + j2] = lw_;
                rs0 += e0 + e1;
                rs1 += e2 + e3;
            }
            rs0 += __shfl_xor_sync(0xFFFFFFFFu, rs0, 1);
            rs0 += __shfl_xor_sync(0xFFFFFFFFu, rs0, 2);
            rs1 += __shfl_xor_sync(0xFFFFFFFFu, rs1, 1);
            rs1 += __shfl_xor_sync(0xFFFFFFFFu, rs1, 2);
            if (lc == 0) {
                lacc[wn * 128 + r]     += rs0;
                lacc[wn * 128 + r + 8] += rs1;
            }
        }
        __syncthreads();

        // ---- PV accumulate: O[iw..+16][0..32] += P_tile * V_tile. P via LDSM ----
        #pragma unroll
        for (int kk2 = 0; kk2 < 32; kk2 += 8) {
            uint32_t ah[4], al[4];
            uint32_t addr = pbase + p_lo + (uint32_t)(kk2 * 4);
            ldsm_x4(ah, addr);
            ldsm_x4(al, addr + 4608 * 4);
            #pragma unroll
            for (int nt = 0; nt < 4; nt++) {
                int d = nt * 8 + lr;
                uint32_t bh[2], bl[2];
                bh[0] = Vpw[d * 36 + kk2 + lc];
                bh[1] = Vpw[d * 36 + kk2 + lc + 4];
                bl[0] = Vlw[d * 36 + kk2 + lc];
                bl[1] = Vlw[d * 36 + kk2 + lc + 4];
                mma3(oacc[nt], ah, al, bh, bl);
            }
        }
    }

    __syncthreads();
    if (tid < 128)
        li[tid] = 1.f / (lacc[tid] + lacc[128 + tid]);
    __syncthreads();

    #pragma unroll
    for (int nt = 0; nt < 4; nt++) {
        int r = iw + lr, c = nt * 8 + lc * 2;
        float inv0 = li[r], inv1 = li[r + 8];
        po[r * 36 + c]           = oacc[nt][0] * inv0;
        po[r * 36 + c + 1]       = oacc[nt][1] * inv0;
        po[(r + 8) * 36 + c]     = oacc[nt][2] * inv1;
        po[(r + 8) * 36 + c + 1] = oacc[nt][3] * inv1;
    }
    __syncthreads();

    // packed-plane store: word(b, h*16+d2, i0+i) = (O[2d2][i], O[2d2+1][i]); coalesced along i
    for (int idx = tid; idx < 2048; idx += 256) {
        int d2 = idx >> 7, i = idx & 127;
        uint32_t hw_, lw_;
        split_pair(po[i * 36 + 2 * d2], po[i * 36 + 2 * d2 + 1], hw_, lw_);
        const size_t o = ((size_t)b * 128 + h * 16 + d2) * HW + i0 + i;
        Oh[o] = hw_;
        Ol[o] = lw_;
    }
}

// ============================================================================
extern "C" void kernel_launch(void* const* d_in, const int* in_sizes, int n_in,
                              void* d_out, int out_size) {
    const float* x    = (const float*)d_in[0];
    const float* wq   = (const float*)d_in[1];
    const float* wk   = (const float*)d_in[2];
    const float* wv   = (const float*)d_in[3];
    const float* wout = (const float*)d_in[4];
    float* out = (float*)d_out;

    float *kvpp;
    uint32_t *wqh, *wql, *wkh, *wkl, *wvh, *wvl, *woh, *wol;
    uint32_t *xph, *xpl, *xrh, *xrl, *qph, *qpl, *aoh, *aol, *kph, *kpl, *vph, *vpl;
    cudaGetSymbolAddress((void**)&kvpp, g_kvp);
    cudaGetSymbolAddress((void**)&wqh,  g_wqh);  cudaGetSymbolAddress((void**)&wql, g_wql);
    cudaGetSymbolAddress((void**)&wkh,  g_wkh);  cudaGetSymbolAddress((void**)&wkl, g_wkl);
    cudaGetSymbolAddress((void**)&wvh,  g_wvh);  cudaGetSymbolAddress((void**)&wvl, g_wvl);
    cudaGetSymbolAddress((void**)&woh,  g_woh);  cudaGetSymbolAddress((void**)&wol, g_wol);
    cudaGetSymbolAddress((void**)&xph,  g_xph);  cudaGetSymbolAddress((void**)&xpl, g_xpl);
    cudaGetSymbolAddress((void**)&xrh,  g_xrh);  cudaGetSymbolAddress((void**)&xrl, g_xrl);
    cudaGetSymbolAddress((void**)&qph,  g_qph);  cudaGetSymbolAddress((void**)&qpl, g_qpl);
    cudaGetSymbolAddress((void**)&aoh,  g_aoh);  cudaGetSymbolAddress((void**)&aol, g_aol);
    cudaGetSymbolAddress((void**)&kph,  g_kph);  cudaGetSymbolAddress((void**)&kpl, g_kpl);
    cudaGetSymbolAddress((void**)&vph,  g_vph);  cudaGetSymbolAddress((void**)&vpl, g_vpl);

    const int g1_smem   = 2 * (2 * 128 * 20 + 2 * 16 * 136) * 4;   // 75776 B
    const int kv_smem   = 2 * (2 * 128 * 20 + 2 * 16 * 72) * 4;    // 59392 B
    const int attn_smem = (2 * 2560 + 2 * 4608 + 2 * 4608 + 256 + 128) * 4; // 95744 B
    const int rp_smem   = 4096 * 4;

    cudaFuncSetAttribute(gemm_q_kernel,  cudaFuncAttributeMaxDynamicSharedMemorySize, g1_smem);
    cudaFuncSetAttribute(gemm_o_kernel,  cudaFuncAttributeMaxDynamicSharedMemorySize, g1_smem);
    cudaFuncSetAttribute(kv_gemm_kernel, cudaFuncAttributeMaxDynamicSharedMemorySize, kv_smem);
    cudaFuncSetAttribute(attn_kernel,    cudaFuncAttributeMaxDynamicSharedMemorySize, attn_smem);
    cudaFuncSetAttribute(repack_kernel,  cudaFuncAttributeMaxDynamicSharedMemorySize, rp_smem);

    // P0: one-time packs (SCALE folded into wq)
    pack_pairs_kernel<<<128,  256>>>(wq,   wqh, wql, 256 * 128, SCALE);
    pack_pairs_kernel<<<2048, 256>>>(wk,   wkh, wkl, 256 * 2048, 1.0f);
    pack_pairs_kernel<<<2048, 256>>>(wv,   wvh, wvl, 256 * 2048, 1.0f);
    pack_pairs_kernel<<<128,  256>>>(wout, woh, wol, 256 * 128, 1.0f);
    pack_x_kernel<<<dim3(HW / 256, 128, BATCH), 256>>>(x, xph, xpl);
    repack_kernel<<<dim3(DIM, BATCH), 256, rp_smem>>>(x, xrh, xrl);

    // K1: q = (wq*SCALE) @ x -> packed planes
    gemm_q_kernel<<<dim3(HW / 128, 2, BATCH), 256, g1_smem>>>(wqh, wql, xph, xpl, qph, qpl);
    // K2: fused k & v GEMM (split-K=4, 128x64 tiles) + reduce-and-pack
    kv_gemm_kernel<<<dim3(4, 4, BATCH * 4), 256, kv_smem>>>(kvpp);
    kv_reduce_pack_kernel<<<768, 256>>>(kvpp, kph, kpl, vph, vpl);
    // K3: fused attention (i-tile 128) -> packed ao planes
    attn_kernel<<<dim3(HW / 128, HEADS, BATCH), 256, attn_smem>>>(aoh, aol);
    // K4: out = wout @ ao
    gemm_o_kernel<<<dim3(HW / 128, 2, BATCH), 256, g1_smem>>>(woh, wol, aoh, aol, out);
}

// round 17
// speedup vs baseline: 3.0991x; 1.0052x over previous
#include <cuda_runtime.h>
#include <math.h>
#include <stdint.h>

#define BATCH 8
#define DIM 256
#define HEADS 8
#define HEAD_DIM 32
#define HW 4096
#define RHW 256
#define SCALE 0.17677669529663687f

// -------- scratch (static device globals; no cudaMalloc allowed) --------
__device__ float    g_kvp[4 * BATCH * 512 * RHW];  // 16 MB kv split-K partials
// packed bf16 hi/lo planes
__device__ uint32_t g_wqh[256 * 128],   g_wql[256 * 128];
__device__ uint32_t g_wkh[256 * 2048],  g_wkl[256 * 2048];
__device__ uint32_t g_wvh[256 * 2048],  g_wvl[256 * 2048];
__device__ uint32_t g_woh[256 * 128],   g_wol[256 * 128];
__device__ uint32_t g_xph[BATCH * 128 * HW],  g_xpl[BATCH * 128 * HW];    // x pairs along c
__device__ uint32_t g_xrh[BATCH * 2048 * RHW], g_xrl[BATCH * 2048 * RHW]; // im2col pairs along k
__device__ uint32_t g_qph[BATCH * HW * 128],  g_qpl[BATCH * HW * 128];    // q: [b][i][d2]
__device__ uint32_t g_aoh[BATCH * 128 * HW],  g_aol[BATCH * 128 * HW];    // ao pairs along d
// pre-packed K/V in attention fragment layouts
__device__ uint32_t g_kph[BATCH * HEADS * 256 * 16], g_kpl[BATCH * HEADS * 256 * 16]; // [bh][j][d2]
__device__ uint32_t g_vph[BATCH * HEADS * 32 * 128], g_vpl[BATCH * HEADS * 32 * 128]; // [bh][d][j2]

extern __shared__ char dynsmem[];

// ======================= bf16 split/pack + MMA helpers =======================
__device__ __forceinline__ uint32_t pack_bf16(float v0, float v1) {
    uint32_t r;
    asm("cvt.rn.bf16x2.f32 %0, %1, %2;" : "=r"(r) : "f"(v1), "f"(v0));
    return r;
}
__device__ __forceinline__ void split_pair(float v0, float v1, uint32_t& h, uint32_t& l) {
    h = pack_bf16(v0, v1);
    float h0 = __uint_as_float(h << 16);
    float h1 = __uint_as_float(h & 0xFFFF0000u);
    l = pack_bf16(v0 - h0, v1 - h1);
}
__device__ __forceinline__ void mma_bf16(float c[4], const uint32_t a[4], const uint32_t b[2]) {
    asm volatile(
        "mma.sync.aligned.m16n8k16.row.col.f32.bf16.bf16.f32 "
        "{%0,%1,%2,%3},{%4,%5,%6,%7},{%8,%9},{%0,%1,%2,%3};"
        : "+f"(c[0]), "+f"(c[1]), "+f"(c[2]), "+f"(c[3])
        : "r"(a[0]), "r"(a[1]), "r"(a[2]), "r"(a[3]), "r"(b[0]), "r"(b[1]));
}
__device__ __forceinline__ void mma3(float c[4], const uint32_t ah[4], const uint32_t al[4],
                                     const uint32_t bh[2], const uint32_t bl[2]) {
    mma_bf16(c, ah, bh);
    mma_bf16(c, al, bh);
    mma_bf16(c, ah, bl);
}
__device__ __forceinline__ void ldsm_x4(uint32_t r[4], uint32_t saddr) {
    asm volatile("ldmatrix.sync.aligned.m8n8.x4.shared.b16 {%0,%1,%2,%3}, [%4];"
        : "=r"(r[0]), "=r"(r[1]), "=r"(r[2]), "=r"(r[3]) : "r"(saddr));
}

// ======================= cp.async helpers =======================
__device__ __forceinline__ void cp16(uint32_t* smem_dst, const uint32_t* gsrc) {
    uint32_t s;
    asm("{ .reg .u64 t; cvta.to.shared.u64 t, %1; cvt.u32.u64 %0, t; }"
        : "=r"(s) : "l"(smem_dst));
    asm volatile("cp.async.ca.shared.global [%0], [%1], 16;" :: "r"(s), "l"(gsrc));
}
__device__ __forceinline__ void cp_commit() { asm volatile("cp.async.commit_group;"); }
template<int N> __device__ __forceinline__ void cp_wait_n() {
    asm volatile("cp.async.wait_group %0;" :: "n"(N));
}
__device__ __forceinline__ uint32_t smem_u32(const void* p) {
    uint32_t a;
    asm("{ .reg .u64 t; cvta.to.shared.u64 t, %1; cvt.u32.u64 %0, t; }" : "=r"(a) : "l"(p));
    return a;
}

// ======================= packed-operand double-buffered GEMM body =======================
template<int BM, int BN, bool PACK>
__device__ __forceinline__ void gemm_packed_body(
    const uint32_t* __restrict__ Ah, const uint32_t* __restrict__ Al, int lda2,
    const uint32_t* __restrict__ Bh, const uint32_t* __restrict__ Bl, int ldb2,
    float* __restrict__ C, int ldc, int k2steps, int m0, int n0, uint32_t* smem,
    uint32_t* __restrict__ POh, uint32_t* __restrict__ POl, size_t prowbase)
{
    constexpr int BK2 = 16;
    constexpr int LDA2 = 20;
    constexpr int LDB2 = BN + 8;
    constexpr int ASZ = BM * LDA2, BSZ = BK2 * LDB2;
    constexpr int STG = 2 * ASZ + 2 * BSZ;
    constexpr int WM = BM / 2, WN = BN / 4;
    constexpr int MT = WM / 16, NT = WN / 8;

    const int tid = threadIdx.x, warp = tid >> 5, lane = tid & 31;
    const int wm = warp >> 2, wn = warp & 3;
    const int lr = lane >> 2, lc = lane & 3;
    const int lrow = lane & 15, lcol = (lane >> 4) << 2;

    const uint32_t sA = smem_u32(smem);
    const uint32_t a_lo = (uint32_t)(((wm * WM + lrow) * LDA2 + lcol) * 4);

    float acc[MT][NT][4];
    #pragma unroll
    for (int i = 0; i < MT; i++)
        #pragma unroll
        for (int j = 0; j < NT; j++)
            #pragma unroll
            for (int q = 0; q < 4; q++) acc[i][j][q] = 0.f;

    auto stage = [&](int k2_0, uint32_t* buf) {
        uint32_t* Aht = buf;
        uint32_t* Alt = buf + ASZ;
        uint32_t* Bht = buf + 2 * ASZ;
        uint32_t* Blt = buf + 2 * ASZ + BSZ;
        #pragma unroll
        for (int i = tid; i < BM * 4; i += 256) {
            int r = i >> 2, c4 = (i & 3) * 4;
            cp16(&Aht[r * LDA2 + c4], &Ah[(size_t)(m0 + r) * lda2 + k2_0 + c4]);
            cp16(&Alt[r * LDA2 + c4], &Al[(size_t)(m0 + r) * lda2 + k2_0 + c4]);
        }
        #pragma unroll
        for (int i = tid; i < BK2 * (BN / 4); i += 256) {
            int r = i / (BN / 4), c4 = (i % (BN / 4)) * 4;
            cp16(&Bht[r * LDB2 + c4], &Bh[(size_t)(k2_0 + r) * ldb2 + n0 + c4]);
            cp16(&Blt[r * LDB2 + c4], &Bl[(size_t)(k2_0 + r) * ldb2 + n0 + c4]);
        }
        cp_commit();
    };

    const int nit = k2steps / BK2;
    stage(0, smem);

    for (int it = 0; it < nit; it++) {
        uint32_t* buf = smem + (it & 1) * STG;
        const uint32_t abase = sA + (uint32_t)((it & 1) * STG) * 4;
        __syncthreads();
        if (it + 1 < nit) {
            stage((it + 1) * BK2, smem + ((it + 1) & 1) * STG);
            cp_wait_n<1>();
        } else {
            cp_wait_n<0>();
        }
        __syncthreads();

        uint32_t* Bht = buf + 2 * ASZ;
        uint32_t* Blt = buf + 2 * ASZ + BSZ;

        #pragma unroll
        for (int kk2 = 0; kk2 < BK2; kk2 += 8) {
            uint32_t ah[MT][4], al[MT][4];
            #pragma unroll
            for (int mt = 0; mt < MT; mt++) {
                uint32_t addr = abase + a_lo + (uint32_t)((mt * 16 * LDA2 + kk2) * 4);
                ldsm_x4(ah[mt], addr);
                ldsm_x4(al[mt], addr + ASZ * 4);
            }
            uint32_t bh[NT][2], bl[NT][2];
            #pragma unroll
            for (int nt = 0; nt < NT; nt++) {
                int cc = wn * WN + nt * 8 + lr;
                bh[nt][0] = Bht[(kk2 + lc) * LDB2 + cc];
                bh[nt][1] = Bht[(kk2 + lc + 4) * LDB2 + cc];
                bl[nt][0] = Blt[(kk2 + lc) * LDB2 + cc];
                bl[nt][1] = Blt[(kk2 + lc + 4) * LDB2 + cc];
            }
            #pragma unroll
            for (int mt = 0; mt < MT; mt++)
                #pragma unroll
                for (int nt = 0; nt < NT; nt++)
                    mma3(acc[mt][nt], ah[mt], al[mt], bh[nt], bl[nt]);
        }
    }

    if (PACK) {
        float* Tf = (float*)smem;            // [BM][133] reuse pipeline buffers
        __syncthreads();
        #pragma unroll
        for (int mt = 0; mt < MT; mt++) {
            int r = wm * WM + mt * 16 + lr;
            #pragma unroll
            for (int nt = 0; nt < NT; nt++) {
                int c = wn * WN + nt * 8 + lc * 2;
                Tf[r * 133 + c]           = acc[mt][nt][0];
                Tf[r * 133 + c + 1]       = acc[mt][nt][1];
                Tf[(r + 8) * 133 + c]     = acc[mt][nt][2];
                Tf[(r + 8) * 133 + c + 1] = acc[mt][nt][3];
            }
        }
        __syncthreads();
        const int d2off = m0 >> 1;
        for (int idx = tid; idx < (BM / 2) * BN; idx += 256) {
            int d2 = idx & (BM / 2 - 1), i = idx / (BM / 2);
            uint32_t hw_, lw_;
            split_pair(Tf[(2 * d2) * 133 + i], Tf[(2 * d2 + 1) * 133 + i], hw_, lw_);
            const size_t o = (prowbase + i) * 128 + d2off + d2;
            POh[o] = hw_;
            POl[o] = lw_;
        }
    } else {
        #pragma unroll
        for (int mt = 0; mt < MT; mt++) {
            int r = m0 + wm * WM + mt * 16 + lr;
            #pragma unroll
            for (int nt = 0; nt < NT; nt++) {
                int c = n0 + wn * WN + nt * 8 + lc * 2;
                *(float2*)&C[(size_t)r * ldc + c]       = make_float2(acc[mt][nt][0], acc[mt][nt][1]);
                *(float2*)&C[(size_t)(r + 8) * ldc + c] = make_float2(acc[mt][nt][2], acc[mt][nt][3]);
            }
        }
    }
}

// ======================= pack kernels =======================
__global__ __launch_bounds__(256)
void pack_pairs_kernel(const float* __restrict__ src, uint32_t* __restrict__ h,
                       uint32_t* __restrict__ l, int npairs, float scale) {
    int idx = blockIdx.x * 256 + threadIdx.x;
    if (idx >= npairs) return;
    float2 v = ((const float2*)src)[idx];
    uint32_t hw_, lw_;
    split_pair(v.x * scale, v.y * scale, hw_, lw_);
    h[idx] = hw_;
    l[idx] = lw_;
}

__global__ __launch_bounds__(256)
void pack_x_kernel(const float* __restrict__ X, uint32_t* __restrict__ h,
                   uint32_t* __restrict__ l) {
    const int n = blockIdx.x * 256 + threadIdx.x;
    const int c2 = blockIdx.y, b = blockIdx.z;
    const float* r0 = X + ((size_t)b * DIM + 2 * c2) * HW;
    uint32_t hw_, lw_;
    split_pair(r0[n], r0[HW + n], hw_, lw_);
    const size_t o = ((size_t)b * 128 + c2) * HW + n;
    h[o] = hw_;
    l[o] = lw_;
}

__global__ __launch_bounds__(256)
void repack_kernel(const float* __restrict__ X, uint32_t* __restrict__ h,
                   uint32_t* __restrict__ l) {
    float* pl = (float*)dynsmem;   // [4096]
    const int ci = blockIdx.x, b = blockIdx.y, tid = threadIdx.x;
    const float* src = X + ((size_t)b * DIM + ci) * HW;
    #pragma unroll
    for (int i = tid; i < 1024; i += 256)
        ((float4*)pl)[i] = ((const float4*)src)[i];
    __syncthreads();
    const int oh = tid >> 4, ow = tid & 15;
    #pragma unroll
    for (int kh = 0; kh < 4; kh++)
        #pragma unroll
        for (int kw2 = 0; kw2 < 2; kw2++) {
            float v0 = pl[(oh * 4 + kh) * 64 + ow * 4 + 2 * kw2];
            float v1 = pl[(oh * 4 + kh) * 64 + ow * 4 + 2 * kw2 + 1];
            uint32_t hw_, lw_;
            split_pair(v0, v1, hw_, lw_);
            const size_t o = ((size_t)b * 2048 + ci * 8 + kh * 2 + kw2) * RHW + tid;
            h[o] = hw_;
            l[o] = lw_;
        }
}

// ======================= kv GEMM (split-K=4, 128x64 tiles) =======================
__global__ __launch_bounds__(256, 2)
void kv_gemm_kernel(float* __restrict__ Part) {
    uint32_t* smem = (uint32_t*)dynsmem;
    const int mblk = blockIdx.y;              // 0..3, 128 stacked rows each
    const int b  = blockIdx.z & 7;
    const int ks = blockIdx.z >> 3;
    const int koff2 = ks * 512;
    const uint32_t* Ah = (mblk < 2) ? (g_wkh + koff2) : (g_wvh + koff2 - (size_t)256 * 2048);
    const uint32_t* Al = (mblk < 2) ? (g_wkl + koff2) : (g_wvl + koff2 - (size_t)256 * 2048);
    const uint32_t* Bh = g_xrh + ((size_t)b * 2048 + koff2) * RHW;
    const uint32_t* Bl = g_xrl + ((size_t)b * 2048 + koff2) * RHW;
    float* C = g_kvp + ((size_t)(ks * BATCH + b) * 512) * RHW;
    gemm_packed_body<128, 64, false>(Ah, Al, 2048, Bh, Bl, RHW,
                                     C, RHW, 512, mblk * 128, blockIdx.x * 64, smem,
                                     nullptr, nullptr, 0);
}

// reduce split-K partials AND emit packed K/V planes.
// K planes: [bh][j][d2] (j-major, ldmatrix-friendly). V planes: [bh][d][j2].
__global__ __launch_bounds__(256)
void kv_reduce_pack_kernel(const float* __restrict__ P,
                           uint32_t* __restrict__ Kph, uint32_t* __restrict__ Kpl,
                           uint32_t* __restrict__ Vph, uint32_t* __restrict__ Vpl) {
    const size_t CH = (size_t)8 * 512 * RHW;
    if (blockIdx.x < 256) {
        int t = blockIdx.x * 256 + threadIdx.x;
        int j4 = (t & 63) * 4;
        int m2 = (t >> 6) & 127;
        int b  = t >> 13;
        const float* p0 = P + ((size_t)b * 512 + 2 * m2) * RHW + j4;
        const float* p1 = p0 + RHW;
        float4 r0 = *(const float4*)p0, r1 = *(const float4*)p1;
        #pragma unroll
        for (int ks = 1; ks < 4; ks++) {
            float4 a = *(const float4*)(p0 + ks * CH);
            float4 c = *(const float4*)(p1 + ks * CH);
            r0.x += a.x; r0.y += a.y; r0.z += a.z; r0.w += a.w;
            r1.x += c.x; r1.y += c.y; r1.z += c.z; r1.w += c.w;
        }
        const int h = m2 >> 4, d2 = m2 & 15;
        const size_t ob = (size_t)(b * 8 + h) * 256;
        uint32_t hw_, lw_;
        split_pair(r0.x, r1.x, hw_, lw_); Kph[(ob + j4 + 0) * 16 + d2] = hw_; Kpl[(ob + j4 + 0) * 16 + d2] = lw_;
        split_pair(r0.y, r1.y, hw_, lw_); Kph[(ob + j4 + 1) * 16 + d2] = hw_; Kpl[(ob + j4 + 1) * 16 + d2] = lw_;
        split_pair(r0.z, r1.z, hw_, lw_); Kph[(ob + j4 + 2) * 16 + d2] = hw_; Kpl[(ob + j4 + 2) * 16 + d2] = lw_;
        split_pair(r0.w, r1.w, hw_, lw_); Kph[(ob + j4 + 3) * 16 + d2] = hw_; Kpl[(ob + j4 + 3) * 16 + d2] = lw_;
    } else {
        int t = (blockIdx.x - 256) * 256 + threadIdx.x;
        int j4 = (t & 63) * 4;
        int m  = (t >> 6) & 255;
        int b  = t >> 14;
        const float* p0 = P + ((size_t)b * 512 + 256 + m) * RHW + j4;
        float4 v = *(const float4*)p0;
        #pragma unroll
        for (int ks = 1; ks < 4; ks++) {
            float4 a = *(const float4*)(p0 + ks * CH);
            v.x += a.x; v.y += a.y; v.z += a.z; v.w += a.w;
        }
        const int h = m >> 5, d = m & 31;
        const size_t o = (((size_t)(b * 8 + h) * 32 + d) * 128) + (j4 >> 1);
        uint32_t hw_, lw_;
        split_pair(v.x, v.y, hw_, lw_); Vph[o]     = hw_; Vpl[o]     = lw_;
        split_pair(v.z, v.w, hw_, lw_); Vph[o + 1] = hw_; Vpl[o + 1] = lw_;
    }
}

// ======================= 1x1-conv GEMMs =======================
__global__ __launch_bounds__(256, 2)
void gemm_q_kernel(const uint32_t* __restrict__ Ah, const uint32_t* __restrict__ Al,
                   const uint32_t* __restrict__ Bh, const uint32_t* __restrict__ Bl,
                   uint32_t* __restrict__ Qh, uint32_t* __restrict__ Ql) {
    uint32_t* smem = (uint32_t*)dynsmem;
    const size_t bo = (size_t)blockIdx.z * 128 * HW;
    const int n0 = blockIdx.x * 128;
    gemm_packed_body<128, 128, true>(Ah, Al, 128, Bh + bo, Bl + bo, HW,
                                     nullptr, 0, 128, blockIdx.y * 128, n0, smem,
                                     Qh, Ql, (size_t)blockIdx.z * HW + n0);
}

__global__ __launch_bounds__(256, 2)
void gemm_o_kernel(const uint32_t* __restrict__ Ah, const uint32_t* __restrict__ Al,
                   const uint32_t* __restrict__ Bh, const uint32_t* __restrict__ Bl,
                   float* __restrict__ Cg) {
    uint32_t* smem = (uint32_t*)dynsmem;
    const size_t bo = (size_t)blockIdx.z * 128 * HW;
    float* C = Cg + (size_t)blockIdx.z * DIM * HW;
    gemm_packed_body<128, 128, false>(Ah, Al, 128, Bh + bo, Bl + bo, HW,
                                      C, HW, 128, blockIdx.y * 128, blockIdx.x * 128, smem,
                                      nullptr, nullptr, 0);
}

// ======================= fused attention: i-tile 128, full-LDSM =======================
// smem words: Qph/Qpl 2x2560 | kvbuf 2x4864 (K[64][20]x2, V[32][36]x2) | Pph/Ppl 2x4608 | lacc 256 | li 128
__global__ __launch_bounds__(256, 2)
void attn_kernel(uint32_t* __restrict__ Oh, uint32_t* __restrict__ Ol) {
    uint32_t* su  = (uint32_t*)dynsmem;
    uint32_t* Qph = su;                    // [128][20]
    uint32_t* Qpl = Qph + 2560;
    uint32_t* kvbuf = Qpl + 2560;          // 2 x [Kh 1280 | Kl 1280 | Vh 1152 | Vl 1152]
    uint32_t* Pph = kvbuf + 2 * 4864;      // [128][36]
    uint32_t* Ppl = Pph + 4608;
    float* lacc  = (float*)(Ppl + 4608);   // [2][128]
    float* li    = lacc + 256;             // [128]
    float* po    = (float*)Pph;            // [128][36] final staging (aliases P)

    const int tid = threadIdx.x, warp = tid >> 5, lane = tid & 31;
    const int lr = lane >> 2, lc = lane & 3;
    const int wm = warp >> 1, wn = warp & 1;   // S phase: 4(m) x 2(n)
    const int iw = warp * 16;                   // PV phase: 8 i-strips
    const int lrow = lane & 15, lcol = (lane >> 4) << 2;
    const int b = blockIdx.z, h = blockIdx.y, i0 = blockIdx.x * 128;

    const uint32_t qbase = smem_u32(Qph);
    const uint32_t pbase = smem_u32(Pph);
    const uint32_t kvb0  = smem_u32(kvbuf);
    const uint32_t q_lo = (uint32_t)(((wm * 32 + lrow) * 20 + lcol) * 4);
    const uint32_t p_lo = (uint32_t)(((iw + lrow) * 36 + lcol) * 4);
    // ldmatrix B-side lane offsets: matrix m = lane>>3; row = lane&7
    //   K (S phase): row j = wn*32 + ntp*16 + (m>>1)*8 + (lane&7), word = kk2 + (m&1)*4
    const uint32_t kB_lo = (uint32_t)(((wn * 32 + ((lane >> 4) << 3) + (lane & 7)) * 20
                                      + (((lane >> 3) & 1) << 2)) * 4);
    //   V (PV phase): row d = ntp*16 + (m>>1)*8 + (lane&7), word = kk2 + (m&1)*4
    const uint32_t vB_lo = (uint32_t)(((((lane >> 4) << 3) + (lane & 7)) * 36
                                      + (((lane >> 3) & 1) << 2)) * 4);

    const uint32_t* Qgh = g_qph + ((size_t)b * HW + i0) * 128 + h * 16;
    const uint32_t* Qgl = g_qpl + ((size_t)b * HW + i0) * 128 + h * 16;
    const uint32_t* Kgh = g_kph + (size_t)(b * 8 + h) * 256 * 16;
    const uint32_t* Kgl = g_kpl + (size_t)(b * 8 + h) * 256 * 16;
    const uint32_t* Vgh = g_vph + (size_t)(b * 8 + h) * 32 * 128;
    const uint32_t* Vgl = g_vpl + (size_t)(b * 8 + h) * 32 * 128;

    auto stageKV = [&](int jt, int bufsel) {
        uint32_t* Kh = kvbuf + bufsel * 4864;
        uint32_t* Kl = Kh + 1280;
        uint32_t* Vh = Kl + 1280;
        uint32_t* Vl = Vh + 1152;
        const int j0 = jt * 64, jw0 = jt * 32;
        {   // K: 64 j-rows x 16 words (4 chunks)
            int r = tid >> 2, c4 = (tid & 3) * 4;
            cp16(&Kh[r * 20 + c4], &Kgh[(size_t)(j0 + r) * 16 + c4]);
            cp16(&Kl[r * 20 + c4], &Kgl[(size_t)(j0 + r) * 16 + c4]);
        }
        {   // V: 32 d-rows x 32 words (8 chunks)
            int r = tid >> 3, c4 = (tid & 7) * 4;
            cp16(&Vh[r * 36 + c4], &Vgh[r * 128 + jw0 + c4]);
            cp16(&Vl[r * 36 + c4], &Vgl[r * 128 + jw0 + c4]);
        }
        cp_commit();
    };

    // stage Q (pre-packed, 128 rows x 4 chunks per plane) + first KV tile
    #pragma unroll
    for (int idx = tid; idx < 512; idx += 256) {
        int r = idx >> 2, c4 = (idx & 3) * 4;
        cp16(&Qph[r * 20 + c4], &Qgh[(size_t)r * 128 + c4]);
        cp16(&Qpl[r * 20 + c4], &Qgl[(size_t)r * 128 + c4]);
    }
    stageKV(0, 0);
    lacc[tid] = 0.f;

    float oacc[4][4];
    #pragma unroll
    for (int nt = 0; nt < 4; nt++)
        #pragma unroll
        for (int q = 0; q < 4; q++) oacc[nt][q] = 0.f;

    for (int jt = 0; jt < 4; jt++) {
        cp_wait_n<0>();
        __syncthreads();   // buf[jt&1] + Q ready; PV of jt-1 done

        if (jt < 3) stageKV(jt + 1, (jt + 1) & 1);

        const uint32_t kbh = kvb0 + (uint32_t)((jt & 1) * 4864) * 4;
        const uint32_t klh = kbh + 1280 * 4;
        const uint32_t vbh = klh + 1280 * 4;
        const uint32_t vlh = vbh + 1152 * 4;

        // ---- S = Q K^T : M=128(i), N=64(j), K=32(d). warp tile 32x32. Q+K via LDSM ----
        float sacc[2][4][4];
        #pragma unroll
        for (int mt = 0; mt < 2; mt++)
            #pragma unroll
            for (int nt = 0; nt < 4; nt++)
                #pragma unroll
                for (int q = 0; q < 4; q++) sacc[mt][nt][q] = 0.f;

        #pragma unroll
        for (int kk2 = 0; kk2 < 16; kk2 += 8) {
            uint32_t ah[2][4], al[2][4];
            #pragma unroll
            for (int mt = 0; mt < 2; mt++) {
                uint32_t addr = qbase + q_lo + (uint32_t)((mt * 16 * 20 + kk2) * 4);
                ldsm_x4(ah[mt], addr);
                ldsm_x4(al[mt], addr + 2560 * 4);
            }
            uint32_t bh[4][2], bl[4][2];
            #pragma unroll
            for (int ntp = 0; ntp < 2; ntp++) {
                uint32_t t4[4];
                uint32_t off = kB_lo + (uint32_t)((ntp * 16 * 20 + kk2) * 4);
                ldsm_x4(t4, kbh + off);
                bh[ntp * 2][0] = t4[0]; bh[ntp * 2][1] = t4[1];
                bh[ntp * 2 + 1][0] = t4[2]; bh[ntp * 2 + 1][1] = t4[3];
                ldsm_x4(t4, klh + off);
                bl[ntp * 2][0] = t4[0]; bl[ntp * 2][1] = t4[1];
                bl[ntp * 2 + 1][0] = t4[2]; bl[ntp * 2 + 1][1] = t4[3];
            }
            #pragma unroll
            for (int mt = 0; mt < 2; mt++)
                #pragma unroll
                for (int nt = 0; nt < 4; nt++)
                    mma3(sacc[mt][nt], ah[mt], al[mt], bh[nt], bl[nt]);
        }

        // ---- exp -> P (packed pairs along j), accumulate row sums ----
        #pragma unroll
        for (int mt = 0; mt < 2; mt++) {
            int r = wm * 32 + mt * 16 + lr;
            float rs0 = 0.f, rs1 = 0.f;
            #pragma unroll
            for (int nt = 0; nt < 4; nt++) {
                int j2 = wn * 16 + nt * 4 + lc;
                float e0 = __expf(sacc[mt][nt][0]);
                float e1 = __expf(sacc[mt][nt][1]);
                float e2 = __expf(sacc[mt][nt][2]);
                float e3 = __expf(sacc[mt][nt][3]);
                uint32_t hw_, lw_;
                split_pair(e0, e1, hw_, lw_);
                Pph[r * 36 + j2] = hw_;  Ppl[r * 36 + j2] = lw_;
                split_pair(e2, e3, hw_, lw_);
                Pph[(r + 8) * 36 + j2] = hw_;  Ppl[(r + 8) * 36 + j2] = lw_;
                rs0 += e0 + e1;
                rs1 += e2 + e3;
            }
            rs0 += __shfl_xor_sync(0xFFFFFFFFu, rs0, 1);
            rs0 += __shfl_xor_sync(0xFFFFFFFFu, rs0, 2);
            rs1 += __shfl_xor_sync(0xFFFFFFFFu, rs1, 1);
            rs1 += __shfl_xor_sync(0xFFFFFFFFu, rs1, 2);
            if (lc == 0) {
                lacc[wn * 128 + r]     += rs0;
                lacc[wn * 128 + r + 8] += rs1;
            }
        }
        __syncthreads();

        // ---- PV accumulate: O[iw..+16][0..32] += P_tile * V_tile. P+V via LDSM ----
        #pragma unroll
        for (int kk2 = 0; kk2 < 32; kk2 += 8) {
            uint32_t ah[4], al[4];
            uint32_t addr = pbase + p_lo + (uint32_t)(kk2 * 4);
            ldsm_x4(ah, addr);
            ldsm_x4(al, addr + 4608 * 4);
            uint32_t bh[4][2], bl[4][2];
            #pragma unroll
            for (int ntp = 0; ntp < 2; ntp++) {
                uint32_t t4[4];
                uint32_t off = vB_lo + (uint32_t)((ntp * 16 * 36 + kk2) * 4);
                ldsm_x4(t4, vbh + off);
                bh[ntp * 2][0] = t4[0]; bh[ntp * 2][1] = t4[1];
                bh[ntp * 2 + 1][0] = t4[2]; bh[ntp * 2 + 1][1] = t4[3];
                ldsm_x4(t4, vlh + off);
                bl[ntp * 2][0] = t4[0]; bl[ntp * 2][1] = t4[1];
                bl[ntp * 2 + 1][0] = t4[2]; bl[ntp * 2 + 1][1] = t4[3];
            }
            #pragma unroll
            for (int nt = 0; nt < 4; nt++)
                mma3(oacc[nt], ah, al, bh[nt], bl[nt]);
        }
    }

    __syncthreads();
    if (tid < 128)
        li[tid] = 1.f / (lacc[tid] + lacc[128 + tid]);
    __syncthreads();

    #pragma unroll
    for (int nt = 0; nt < 4; nt++) {
        int r = iw + lr, c = nt * 8 + lc * 2;
        float inv0 = li[r], inv1 = li[r + 8];
        po[r * 36 + c]           = oacc[nt][0] * inv0;
        po[r * 36 + c + 1]       = oacc[nt][1] * inv0;
        po[(r + 8) * 36 + c]     = oacc[nt][2] * inv1;
        po[(r + 8) * 36 + c + 1] = oacc[nt][3] * inv1;
    }
    __syncthreads();

    // packed-plane store: word(b, h*16+d2, i0+i) = (O[2d2][i], O[2d2+1][i]); coalesced along i
    for (int idx = tid; idx < 2048; idx += 256) {
        int d2 = idx >> 7, i = idx & 127;
        uint32_t hw_, lw_;
        split_pair(po[i * 36 + 2 * d2], po[i * 36 + 2 * d2 + 1], hw_, lw_);
        const size_t o = ((size_t)b * 128 + h * 16 + d2) * HW + i0 + i;
        Oh[o] = hw_;
        Ol[o] = lw_;
    }
}

// ============================================================================
extern "C" void kernel_launch(void* const* d_in, const int* in_sizes, int n_in,
                              void* d_out, int out_size) {
    const float* x    = (const float*)d_in[0];
    const float* wq   = (const float*)d_in[1];
    const float* wk   = (const float*)d_in[2];
    const float* wv   = (const float*)d_in[3];
    const float* wout = (const float*)d_in[4];
    float* out = (float*)d_out;

    float *kvpp;
    uint32_t *wqh, *wql, *wkh, *wkl, *wvh, *wvl, *woh, *wol;
    uint32_t *xph, *xpl, *xrh, *xrl, *qph, *qpl, *aoh, *aol, *kph, *kpl, *vph, *vpl;
    cudaGetSymbolAddress((void**)&kvpp, g_kvp);
    cudaGetSymbolAddress((void**)&wqh,  g_wqh);  cudaGetSymbolAddress((void**)&wql, g_wql);
    cudaGetSymbolAddress((void**)&wkh,  g_wkh);  cudaGetSymbolAddress((void**)&wkl, g_wkl);
    cudaGetSymbolAddress((void**)&wvh,  g_wvh);  cudaGetSymbolAddress((void**)&wvl, g_wvl);
    cudaGetSymbolAddress((void**)&woh,  g_woh);  cudaGetSymbolAddress((void**)&wol, g_wol);
    cudaGetSymbolAddress((void**)&xph,  g_xph);  cudaGetSymbolAddress((void**)&xpl, g_xpl);
    cudaGetSymbolAddress((void**)&xrh,  g_xrh);  cudaGetSymbolAddress((void**)&xrl, g_xrl);
    cudaGetSymbolAddress((void**)&qph,  g_qph);  cudaGetSymbolAddress((void**)&qpl, g_qpl);
    cudaGetSymbolAddress((void**)&aoh,  g_aoh);  cudaGetSymbolAddress((void**)&aol, g_aol);
    cudaGetSymbolAddress((void**)&kph,  g_kph);  cudaGetSymbolAddress((void**)&kpl, g_kpl);
    cudaGetSymbolAddress((void**)&vph,  g_vph);  cudaGetSymbolAddress((void**)&vpl, g_vpl);

    const int g1_smem   = 2 * (2 * 128 * 20 + 2 * 16 * 136) * 4;   // 75776 B
    const int kv_smem   = 2 * (2 * 128 * 20 + 2 * 16 * 72) * 4;    // 59392 B
    const int attn_smem = (2 * 2560 + 2 * 4864 + 2 * 4608 + 256 + 128) * 4; // 97792 B
    const int rp_smem   = 4096 * 4;

    cudaFuncSetAttribute(gemm_q_kernel,  cudaFuncAttributeMaxDynamicSharedMemorySize, g1_smem);
    cudaFuncSetAttribute(gemm_o_kernel,  cudaFuncAttributeMaxDynamicSharedMemorySize, g1_smem);
    cudaFuncSetAttribute(kv_gemm_kernel, cudaFuncAttributeMaxDynamicSharedMemorySize, kv_smem);
    cudaFuncSetAttribute(attn_kernel,    cudaFuncAttributeMaxDynamicSharedMemorySize, attn_smem);
    cudaFuncSetAttribute(repack_kernel,  cudaFuncAttributeMaxDynamicSharedMemorySize, rp_smem);

    // P0: one-time packs (SCALE folded into wq)
    pack_pairs_kernel<<<128,  256>>>(wq,   wqh, wql, 256 * 128, SCALE);
    pack_pairs_kernel<<<2048, 256>>>(wk,   wkh, wkl, 256 * 2048, 1.0f);
    pack_pairs_kernel<<<2048, 256>>>(wv,   wvh, wvl, 256 * 2048, 1.0f);
    pack_pairs_kernel<<<128,  256>>>(wout, woh, wol, 256 * 128, 1.0f);
    pack_x_kernel<<<dim3(HW / 256, 128, BATCH), 256>>>(x, xph, xpl);
    repack_kernel<<<dim3(DIM, BATCH), 256, rp_smem>>>(x, xrh, xrl);

    // K1: q = (wq*SCALE) @ x -> packed planes
    gemm_q_kernel<<<dim3(HW / 128, 2, BATCH), 256, g1_smem>>>(wqh, wql, xph, xpl, qph, qpl);
    // K2: fused k & v GEMM (split-K=4, 128x64 tiles) + reduce-and-pack
    kv_gemm_kernel<<<dim3(4, 4, BATCH * 4), 256, kv_smem>>>(kvpp);
    kv_reduce_pack_kernel<<<768, 256>>>(kvpp, kph, kpl, vph, vpl);
    // K3: fused attention (i-tile 128, full-LDSM) -> packed ao planes
    attn_kernel<<<dim3(HW / 128, HEADS, BATCH), 256, attn_smem>>>(aoh, aol);
    // K4: out = wout @ ao
    gemm_o_kernel<<<dim3(HW / 128, 2, BATCH), 256, g1_smem>>>(woh, wol, aoh, aol, out);
}